// round 13
// baseline (speedup 1.0000x reference)
#include <cuda_runtime.h>
#include <cuda_bf16.h>
#include <stdint.h>

#define SEQ    2048
#define DIM    4096
#define NH     32
#define NKV    8
#define HD     128
#define KV_DIM 1024
#define BQT    128
#define BKT    64
#define PADK   136

#if defined(__CUDA_ARCH_FEAT_SM103_ALL) || defined(__CUDA_ARCH_FEAT_SM100_ALL)
#define HAS_TCGEN05 1
#else
#define HAS_TCGEN05 0
#endif

// ---------------------------------------------------------------------------
// Static device scratch
// ---------------------------------------------------------------------------
__device__ __nv_bfloat16 g_xh[SEQ * DIM],     g_xl[SEQ * DIM];
__device__ __nv_bfloat16 g_wqh[DIM * DIM],    g_wql[DIM * DIM];
__device__ __nv_bfloat16 g_wkh[KV_DIM * DIM], g_wkl[KV_DIM * DIM];
__device__ __nv_bfloat16 g_wvh[KV_DIM * DIM], g_wvl[KV_DIM * DIM];
__device__ __nv_bfloat16 g_woh[DIM * DIM],    g_wol[DIM * DIM];
__device__ __nv_bfloat16 g_oh[SEQ * DIM],     g_ol[SEQ * DIM];

__device__ __nv_bfloat16 g_Qh[SEQ * DIM],     g_Ql[SEQ * DIM];
__device__ __nv_bfloat16 g_Kh[SEQ * KV_DIM],  g_Kl[SEQ * KV_DIM];
__device__ __nv_bfloat16 g_Vh[SEQ * KV_DIM],  g_Vl[SEQ * KV_DIM];
__device__ __nv_bfloat16 g_Vth[KV_DIM * SEQ], g_Vtl[KV_DIM * SEQ];  // [d][seq]

// ---------------------------------------------------------------------------
// Helpers
// ---------------------------------------------------------------------------
__device__ __forceinline__ uint32_t smaddr(const void* p) {
    return (uint32_t)__cvta_generic_to_shared(p);
}
__device__ __forceinline__ void cp16(uint32_t s, const void* g) {
    asm volatile("cp.async.cg.shared.global [%0], [%1], 16;" :: "r"(s), "l"(g));
}
__device__ __forceinline__ void cp_commit() {
    asm volatile("cp.async.commit_group;");
}
__device__ __forceinline__ void ldsm4(uint32_t& r0, uint32_t& r1,
                                      uint32_t& r2, uint32_t& r3, uint32_t a) {
    asm volatile("ldmatrix.sync.aligned.m8n8.x4.shared.b16 {%0,%1,%2,%3}, [%4];"
                 : "=r"(r0), "=r"(r1), "=r"(r2), "=r"(r3) : "r"(a));
}
__device__ __forceinline__ void ldsm4t(uint32_t& r0, uint32_t& r1,
                                       uint32_t& r2, uint32_t& r3, uint32_t a) {
    asm volatile("ldmatrix.sync.aligned.m8n8.x4.trans.shared.b16 {%0,%1,%2,%3}, [%4];"
                 : "=r"(r0), "=r"(r1), "=r"(r2), "=r"(r3) : "r"(a));
}
__device__ __forceinline__ void mma16816(float* c, const uint32_t* a,
                                         uint32_t b0, uint32_t b1) {
    asm volatile(
        "mma.sync.aligned.m16n8k16.row.col.f32.bf16.bf16.f32 "
        "{%0,%1,%2,%3},{%4,%5,%6,%7},{%8,%9},{%0,%1,%2,%3};"
        : "+f"(c[0]), "+f"(c[1]), "+f"(c[2]), "+f"(c[3])
        : "r"(a[0]), "r"(a[1]), "r"(a[2]), "r"(a[3]), "r"(b0), "r"(b1));
}
__device__ __forceinline__ uint32_t bpack(float a, float b) {
    __nv_bfloat162 v;
    v.x = __float2bfloat16(a);
    v.y = __float2bfloat16(b);
    return *(uint32_t*)&v;
}

// ---- tcgen05 -----------------------------------------------------------------
static constexpr uint64_t SMEM_DESC_BASE_SW128 =
    (uint64_t(2)  << 61) | (uint64_t(1) << 46) |
    (uint64_t(64) << 32) | (uint64_t(1) << 16);
#define MAKE_SMEM_DESC(base_addr) \
    (SMEM_DESC_BASE_SW128 | ((uint64_t)((base_addr) >> 4) & 0x3FFF))

#define MBARRIER_INIT(mbar, count) \
    asm volatile("mbarrier.init.shared.b64 [%0], %1;" \
                 :: "r"((uint32_t)(mbar)), "r"((uint32_t)(count)) : "memory")
#define FENCE_ASYNC() \
    asm volatile("fence.proxy.async.shared::cta;" ::: "memory")

#define MBARRIER_WAIT_PARITY(mbar_smem_addr, phase_parity) do { \
    uint32_t _mbar = (uint32_t)(mbar_smem_addr); \
    uint32_t _parity = (uint32_t)(phase_parity); \
    uint32_t _done; \
    asm volatile( \
        "{\n\t.reg .pred p;\n\t" \
        "mbarrier.try_wait.parity.acquire.cta.shared::cta.b64 p, [%1], %2;\n\t" \
        "selp.b32 %0, 1, 0, p;\n\t}" \
        : "=r"(_done) : "r"(_mbar), "r"(_parity) : "memory"); \
    if (!_done) { \
        asm volatile( \
            "{\n\t.reg .pred P1;\n\t" \
            "WAIT_LOOP_%=:\n\t" \
            "mbarrier.try_wait.parity.acquire.cta.shared::cta.b64 P1, [%0], %1, 0x989680;\n\t" \
            "@P1 bra.uni WAIT_DONE_%=;\n\t" \
            "bra.uni WAIT_LOOP_%=;\n\t" \
            "WAIT_DONE_%=:\n\t}" \
            :: "r"(_mbar), "r"(_parity) : "memory"); \
    } \
} while(0)

#if HAS_TCGEN05
#define TCGEN05_ALLOC(smem_result_addr, nCols) \
    asm volatile("tcgen05.alloc.cta_group::1.sync.aligned.shared::cta.b32 [%0], %1;" \
                 :: "r"((uint32_t)(smem_result_addr)), "r"((uint32_t)(nCols)) : "memory")
#define TCGEN05_DEALLOC(tmem_addr, nCols) \
    asm volatile("tcgen05.dealloc.cta_group::1.sync.aligned.b32 %0, %1;" \
                 :: "r"(tmem_addr), "r"((uint32_t)(nCols)))
#define TCGEN05_RELINQ() \
    asm volatile("tcgen05.relinquish_alloc_permit.cta_group::1.sync.aligned;")
#define TCGEN05_COMMIT(mbar) \
    asm volatile("tcgen05.commit.cta_group::1.mbarrier::arrive::one.shared::cluster.b64 [%0];" \
                 :: "r"((uint32_t)(mbar)) : "memory")
#define TCGEN05_FENCE_AFTER() \
    asm volatile("tcgen05.fence::after_thread_sync;" ::: "memory")
#define TCGEN05_FENCE_BEFORE() \
    asm volatile("tcgen05.fence::before_thread_sync;" ::: "memory")
#define TCGEN05_WAIT_LD() \
    asm volatile("tcgen05.wait::ld.sync.aligned;" ::: "memory")
#define TCGEN05_WAIT_ST() \
    asm volatile("tcgen05.wait::st.sync.aligned;" ::: "memory")
#define TCGEN05_LD_X32(r, tmem_addr) \
    asm volatile( \
        "tcgen05.ld.sync.aligned.32x32b.x32.b32 " \
        "{%0, %1, %2, %3, %4, %5, %6, %7, " \
        " %8, %9, %10, %11, %12, %13, %14, %15, " \
        " %16, %17, %18, %19, %20, %21, %22, %23, " \
        " %24, %25, %26, %27, %28, %29, %30, %31}, [%32];" \
        : "=r"((r)[0]),  "=r"((r)[1]),  "=r"((r)[2]),  "=r"((r)[3]), \
          "=r"((r)[4]),  "=r"((r)[5]),  "=r"((r)[6]),  "=r"((r)[7]), \
          "=r"((r)[8]),  "=r"((r)[9]),  "=r"((r)[10]), "=r"((r)[11]), \
          "=r"((r)[12]), "=r"((r)[13]), "=r"((r)[14]), "=r"((r)[15]), \
          "=r"((r)[16]), "=r"((r)[17]), "=r"((r)[18]), "=r"((r)[19]), \
          "=r"((r)[20]), "=r"((r)[21]), "=r"((r)[22]), "=r"((r)[23]), \
          "=r"((r)[24]), "=r"((r)[25]), "=r"((r)[26]), "=r"((r)[27]), \
          "=r"((r)[28]), "=r"((r)[29]), "=r"((r)[30]), "=r"((r)[31]) \
        : "r"(tmem_addr))
#define TCGEN05_ST_X16(tmem_addr, r) \
    asm volatile( \
        "tcgen05.st.sync.aligned.32x32b.x16.b32 [%0], " \
        "{%1, %2, %3, %4, %5, %6, %7, %8, " \
        " %9, %10, %11, %12, %13, %14, %15, %16};" \
        :: "r"(tmem_addr), \
           "r"((r)[0]),  "r"((r)[1]),  "r"((r)[2]),  "r"((r)[3]), \
           "r"((r)[4]),  "r"((r)[5]),  "r"((r)[6]),  "r"((r)[7]), \
           "r"((r)[8]),  "r"((r)[9]),  "r"((r)[10]), "r"((r)[11]), \
           "r"((r)[12]), "r"((r)[13]), "r"((r)[14]), "r"((r)[15]) \
        : "memory")

__device__ __forceinline__ void umma_f16_ss(uint32_t d, uint64_t a, uint64_t b,
                                            uint32_t idesc, uint32_t en) {
    asm volatile(
        "{\n\t.reg .pred p;\n\t"
        "setp.ne.u32 p, %5, 0;\n\t"
        "tcgen05.mma.cta_group::1.kind::f16 [%0], %1, %2, %3, {%4,%4,%4,%4}, p;\n\t}"
        :: "r"(d), "l"(a), "l"(b), "r"(idesc), "r"(0u), "r"(en) : "memory");
}
__device__ __forceinline__ void umma_f16_ts(uint32_t d, uint32_t a_tmem,
                                            uint64_t b, uint32_t idesc,
                                            uint32_t en) {
    asm volatile(
        "{\n\t.reg .pred p;\n\t"
        "setp.ne.u32 p, %5, 0;\n\t"
        "tcgen05.mma.cta_group::1.kind::f16 [%0], [%1], %2, %3, {%4,%4,%4,%4}, p;\n\t}"
        :: "r"(d), "r"(a_tmem), "l"(b), "r"(idesc), "r"(0u), "r"(en) : "memory");
}
#endif

// idescs: F32 accum, bf16 A/B, M=128; N variants
#define GEMM_IDESC ((1u<<4)|(1u<<7)|(1u<<10)|((128u/8)<<17)|((128u/16)<<24))
#define IDESC_S    ((1u<<4)|(1u<<7)|(1u<<10)|((64u/8)<<17)|((128u/16)<<24))
#define IDESC_PV   GEMM_IDESC

// ---------------------------------------------------------------------------
// fp32 -> bf16 hi/lo split (4x float4 per thread for MLP)
// ---------------------------------------------------------------------------
__global__ void split_bf16(const float* __restrict__ in,
                           __nv_bfloat16* __restrict__ hi,
                           __nv_bfloat16* __restrict__ lo, int n4) {
    int i0 = (blockIdx.x * blockDim.x + threadIdx.x) * 4;
    if (i0 >= n4) return;
    float4 vv[4];
#pragma unroll
    for (int q = 0; q < 4; ++q) vv[q] = ((const float4*)in)[i0 + q];
    __nv_bfloat162* hp = (__nv_bfloat162*)hi;
    __nv_bfloat162* lp = (__nv_bfloat162*)lo;
#pragma unroll
    for (int q = 0; q < 4; ++q) {
        float4 v = vv[q];
        __nv_bfloat16 h0 = __float2bfloat16(v.x);
        __nv_bfloat16 h1 = __float2bfloat16(v.y);
        __nv_bfloat16 h2 = __float2bfloat16(v.z);
        __nv_bfloat16 h3 = __float2bfloat16(v.w);
        int i = i0 + q;
        hp[i * 2 + 0] = __halves2bfloat162(h0, h1);
        hp[i * 2 + 1] = __halves2bfloat162(h2, h3);
        lp[i * 2 + 0] = __halves2bfloat162(
            __float2bfloat16(v.x - __bfloat162float(h0)),
            __float2bfloat16(v.y - __bfloat162float(h1)));
        lp[i * 2 + 1] = __halves2bfloat162(
            __float2bfloat16(v.z - __bfloat162float(h2)),
            __float2bfloat16(v.w - __bfloat162float(h3)));
    }
}

// ---------------------------------------------------------------------------
// V transpose copy (bf16): Vh/Vl [seq][KV_DIM] -> Vth/Vtl [d][seq]
// ---------------------------------------------------------------------------
__global__ void vt_copy(const __nv_bfloat16* __restrict__ Vh,
                        const __nv_bfloat16* __restrict__ Vl,
                        __nv_bfloat16* __restrict__ Vth,
                        __nv_bfloat16* __restrict__ Vtl) {
    __shared__ __nv_bfloat16 th[32][33], tl[32][33];
    int s0 = blockIdx.x * 32, d0 = blockIdx.y * 32;
    int tx = threadIdx.x;
    for (int r = threadIdx.y; r < 32; r += 8) {
        long gi = (long)(s0 + r) * KV_DIM + d0 + tx;
        th[r][tx] = Vh[gi];
        tl[r][tx] = Vl[gi];
    }
    __syncthreads();
    for (int r = threadIdx.y; r < 32; r += 8) {
        long o = (long)(d0 + r) * SEQ + s0 + tx;
        Vth[o] = th[tx][r];
        Vtl[o] = tl[tx][r];
    }
}

// ---------------------------------------------------------------------------
// epilogue pair helpers
// ---------------------------------------------------------------------------
__device__ __forceinline__ void rope_pair_store(
    float v0, float v1, int row, int col, int N, float scale,
    const float* cs, const float* sn,
    __nv_bfloat16* Xh, __nv_bfloat16* Xl) {
    int p = (col & 127) >> 1;
    float c = cs[row * 64 + p], s = sn[row * 64 + p];
    float o0 = (v0 * c - v1 * s) * scale;
    float o1 = (v0 * s + v1 * c) * scale;
    uint32_t hh = bpack(o0, o1);
    __nv_bfloat162 hv = *(__nv_bfloat162*)&hh;
    uint32_t ll = bpack(o0 - __bfloat162float(hv.x),
                        o1 - __bfloat162float(hv.y));
    *(uint32_t*)&Xh[(long)row * N + col] = hh;
    *(uint32_t*)&Xl[(long)row * N + col] = ll;
}
__device__ __forceinline__ void split_pair_store(
    float o0, float o1, int row, int col, int N,
    __nv_bfloat16* Xh, __nv_bfloat16* Xl) {
    uint32_t hh = bpack(o0, o1);
    __nv_bfloat162 hv = *(__nv_bfloat162*)&hh;
    uint32_t ll = bpack(o0 - __bfloat162float(hv.x),
                        o1 - __bfloat162float(hv.y));
    *(uint32_t*)&Xh[(long)row * N + col] = hh;
    *(uint32_t*)&Xl[(long)row * N + col] = ll;
}

// ---------------------------------------------------------------------------
// Dual-path GEMM (NT): 128x256 tile, tcgen05 (mma.sync fallback). R10-proven.
// Output set 1: fp32 C, OR rope+scale+split (Ch/Cl).
// Output set 2: fp32 C2, OR plain split (C2h/C2l).
// ---------------------------------------------------------------------------
#define GT_ST_A 16384
#define GT_ST_B 32768
#define GT_STAGE (2*GT_ST_A + 2*GT_ST_B)
#define GT_SMEM (1024 + 2*GT_STAGE + 64)

__device__ __forceinline__ void gt_stage(
    const __nv_bfloat16* Ah, const __nv_bfloat16* Al,
    const __nv_bfloat16* Bh, const __nv_bfloat16* Bl,
    uint32_t sb, int m0, int n0, int K, int kc, int tid) {
#pragma unroll
    for (int i = 0; i < 4; ++i) {
        int c = tid + 256 * i;
        int row = c >> 3, col = c & 7;
        int so = row * 128 + ((col ^ (row & 7)) << 4);
        long ga = (long)(m0 + row) * K + kc + col * 8;
        cp16(sb + so,           Ah + ga);
        cp16(sb + GT_ST_A + so, Al + ga);
    }
#pragma unroll
    for (int i = 0; i < 8; ++i) {
        int c = tid + 256 * i;
        int row = c >> 3, col = c & 7;
        int so = row * 128 + ((col ^ (row & 7)) << 4);
        long gb = (long)(n0 + row) * K + kc + col * 8;
        cp16(sb + 2 * GT_ST_A + so,            Bh + gb);
        cp16(sb + 2 * GT_ST_A + GT_ST_B + so,  Bl + gb);
    }
    cp_commit();
}

__global__ __launch_bounds__(256, 1)
void gemm_tc(const __nv_bfloat16* __restrict__ Ah,
             const __nv_bfloat16* __restrict__ Al,
             const __nv_bfloat16* __restrict__ Bh_,
             const __nv_bfloat16* __restrict__ Bl_,
             float* __restrict__ C_,
             __nv_bfloat16* __restrict__ Ch,
             __nv_bfloat16* __restrict__ Cl,
             float scale,
             const __nv_bfloat16* __restrict__ Bh2,
             const __nv_bfloat16* __restrict__ Bl2,
             float* __restrict__ C2,
             __nv_bfloat16* __restrict__ C2h,
             __nv_bfloat16* __restrict__ C2l,
             const float* __restrict__ cs,
             const float* __restrict__ sn,
             int M, int N, int K) {
    extern __shared__ char smg_raw[];
    uint32_t u = smaddr(smg_raw);
    uint32_t t0 = (u + 1023u) & ~1023u;
    const int tid = threadIdx.x;
    const int wid = tid >> 5;
    const int lane = tid & 31;
    const int m0 = blockIdx.y * 128;
    const int nst = K >> 6;

    const __nv_bfloat16* Bh = Bh_;
    const __nv_bfloat16* Bl = Bl_;
    bool second = false;
    int bx = blockIdx.x;
    if (Bh2 != nullptr) {
        int half = gridDim.x >> 1;
        if (bx >= half) { bx -= half; Bh = Bh2; Bl = Bl2; second = true; }
    }
    const int n0 = bx * 256;
    const bool dosplit  = (Ch != nullptr) && !second;
    const bool dosplit2 = second && (C2h != nullptr);
    float* C = second ? C2 : C_;

#if HAS_TCGEN05
    uint32_t ctrl = t0 + 2 * GT_STAGE;
    uint32_t mb[2] = {ctrl + 8, ctrl + 16};

    if (wid == 0) {
        TCGEN05_ALLOC(ctrl, 256);
        TCGEN05_RELINQ();
    }
    if (tid == 0) {
        MBARRIER_INIT(mb[0], 1);
        MBARRIER_INIT(mb[1], 1);
    }
    __syncthreads();
    uint32_t tmem;
    asm volatile("ld.shared.b32 %0, [%1];" : "=r"(tmem) : "r"(ctrl));

    gt_stage(Ah, Al, Bh, Bl, t0,            m0, n0, K, 0,  tid);
    gt_stage(Ah, Al, Bh, Bl, t0 + GT_STAGE, m0, n0, K, 64, tid);

    for (int t = 0; t < nst; ++t) {
        if (t + 1 < nst) asm volatile("cp.async.wait_group 1;");
        else             asm volatile("cp.async.wait_group 0;");
        FENCE_ASYNC();
        __syncthreads();

        if (tid == 0) {
            TCGEN05_FENCE_AFTER();
            uint32_t base = t0 + (t & 1) * GT_STAGE;
            uint64_t dAh = MAKE_SMEM_DESC(base);
            uint64_t dAl = MAKE_SMEM_DESC(base + GT_ST_A);
            uint64_t dBh = MAKE_SMEM_DESC(base + 2 * GT_ST_A);
            uint64_t dBl = MAKE_SMEM_DESC(base + 2 * GT_ST_A + GT_ST_B);
#pragma unroll
            for (int s = 0; s < 4; ++s) {
#pragma unroll
                for (int nh = 0; nh < 2; ++nh) {
                    uint64_t bo = (uint64_t)(2 * s + nh * 1024);
                    uint32_t dd = tmem + nh * 128;
                    umma_f16_ss(dd, dAh + 2 * s, dBh + bo, GEMM_IDESC,
                                (t == 0 && s == 0) ? 0u : 1u);
                    umma_f16_ss(dd, dAh + 2 * s, dBl + bo, GEMM_IDESC, 1u);
                    umma_f16_ss(dd, dAl + 2 * s, dBh + bo, GEMM_IDESC, 1u);
                }
            }
            TCGEN05_COMMIT(mb[t & 1]);
        }

        if (t + 2 < nst) {
            MBARRIER_WAIT_PARITY(mb[t & 1], (t >> 1) & 1);
            gt_stage(Ah, Al, Bh, Bl, t0 + (t & 1) * GT_STAGE, m0, n0, K,
                     (t + 2) * 64, tid);
        }
    }

    MBARRIER_WAIT_PARITY(mb[(nst - 1) & 1], ((nst - 1) >> 1) & 1);
    TCGEN05_FENCE_AFTER();

    {
        int row = m0 + (wid & 3) * 32 + lane;
        uint32_t cb = (wid >> 2) * 128;
#pragma unroll
        for (int cc = 0; cc < 4; ++cc) {
            uint32_t r[32];
            TCGEN05_LD_X32(r, tmem + cb + cc * 32);
            TCGEN05_WAIT_LD();
            int colbase = n0 + (int)cb + cc * 32;
            if (dosplit) {
                int p0 = (colbase & 127) >> 1;
                const float4* cs4 = (const float4*)(cs + row * 64 + p0);
                const float4* sn4 = (const float4*)(sn + row * 64 + p0);
                uint32_t hh[16], ll[16];
#pragma unroll
                for (int qv = 0; qv < 4; ++qv) {
                    float4 cv = cs4[qv];
                    float4 svv = sn4[qv];
                    float ca[4] = {cv.x, cv.y, cv.z, cv.w};
                    float sa[4] = {svv.x, svv.y, svv.z, svv.w};
#pragma unroll
                    for (int e = 0; e < 4; ++e) {
                        float v0 = __uint_as_float(r[qv * 8 + e * 2]);
                        float v1 = __uint_as_float(r[qv * 8 + e * 2 + 1]);
                        float o0 = (v0 * ca[e] - v1 * sa[e]) * scale;
                        float o1 = (v0 * sa[e] + v1 * ca[e]) * scale;
                        int j = qv * 4 + e;
                        hh[j] = bpack(o0, o1);
                        __nv_bfloat162 hv = *(__nv_bfloat162*)&hh[j];
                        ll[j] = bpack(o0 - __bfloat162float(hv.x),
                                      o1 - __bfloat162float(hv.y));
                    }
                }
                uint4* dh = (uint4*)&Ch[(long)row * N + colbase];
                uint4* dl = (uint4*)&Cl[(long)row * N + colbase];
#pragma unroll
                for (int qv = 0; qv < 4; ++qv) {
                    dh[qv] = make_uint4(hh[qv * 4], hh[qv * 4 + 1],
                                        hh[qv * 4 + 2], hh[qv * 4 + 3]);
                    dl[qv] = make_uint4(ll[qv * 4], ll[qv * 4 + 1],
                                        ll[qv * 4 + 2], ll[qv * 4 + 3]);
                }
            } else if (dosplit2) {
                uint32_t hh[16], ll[16];
#pragma unroll
                for (int j = 0; j < 16; ++j) {
                    float o0 = __uint_as_float(r[j * 2]);
                    float o1 = __uint_as_float(r[j * 2 + 1]);
                    hh[j] = bpack(o0, o1);
                    __nv_bfloat162 hv = *(__nv_bfloat162*)&hh[j];
                    ll[j] = bpack(o0 - __bfloat162float(hv.x),
                                  o1 - __bfloat162float(hv.y));
                }
                uint4* dh = (uint4*)&C2h[(long)row * N + colbase];
                uint4* dl = (uint4*)&C2l[(long)row * N + colbase];
#pragma unroll
                for (int qv = 0; qv < 4; ++qv) {
                    dh[qv] = make_uint4(hh[qv * 4], hh[qv * 4 + 1],
                                        hh[qv * 4 + 2], hh[qv * 4 + 3]);
                    dl[qv] = make_uint4(ll[qv * 4], ll[qv * 4 + 1],
                                        ll[qv * 4 + 2], ll[qv * 4 + 3]);
                }
            } else {
                float* dst = &C[(long)row * N + colbase];
#pragma unroll
                for (int q = 0; q < 8; ++q) {
                    *(float4*)(dst + q * 4) = make_float4(
                        __uint_as_float(r[q * 4 + 0]), __uint_as_float(r[q * 4 + 1]),
                        __uint_as_float(r[q * 4 + 2]), __uint_as_float(r[q * 4 + 3]));
                }
            }
        }
    }
    __syncthreads();
    if (wid == 0) TCGEN05_DEALLOC(tmem, 256);

#else
    const int wm = (wid >> 1) * 32;
    const int wn = (wid & 1) * 128;

    float acc[2][16][4];
#pragma unroll
    for (int i = 0; i < 2; ++i)
#pragma unroll
        for (int j = 0; j < 16; ++j)
#pragma unroll
            for (int q = 0; q < 4; ++q) acc[i][j][q] = 0.0f;

    for (int t = 0; t < nst; ++t) {
        gt_stage(Ah, Al, Bh, Bl, t0, m0, n0, K, t * 64, tid);
        asm volatile("cp.async.wait_group 0;");
        __syncthreads();

#pragma unroll
        for (int kb = 0; kb < 4; ++kb) {
            uint32_t ah[2][4], al[2][4];
#pragma unroll
            for (int mf = 0; mf < 2; ++mf) {
                int arow = wm + mf * 16 + (lane & 15);
                int col8 = kb * 2 + (lane >> 4);
                uint32_t off = arow * 128 + ((col8 ^ (arow & 7)) << 4);
                ldsm4(ah[mf][0], ah[mf][1], ah[mf][2], ah[mf][3], t0 + off);
                ldsm4(al[mf][0], al[mf][1], al[mf][2], al[mf][3],
                      t0 + GT_ST_A + off);
            }
#pragma unroll
            for (int np = 0; np < 8; ++np) {
                int brow = wn + np * 16 + (lane & 7) + ((lane >> 4) << 3);
                int col8 = kb * 2 + ((lane >> 3) & 1);
                uint32_t off = brow * 128 + ((col8 ^ (brow & 7)) << 4);
                uint32_t bh[4], bl[4];
                ldsm4(bh[0], bh[1], bh[2], bh[3], t0 + 2 * GT_ST_A + off);
                ldsm4(bl[0], bl[1], bl[2], bl[3],
                      t0 + 2 * GT_ST_A + GT_ST_B + off);
#pragma unroll
                for (int hf = 0; hf < 2; ++hf) {
                    int nf = np * 2 + hf;
#pragma unroll
                    for (int mf = 0; mf < 2; ++mf) {
                        mma16816(acc[mf][nf], ah[mf], bh[hf * 2], bh[hf * 2 + 1]);
                        mma16816(acc[mf][nf], ah[mf], bl[hf * 2], bl[hf * 2 + 1]);
                        mma16816(acc[mf][nf], al[mf], bh[hf * 2], bh[hf * 2 + 1]);
                    }
                }
            }
        }
        __syncthreads();
    }

#pragma unroll
    for (int mf = 0; mf < 2; ++mf) {
        int row = m0 + wm + mf * 16 + (lane >> 2);
#pragma unroll
        for (int nf = 0; nf < 16; ++nf) {
            int col = n0 + wn + nf * 8 + (lane & 3) * 2;
            if (dosplit) {
                rope_pair_store(acc[mf][nf][0], acc[mf][nf][1],
                                row, col, N, scale, cs, sn, Ch, Cl);
                rope_pair_store(acc[mf][nf][2], acc[mf][nf][3],
                                row + 8, col, N, scale, cs, sn, Ch, Cl);
            } else if (dosplit2) {
                split_pair_store(acc[mf][nf][0], acc[mf][nf][1],
                                 row, col, N, C2h, C2l);
                split_pair_store(acc[mf][nf][2], acc[mf][nf][3],
                                 row + 8, col, N, C2h, C2l);
            } else {
                *(float2*)&C[(long)row * N + col] =
                    make_float2(acc[mf][nf][0], acc[mf][nf][1]);
                *(float2*)&C[(long)(row + 8) * N + col] =
                    make_float2(acc[mf][nf][2], acc[mf][nf][3]);
            }
        }
    }
#endif
}

// ---------------------------------------------------------------------------
// tcgen05 flash attention (causal, GQA 4:1) — R10-proven structure.
// TMEM: S [0,64) | Ph [64,96) | Pl [96,128) | PV [128,256).
// ---------------------------------------------------------------------------
#define ATC_STAGE 65536
#define ATC_CTRL  (3 * 65536)
#define ATC_SMEM  (1024 + ATC_CTRL + 64 + 3072)
#define ATT_TS (64 * PADK)
#define ATT_SMEM_FB (8 * ATT_TS * 2)

__device__ __forceinline__ void atc_stage(
    const __nv_bfloat16* Kh, const __nv_bfloat16* Kl,
    const __nv_bfloat16* Vth, const __nv_bfloat16* Vtl,
    uint32_t sbase, int j0, int kvh, int tid) {
#pragma unroll
    for (int i = 0; i < 4; ++i) {
        int c = tid + 256 * i;
        int kr = c >> 4, kc = c & 15;
        int ch = kc >> 3, col = kc & 7;
        uint32_t so = sbase + ch * 8192 + kr * 128 + ((col ^ (kr & 7)) << 4);
        long g = (long)(j0 + kr) * KV_DIM + kvh * HD + kc * 8;
        cp16(so,          Kh + g);
        cp16(so + 16384,  Kl + g);
    }
#pragma unroll
    for (int i = 0; i < 4; ++i) {
        int c = tid + 256 * i;
        int vr = c >> 3, col = c & 7;
        uint32_t so = sbase + 32768 + vr * 128 + ((col ^ (vr & 7)) << 4);
        long g = (long)(kvh * HD + vr) * SEQ + j0 + col * 8;
        cp16(so,          Vth + g);
        cp16(so + 16384,  Vtl + g);
    }
    cp_commit();
}

__device__ __forceinline__ void attn_issue_fb(
    const __nv_bfloat16* Kh_, const __nv_bfloat16* Kl_,
    const __nv_bfloat16* Vh_, const __nv_bfloat16* Vl_,
    __nv_bfloat16* sKh, __nv_bfloat16* sKl,
    __nv_bfloat16* sVh, __nv_bfloat16* sVl,
    int j0, int kvh, int tid) {
#pragma unroll
    for (int i = 0; i < 4; ++i) {
        int c = tid + 256 * i;
        int row = c >> 4, c16 = c & 15;
        long g = (long)(j0 + row) * KV_DIM + kvh * HD + c16 * 8;
        int so = row * PADK + c16 * 8;
        cp16(smaddr(sKh + so), Kh_ + g);
        cp16(smaddr(sKl + so), Kl_ + g);
        cp16(smaddr(sVh + so), Vh_ + g);
        cp16(smaddr(sVl + so), Vl_ + g);
    }
    cp_commit();
}

__global__ __launch_bounds__(256, 1)
void attn_tc(const __nv_bfloat16* __restrict__ Qh,
             const __nv_bfloat16* __restrict__ Ql,
             const __nv_bfloat16* __restrict__ Kh,
             const __nv_bfloat16* __restrict__ Kl,
             const __nv_bfloat16* __restrict__ Vh,
             const __nv_bfloat16* __restrict__ Vl,
             const __nv_bfloat16* __restrict__ Vth,
             const __nv_bfloat16* __restrict__ Vtl,
             __nv_bfloat16* __restrict__ Oh,
             __nv_bfloat16* __restrict__ Ol) {
    extern __shared__ char smg_raw[];
    const int tid = threadIdx.x;
    const int lane = tid & 31;
    const int w = tid >> 5;
    const int h = blockIdx.y;
    const int kvh = h >> 2;
    const int qt = gridDim.x - 1 - blockIdx.x;
    const int q0 = qt * BQT;
    const int nt = 2 * qt + 2;

#if HAS_TCGEN05
    uint32_t u = smaddr(smg_raw);
    uint32_t t0 = (u + 1023u) & ~1023u;
    char* gb = smg_raw + (t0 - u);
    const int half = w >> 2;
    const int sp = w & 3;
    const int row = sp * 32 + lane;
    const int qrow = q0 + row;

    uint32_t ctrl = t0 + ATC_CTRL;
    uint32_t mbs = ctrl + 8, mbpv = ctrl + 16;
    float* red0 = (float*)(gb + ATC_CTRL + 64);
    float* red1 = red0 + 256;
    float* smm  = red1 + 256;
    float* sml  = smm + 128;

    if (w == 0) {
        TCGEN05_ALLOC(ctrl, 256);
        TCGEN05_RELINQ();
    }
    if (tid == 0) {
        MBARRIER_INIT(mbs, 1);
        MBARRIER_INIT(mbpv, 1);
    }
    if (tid < 128) { smm[tid] = -1e30f; sml[tid] = 0.0f; }
    __syncthreads();
    uint32_t tmem;
    asm volatile("ld.shared.b32 %0, [%1];" : "=r"(tmem) : "r"(ctrl));

#pragma unroll
    for (int i = 0; i < 8; ++i) {
        int c = tid + 256 * i;
        int r = c >> 4, kc = c & 15;
        int ch = kc >> 3, col = kc & 7;
        uint32_t so = t0 + ch * 16384 + r * 128 + ((col ^ (r & 7)) << 4);
        long g = (long)(q0 + r) * DIM + h * HD + kc * 8;
        cp16(so,          Qh + g);
        cp16(so + 32768,  Ql + g);
    }
    atc_stage(Kh, Kl, Vth, Vtl, t0 + ATC_STAGE,     0,  kvh, tid);
    atc_stage(Kh, Kl, Vth, Vtl, t0 + 2 * ATC_STAGE, 64, kvh, tid);

    float of[64];
#pragma unroll
    for (int j = 0; j < 64; ++j) of[j] = 0.0f;

    for (int t = 0; t < nt; ++t) {
        const int j0 = t * BKT;
        if (t >= 1 && t + 1 < nt)
            atc_stage(Kh, Kl, Vth, Vtl, t0 + ATC_STAGE * (1 + ((t + 1) & 1)),
                      (t + 1) * BKT, kvh, tid);
        if (t + 1 < nt) asm volatile("cp.async.wait_group 1;");
        else            asm volatile("cp.async.wait_group 0;");
        FENCE_ASYNC();
        __syncthreads();

        const uint32_t sbase = t0 + ATC_STAGE * (1 + (t & 1));

        if (tid == 0) {
            TCGEN05_FENCE_AFTER();
#pragma unroll
            for (int c = 0; c < 2; ++c) {
                uint64_t dQh = MAKE_SMEM_DESC(t0 + c * 16384);
                uint64_t dQl = MAKE_SMEM_DESC(t0 + 32768 + c * 16384);
                uint64_t dKh = MAKE_SMEM_DESC(sbase + c * 8192);
                uint64_t dKl = MAKE_SMEM_DESC(sbase + 16384 + c * 8192);
#pragma unroll
                for (int s = 0; s < 4; ++s) {
                    umma_f16_ss(tmem, dQh + 2 * s, dKh + 2 * s, IDESC_S,
                                (c == 0 && s == 0) ? 0u : 1u);
                    umma_f16_ss(tmem, dQh + 2 * s, dKl + 2 * s, IDESC_S, 1u);
                    umma_f16_ss(tmem, dQl + 2 * s, dKh + 2 * s, IDESC_S, 1u);
                }
            }
            TCGEN05_COMMIT(mbs);
        }
        MBARRIER_WAIT_PARITY(mbs, t & 1);
        TCGEN05_FENCE_AFTER();

        uint32_t sr[32];
        TCGEN05_LD_X32(sr, tmem + half * 32);
        TCGEN05_WAIT_LD();
        float sv[32];
#pragma unroll
        for (int j = 0; j < 32; ++j) sv[j] = __uint_as_float(sr[j]);
        if (t >= nt - 2) {
#pragma unroll
            for (int j = 0; j < 32; ++j)
                if (j0 + half * 32 + j > qrow) sv[j] = -1e30f;
        }
        float mymax = -1e30f;
#pragma unroll
        for (int j = 0; j < 32; ++j) mymax = fmaxf(mymax, sv[j]);
        red0[half * 128 + row] = mymax;
        __syncthreads();
        float mt = fmaxf(red0[row], red0[128 + row]);
        float mold = smm[row];
        float mn = fmaxf(mold, mt);
        float alpha = __expf(mold - mn);
        float mysum = 0.0f;
#pragma unroll
        for (int j = 0; j < 32; ++j) {
            sv[j] = __expf(sv[j] - mn);
            mysum += sv[j];
        }
        red1[half * 128 + row] = mysum;
        __syncthreads();
        if (half == 0) {
            sml[row] = sml[row] * alpha + red1[row] + red1[128 + row];
            smm[row] = mn;
        }

        uint32_t ph[16], pl[16];
#pragma unroll
        for (int j = 0; j < 16; ++j) {
            float a = sv[2 * j], b = sv[2 * j + 1];
            ph[j] = bpack(a, b);
            __nv_bfloat162 hv = *(__nv_bfloat162*)&ph[j];
            pl[j] = bpack(a - __bfloat162float(hv.x), b - __bfloat162float(hv.y));
        }
        uint32_t lo_off = (uint32_t)sp << 21;
        TCGEN05_ST_X16(tmem + 64 + half * 16 + lo_off, ph);
        TCGEN05_ST_X16(tmem + 96 + half * 16 + lo_off, pl);
        TCGEN05_WAIT_ST();
        TCGEN05_FENCE_BEFORE();
        __syncthreads();

        if (tid == 0) {
            TCGEN05_FENCE_AFTER();
            uint64_t dVh = MAKE_SMEM_DESC(sbase + 32768);
            uint64_t dVl = MAKE_SMEM_DESC(sbase + 49152);
#pragma unroll
            for (int ks = 0; ks < 4; ++ks) {
                umma_f16_ts(tmem + 128, tmem + 64 + ks * 8, dVh + 2 * ks,
                            IDESC_PV, ks == 0 ? 0u : 1u);
                umma_f16_ts(tmem + 128, tmem + 64 + ks * 8, dVl + 2 * ks,
                            IDESC_PV, 1u);
                umma_f16_ts(tmem + 128, tmem + 96 + ks * 8, dVh + 2 * ks,
                            IDESC_PV, 1u);
            }
            TCGEN05_COMMIT(mbpv);
        }
        MBARRIER_WAIT_PARITY(mbpv, t & 1);
        TCGEN05_FENCE_AFTER();

        uint32_t pv[32];
        TCGEN05_LD_X32(pv, tmem + 128 + half * 64);
        TCGEN05_WAIT_LD();
#pragma unroll
        for (int j = 0; j < 32; ++j)
            of[j] = of[j] * alpha + __uint_as_float(pv[j]);
        TCGEN05_LD_X32(pv, tmem + 128 + half * 64 + 32);
        TCGEN05_WAIT_LD();
#pragma unroll
        for (int j = 0; j < 32; ++j)
            of[32 + j] = of[32 + j] * alpha + __uint_as_float(pv[j]);
    }

    float inv = 1.0f / sml[row];
#pragma unroll
    for (int j = 0; j < 32; ++j) {
        float a = of[2 * j] * inv, b = of[2 * j + 1] * inv;
        uint32_t hh = bpack(a, b);
        __nv_bfloat162 hv = *(__nv_bfloat162*)&hh;
        uint32_t ll = bpack(a - __bfloat162float(hv.x),
                            b - __bfloat162float(hv.y));
        long o = (long)qrow * DIM + h * HD + half * 64 + 2 * j;
        *(uint32_t*)&Oh[o] = hh;
        *(uint32_t*)&Ol[o] = ll;
    }
    __syncthreads();
    if (w == 0) TCGEN05_DEALLOC(tmem, 256);

#else
    // ======================= mma.sync fallback ===============================
    __nv_bfloat16* sma = (__nv_bfloat16*)smg_raw;
    __nv_bfloat16* sKh[2] = {sma + 0 * ATT_TS, sma + 1 * ATT_TS};
    __nv_bfloat16* sKl[2] = {sma + 2 * ATT_TS, sma + 3 * ATT_TS};
    __nv_bfloat16* sVh[2] = {sma + 4 * ATT_TS, sma + 5 * ATT_TS};
    __nv_bfloat16* sVl[2] = {sma + 6 * ATT_TS, sma + 7 * ATT_TS};

    const int g = lane >> 2;
    const int qq = lane & 3;
    const int r0 = q0 + w * 16 + g;
    const int r1 = r0 + 8;
    uint32_t qfh[8][4], qfl[8][4];
#pragma unroll
    for (int k = 0; k < 8; ++k) {
        int c = h * HD + k * 16 + qq * 2;
        qfh[k][0] = *(const uint32_t*)&Qh[(long)r0 * DIM + c];
        qfh[k][1] = *(const uint32_t*)&Qh[(long)r1 * DIM + c];
        qfh[k][2] = *(const uint32_t*)&Qh[(long)r0 * DIM + c + 8];
        qfh[k][3] = *(const uint32_t*)&Qh[(long)r1 * DIM + c + 8];
        qfl[k][0] = *(const uint32_t*)&Ql[(long)r0 * DIM + c];
        qfl[k][1] = *(const uint32_t*)&Ql[(long)r1 * DIM + c];
        qfl[k][2] = *(const uint32_t*)&Ql[(long)r0 * DIM + c + 8];
        qfl[k][3] = *(const uint32_t*)&Ql[(long)r1 * DIM + c + 8];
    }

    float of[16][4];
#pragma unroll
    for (int i = 0; i < 16; ++i)
#pragma unroll
        for (int j = 0; j < 4; ++j) of[i][j] = 0.0f;
    float m0 = -1e30f, m1 = -1e30f, l0 = 0.0f, l1 = 0.0f;

    attn_issue_fb(Kh, Kl, Vh, Vl, sKh[0], sKl[0], sVh[0], sVl[0], 0, kvh, tid);

    for (int t = 0; t < nt; ++t) {
        if (t + 1 < nt) {
            int bb = (t + 1) & 1;
            attn_issue_fb(Kh, Kl, Vh, Vl, sKh[bb], sKl[bb], sVh[bb], sVl[bb],
                          (t + 1) * BKT, kvh, tid);
            asm volatile("cp.async.wait_group 1;");
        } else {
            asm volatile("cp.async.wait_group 0;");
        }
        __syncthreads();
        const int buf = t & 1;
        const int j0 = t * BKT;

        float sc[8][4];
#pragma unroll
        for (int i = 0; i < 8; ++i)
#pragma unroll
            for (int j = 0; j < 4; ++j) sc[i][j] = 0.0f;

#pragma unroll
        for (int k = 0; k < 8; ++k) {
#pragma unroll
            for (int np = 0; np < 4; ++np) {
                int brow = np * 16 + (lane & 7) + ((lane >> 4) << 3);
                int bcol = k * 16 + (((lane >> 3) & 1) << 3);
                uint32_t bh[4], bl[4];
                ldsm4(bh[0], bh[1], bh[2], bh[3],
                      smaddr(sKh[buf] + brow * PADK + bcol));
                ldsm4(bl[0], bl[1], bl[2], bl[3],
                      smaddr(sKl[buf] + brow * PADK + bcol));
#pragma unroll
                for (int hf = 0; hf < 2; ++hf) {
                    int nf = np * 2 + hf;
                    mma16816(sc[nf], qfh[k], bh[hf * 2], bh[hf * 2 + 1]);
                    mma16816(sc[nf], qfh[k], bl[hf * 2], bl[hf * 2 + 1]);
                    mma16816(sc[nf], qfl[k], bh[hf * 2], bh[hf * 2 + 1]);
                }
            }
        }

        if (t >= nt - 2) {
#pragma unroll
            for (int nf = 0; nf < 8; ++nf) {
                int cb = j0 + nf * 8 + qq * 2;
                if (cb > r0)     sc[nf][0] = -1e30f;
                if (cb + 1 > r0) sc[nf][1] = -1e30f;
                if (cb > r1)     sc[nf][2] = -1e30f;
                if (cb + 1 > r1) sc[nf][3] = -1e30f;
            }
        }

        float mt0 = -1e30f, mt1 = -1e30f;
#pragma unroll
        for (int nf = 0; nf < 8; ++nf) {
            mt0 = fmaxf(mt0, fmaxf(sc[nf][0], sc[nf][1]));
            mt1 = fmaxf(mt1, fmaxf(sc[nf][2], sc[nf][3]));
        }
        mt0 = fmaxf(mt0, __shfl_xor_sync(0xffffffff, mt0, 1));
        mt0 = fmaxf(mt0, __shfl_xor_sync(0xffffffff, mt0, 2));
        mt1 = fmaxf(mt1, __shfl_xor_sync(0xffffffff, mt1, 1));
        mt1 = fmaxf(mt1, __shfl_xor_sync(0xffffffff, mt1, 2));
        float mn0 = fmaxf(m0, mt0), mn1 = fmaxf(m1, mt1);
        float a0 = __expf(m0 - mn0), a1 = __expf(m1 - mn1);
        m0 = mn0; m1 = mn1;

        float rs0 = 0.0f, rs1 = 0.0f;
#pragma unroll
        for (int nf = 0; nf < 8; ++nf) {
            sc[nf][0] = __expf(sc[nf][0] - mn0); rs0 += sc[nf][0];
            sc[nf][1] = __expf(sc[nf][1] - mn0); rs0 += sc[nf][1];
            sc[nf][2] = __expf(sc[nf][2] - mn1); rs1 += sc[nf][2];
            sc[nf][3] = __expf(sc[nf][3] - mn1); rs1 += sc[nf][3];
        }
        rs0 += __shfl_xor_sync(0xffffffff, rs0, 1);
        rs0 += __shfl_xor_sync(0xffffffff, rs0, 2);
        rs1 += __shfl_xor_sync(0xffffffff, rs1, 1);
        rs1 += __shfl_xor_sync(0xffffffff, rs1, 2);
        l0 = l0 * a0 + rs0;
        l1 = l1 * a1 + rs1;

#pragma unroll
        for (int nf = 0; nf < 16; ++nf) {
            of[nf][0] *= a0; of[nf][1] *= a0;
            of[nf][2] *= a1; of[nf][3] *= a1;
        }

#pragma unroll
        for (int ks = 0; ks < 4; ++ks) {
            uint32_t ph[4], pl[4];
            {
                float s00 = sc[2 * ks][0],     s01 = sc[2 * ks][1];
                float s02 = sc[2 * ks][2],     s03 = sc[2 * ks][3];
                float s10 = sc[2 * ks + 1][0], s11 = sc[2 * ks + 1][1];
                float s12 = sc[2 * ks + 1][2], s13 = sc[2 * ks + 1][3];
                ph[0] = bpack(s00, s01); ph[1] = bpack(s02, s03);
                ph[2] = bpack(s10, s11); ph[3] = bpack(s12, s13);
                __nv_bfloat162* hp;
                hp = (__nv_bfloat162*)&ph[0];
                pl[0] = bpack(s00 - __bfloat162float(hp->x), s01 - __bfloat162float(hp->y));
                hp = (__nv_bfloat162*)&ph[1];
                pl[1] = bpack(s02 - __bfloat162float(hp->x), s03 - __bfloat162float(hp->y));
                hp = (__nv_bfloat162*)&ph[2];
                pl[2] = bpack(s10 - __bfloat162float(hp->x), s11 - __bfloat162float(hp->y));
                hp = (__nv_bfloat162*)&ph[3];
                pl[3] = bpack(s12 - __bfloat162float(hp->x), s13 - __bfloat162float(hp->y));
            }
            int vrow = ks * 16 + (lane & 7) + (((lane >> 3) & 1) << 3);
#pragma unroll
            for (int nn = 0; nn < 8; ++nn) {
                int vcol = nn * 16 + ((lane >> 4) << 3);
                uint32_t vh[4], vl[4];
                ldsm4t(vh[0], vh[1], vh[2], vh[3],
                       smaddr(sVh[buf] + vrow * PADK + vcol));
                ldsm4t(vl[0], vl[1], vl[2], vl[3],
                       smaddr(sVl[buf] + vrow * PADK + vcol));
                mma16816(of[nn * 2], ph, vh[0], vh[1]);
                mma16816(of[nn * 2], ph, vl[0], vl[1]);
                mma16816(of[nn * 2], pl, vh[0], vh[1]);
                mma16816(of[nn * 2 + 1], ph, vh[2], vh[3]);
                mma16816(of[nn * 2 + 1], ph, vl[2], vl[3]);
                mma16816(of[nn * 2 + 1], pl, vh[2], vh[3]);
            }
        }
        __syncthreads();
    }

    float inv0 = 1.0f / l0, inv1 = 1.0f / l1;
#pragma unroll
    for (int nf = 0; nf < 16; ++nf) {
        int col = h * HD + nf * 8 + qq * 2;
        {
            float a = of[nf][0] * inv0, b = of[nf][1] * inv0;
            uint32_t hh = bpack(a, b);
            __nv_bfloat162 hv = *(__nv_bfloat162*)&hh;
            uint32_t ll = bpack(a - __bfloat162float(hv.x),
                                b - __bfloat162float(hv.y));
            *(uint32_t*)&Oh[(long)r0 * DIM + col] = hh;
            *(uint32_t*)&Ol[(long)r0 * DIM + col] = ll;
        }
        {
            float a = of[nf][2] * inv1, b = of[nf][3] * inv1;
            uint32_t hh = bpack(a, b);
            __nv_bfloat162 hv = *(__nv_bfloat162*)&hh;
            uint32_t ll = bpack(a - __bfloat162float(hv.x),
                                b - __bfloat162float(hv.y));
            *(uint32_t*)&Oh[(long)r1 * DIM + col] = hh;
            *(uint32_t*)&Ol[(long)r1 * DIM + col] = ll;
        }
    }
#endif
}

// ---------------------------------------------------------------------------
// Launcher
// ---------------------------------------------------------------------------
extern "C" void kernel_launch(void* const* d_in, const int* in_sizes, int n_in,
                              void* d_out, int out_size) {
    const float* x  = (const float*)d_in[0];
    const float* wq = (const float*)d_in[1];
    const float* wk = (const float*)d_in[2];
    const float* wv = (const float*)d_in[3];
    const float* wo = (const float*)d_in[4];
    const float* fc = (const float*)d_in[5];
    const float* fs = (const float*)d_in[6];
    float* out = (float*)d_out;

    __nv_bfloat16 *xh, *xl, *wqh, *wql, *wkh, *wkl, *wvh, *wvl, *woh, *wol, *oh, *ol;
    __nv_bfloat16 *qh, *ql, *kh, *kl, *vh, *vl, *vth, *vtl;
    cudaGetSymbolAddress((void**)&xh,  g_xh);  cudaGetSymbolAddress((void**)&xl,  g_xl);
    cudaGetSymbolAddress((void**)&wqh, g_wqh); cudaGetSymbolAddress((void**)&wql, g_wql);
    cudaGetSymbolAddress((void**)&wkh, g_wkh); cudaGetSymbolAddress((void**)&wkl, g_wkl);
    cudaGetSymbolAddress((void**)&wvh, g_wvh); cudaGetSymbolAddress((void**)&wvl, g_wvl);
    cudaGetSymbolAddress((void**)&woh, g_woh); cudaGetSymbolAddress((void**)&wol, g_wol);
    cudaGetSymbolAddress((void**)&oh,  g_oh);  cudaGetSymbolAddress((void**)&ol,  g_ol);
    cudaGetSymbolAddress((void**)&qh,  g_Qh);  cudaGetSymbolAddress((void**)&ql,  g_Ql);
    cudaGetSymbolAddress((void**)&kh,  g_Kh);  cudaGetSymbolAddress((void**)&kl,  g_Kl);
    cudaGetSymbolAddress((void**)&vh,  g_Vh);  cudaGetSymbolAddress((void**)&vl,  g_Vl);
    cudaGetSymbolAddress((void**)&vth, g_Vth); cudaGetSymbolAddress((void**)&vtl, g_Vtl);

    cudaFuncSetAttribute(gemm_tc,
                         cudaFuncAttributeMaxDynamicSharedMemorySize, GT_SMEM);
    int att_smem = ATC_SMEM > ATT_SMEM_FB ? ATC_SMEM : ATT_SMEM_FB;
    cudaFuncSetAttribute(attn_tc,
                         cudaFuncAttributeMaxDynamicSharedMemorySize, att_smem);

    auto launch_split = [](const float* in, __nv_bfloat16* hi, __nv_bfloat16* lo, int n) {
        int n4 = n / 4;
        int nthread = n4 / 4;                 // 4 float4 per thread
        split_bf16<<<(nthread + 255) / 256, 256>>>(in, hi, lo, n4);
    };
    launch_split(x,  xh,  xl,  SEQ * DIM);
    launch_split(wq, wqh, wql, DIM * DIM);
    launch_split(wk, wkh, wkl, KV_DIM * DIM);
    launch_split(wv, wvh, wvl, KV_DIM * DIM);
    launch_split(wo, woh, wol, DIM * DIM);

    const float qscale = 0.08838834764831845f;

    // Q projection: fused RoPE + scale + hi/lo split epilogue
    gemm_tc<<<dim3(DIM / 256, SEQ / 128), 256, GT_SMEM>>>(
        xh, xl, wqh, wql, nullptr, qh, ql, qscale,
        nullptr, nullptr, nullptr, nullptr, nullptr, fc, fs, SEQ, DIM, DIM);
    // K (rope-split) + V (plain split) fused launch — no fp32 V round-trip
    gemm_tc<<<dim3(2 * KV_DIM / 256, SEQ / 128), 256, GT_SMEM>>>(
        xh, xl, wkh, wkl, nullptr, kh, kl, 1.0f,
        wvh, wvl, nullptr, vh, vl, fc, fs, SEQ, KV_DIM, DIM);

    // V transpose copy (bf16)
    vt_copy<<<dim3(SEQ / 32, KV_DIM / 32), dim3(32, 8)>>>(vh, vl, vth, vtl);

    // Flash attention (tcgen05, R10 structure) -> bf16 hi/lo output
    attn_tc<<<dim3(SEQ / BQT, NH), 256, att_smem>>>(
        qh, ql, kh, kl, vh, vl, vth, vtl, oh, ol);

    // Output projection (fp32 out)
    gemm_tc<<<dim3(DIM / 256, SEQ / 128), 256, GT_SMEM>>>(
        oh, ol, woh, wol, out, nullptr, nullptr, 0.0f,
        nullptr, nullptr, nullptr, nullptr, nullptr, fc, fs, SEQ, DIM, DIM);
}

// round 14
// speedup vs baseline: 1.2052x; 1.2052x over previous
#include <cuda_runtime.h>
#include <cuda_bf16.h>
#include <stdint.h>

#define SEQ    2048
#define DIM    4096
#define NH     32
#define NKV    8
#define HD     128
#define KV_DIM 1024
#define BQT    128
#define BKT    64
#define PADK   136

#if defined(__CUDA_ARCH_FEAT_SM103_ALL) || defined(__CUDA_ARCH_FEAT_SM100_ALL)
#define HAS_TCGEN05 1
#else
#define HAS_TCGEN05 0
#endif

// ---------------------------------------------------------------------------
// Static device scratch
// ---------------------------------------------------------------------------
__device__ float g_V[SEQ * KV_DIM];

__device__ __nv_bfloat16 g_xh[SEQ * DIM],     g_xl[SEQ * DIM];
__device__ __nv_bfloat16 g_wqh[DIM * DIM],    g_wql[DIM * DIM];
__device__ __nv_bfloat16 g_wkh[KV_DIM * DIM], g_wkl[KV_DIM * DIM];
__device__ __nv_bfloat16 g_wvh[KV_DIM * DIM], g_wvl[KV_DIM * DIM];
__device__ __nv_bfloat16 g_woh[DIM * DIM],    g_wol[DIM * DIM];
__device__ __nv_bfloat16 g_oh[SEQ * DIM],     g_ol[SEQ * DIM];

__device__ __nv_bfloat16 g_Qh[SEQ * DIM],     g_Ql[SEQ * DIM];
__device__ __nv_bfloat16 g_Kh[SEQ * KV_DIM],  g_Kl[SEQ * KV_DIM];
__device__ __nv_bfloat16 g_Vh[SEQ * KV_DIM],  g_Vl[SEQ * KV_DIM];
__device__ __nv_bfloat16 g_Vth[KV_DIM * SEQ], g_Vtl[KV_DIM * SEQ];  // [d][seq]

// ---------------------------------------------------------------------------
// Helpers
// ---------------------------------------------------------------------------
__device__ __forceinline__ uint32_t smaddr(const void* p) {
    return (uint32_t)__cvta_generic_to_shared(p);
}
__device__ __forceinline__ void cp16(uint32_t s, const void* g) {
    asm volatile("cp.async.cg.shared.global [%0], [%1], 16;" :: "r"(s), "l"(g));
}
__device__ __forceinline__ void cp_commit() {
    asm volatile("cp.async.commit_group;");
}
__device__ __forceinline__ void ldsm4(uint32_t& r0, uint32_t& r1,
                                      uint32_t& r2, uint32_t& r3, uint32_t a) {
    asm volatile("ldmatrix.sync.aligned.m8n8.x4.shared.b16 {%0,%1,%2,%3}, [%4];"
                 : "=r"(r0), "=r"(r1), "=r"(r2), "=r"(r3) : "r"(a));
}
__device__ __forceinline__ void ldsm4t(uint32_t& r0, uint32_t& r1,
                                       uint32_t& r2, uint32_t& r3, uint32_t a) {
    asm volatile("ldmatrix.sync.aligned.m8n8.x4.trans.shared.b16 {%0,%1,%2,%3}, [%4];"
                 : "=r"(r0), "=r"(r1), "=r"(r2), "=r"(r3) : "r"(a));
}
__device__ __forceinline__ void mma16816(float* c, const uint32_t* a,
                                         uint32_t b0, uint32_t b1) {
    asm volatile(
        "mma.sync.aligned.m16n8k16.row.col.f32.bf16.bf16.f32 "
        "{%0,%1,%2,%3},{%4,%5,%6,%7},{%8,%9},{%0,%1,%2,%3};"
        : "+f"(c[0]), "+f"(c[1]), "+f"(c[2]), "+f"(c[3])
        : "r"(a[0]), "r"(a[1]), "r"(a[2]), "r"(a[3]), "r"(b0), "r"(b1));
}
__device__ __forceinline__ uint32_t bpack(float a, float b) {
    __nv_bfloat162 v;
    v.x = __float2bfloat16(a);
    v.y = __float2bfloat16(b);
    return *(uint32_t*)&v;
}

// ---- tcgen05 -----------------------------------------------------------------
static constexpr uint64_t SMEM_DESC_BASE_SW128 =
    (uint64_t(2)  << 61) | (uint64_t(1) << 46) |
    (uint64_t(64) << 32) | (uint64_t(1) << 16);
#define MAKE_SMEM_DESC(base_addr) \
    (SMEM_DESC_BASE_SW128 | ((uint64_t)((base_addr) >> 4) & 0x3FFF))

#define MBARRIER_INIT(mbar, count) \
    asm volatile("mbarrier.init.shared.b64 [%0], %1;" \
                 :: "r"((uint32_t)(mbar)), "r"((uint32_t)(count)) : "memory")
#define FENCE_ASYNC() \
    asm volatile("fence.proxy.async.shared::cta;" ::: "memory")

#define MBARRIER_WAIT_PARITY(mbar_smem_addr, phase_parity) do { \
    uint32_t _mbar = (uint32_t)(mbar_smem_addr); \
    uint32_t _parity = (uint32_t)(phase_parity); \
    uint32_t _done; \
    asm volatile( \
        "{\n\t.reg .pred p;\n\t" \
        "mbarrier.try_wait.parity.acquire.cta.shared::cta.b64 p, [%1], %2;\n\t" \
        "selp.b32 %0, 1, 0, p;\n\t}" \
        : "=r"(_done) : "r"(_mbar), "r"(_parity) : "memory"); \
    if (!_done) { \
        asm volatile( \
            "{\n\t.reg .pred P1;\n\t" \
            "WAIT_LOOP_%=:\n\t" \
            "mbarrier.try_wait.parity.acquire.cta.shared::cta.b64 P1, [%0], %1, 0x989680;\n\t" \
            "@P1 bra.uni WAIT_DONE_%=;\n\t" \
            "bra.uni WAIT_LOOP_%=;\n\t" \
            "WAIT_DONE_%=:\n\t}" \
            :: "r"(_mbar), "r"(_parity) : "memory"); \
    } \
} while(0)

#if HAS_TCGEN05
#define TCGEN05_ALLOC(smem_result_addr, nCols) \
    asm volatile("tcgen05.alloc.cta_group::1.sync.aligned.shared::cta.b32 [%0], %1;" \
                 :: "r"((uint32_t)(smem_result_addr)), "r"((uint32_t)(nCols)) : "memory")
#define TCGEN05_DEALLOC(tmem_addr, nCols) \
    asm volatile("tcgen05.dealloc.cta_group::1.sync.aligned.b32 %0, %1;" \
                 :: "r"(tmem_addr), "r"((uint32_t)(nCols)))
#define TCGEN05_RELINQ() \
    asm volatile("tcgen05.relinquish_alloc_permit.cta_group::1.sync.aligned;")
#define TCGEN05_COMMIT(mbar) \
    asm volatile("tcgen05.commit.cta_group::1.mbarrier::arrive::one.shared::cluster.b64 [%0];" \
                 :: "r"((uint32_t)(mbar)) : "memory")
#define TCGEN05_FENCE_AFTER() \
    asm volatile("tcgen05.fence::after_thread_sync;" ::: "memory")
#define TCGEN05_FENCE_BEFORE() \
    asm volatile("tcgen05.fence::before_thread_sync;" ::: "memory")
#define TCGEN05_WAIT_LD() \
    asm volatile("tcgen05.wait::ld.sync.aligned;" ::: "memory")
#define TCGEN05_WAIT_ST() \
    asm volatile("tcgen05.wait::st.sync.aligned;" ::: "memory")
#define TCGEN05_LD_X32(r, tmem_addr) \
    asm volatile( \
        "tcgen05.ld.sync.aligned.32x32b.x32.b32 " \
        "{%0, %1, %2, %3, %4, %5, %6, %7, " \
        " %8, %9, %10, %11, %12, %13, %14, %15, " \
        " %16, %17, %18, %19, %20, %21, %22, %23, " \
        " %24, %25, %26, %27, %28, %29, %30, %31}, [%32];" \
        : "=r"((r)[0]),  "=r"((r)[1]),  "=r"((r)[2]),  "=r"((r)[3]), \
          "=r"((r)[4]),  "=r"((r)[5]),  "=r"((r)[6]),  "=r"((r)[7]), \
          "=r"((r)[8]),  "=r"((r)[9]),  "=r"((r)[10]), "=r"((r)[11]), \
          "=r"((r)[12]), "=r"((r)[13]), "=r"((r)[14]), "=r"((r)[15]), \
          "=r"((r)[16]), "=r"((r)[17]), "=r"((r)[18]), "=r"((r)[19]), \
          "=r"((r)[20]), "=r"((r)[21]), "=r"((r)[22]), "=r"((r)[23]), \
          "=r"((r)[24]), "=r"((r)[25]), "=r"((r)[26]), "=r"((r)[27]), \
          "=r"((r)[28]), "=r"((r)[29]), "=r"((r)[30]), "=r"((r)[31]) \
        : "r"(tmem_addr))
#define TCGEN05_ST_X16(tmem_addr, r) \
    asm volatile( \
        "tcgen05.st.sync.aligned.32x32b.x16.b32 [%0], " \
        "{%1, %2, %3, %4, %5, %6, %7, %8, " \
        " %9, %10, %11, %12, %13, %14, %15, %16};" \
        :: "r"(tmem_addr), \
           "r"((r)[0]),  "r"((r)[1]),  "r"((r)[2]),  "r"((r)[3]), \
           "r"((r)[4]),  "r"((r)[5]),  "r"((r)[6]),  "r"((r)[7]), \
           "r"((r)[8]),  "r"((r)[9]),  "r"((r)[10]), "r"((r)[11]), \
           "r"((r)[12]), "r"((r)[13]), "r"((r)[14]), "r"((r)[15]) \
        : "memory")

__device__ __forceinline__ void umma_f16_ss(uint32_t d, uint64_t a, uint64_t b,
                                            uint32_t idesc, uint32_t en) {
    asm volatile(
        "{\n\t.reg .pred p;\n\t"
        "setp.ne.u32 p, %5, 0;\n\t"
        "tcgen05.mma.cta_group::1.kind::f16 [%0], %1, %2, %3, {%4,%4,%4,%4}, p;\n\t}"
        :: "r"(d), "l"(a), "l"(b), "r"(idesc), "r"(0u), "r"(en) : "memory");
}
__device__ __forceinline__ void umma_f16_ts(uint32_t d, uint32_t a_tmem,
                                            uint64_t b, uint32_t idesc,
                                            uint32_t en) {
    asm volatile(
        "{\n\t.reg .pred p;\n\t"
        "setp.ne.u32 p, %5, 0;\n\t"
        "tcgen05.mma.cta_group::1.kind::f16 [%0], [%1], %2, %3, {%4,%4,%4,%4}, p;\n\t}"
        :: "r"(d), "r"(a_tmem), "l"(b), "r"(idesc), "r"(0u), "r"(en) : "memory");
}
#endif

// idescs: F32 accum, bf16 A/B, M=128; N variants
#define GEMM_IDESC ((1u<<4)|(1u<<7)|(1u<<10)|((128u/8)<<17)|((128u/16)<<24))
#define IDESC_S    ((1u<<4)|(1u<<7)|(1u<<10)|((64u/8)<<17)|((128u/16)<<24))
#define IDESC_PV   GEMM_IDESC

// ---------------------------------------------------------------------------
// fp32 -> bf16 hi/lo split.
// Block-tile of 1024 float4s; thread t handles t, t+256, t+512, t+768 —
// coalesced within each load (16B-contiguous lanes) AND MLP=4 per thread.
// ---------------------------------------------------------------------------
__global__ void split_bf16(const float* __restrict__ in,
                           __nv_bfloat16* __restrict__ hi,
                           __nv_bfloat16* __restrict__ lo, int n4) {
    int base = blockIdx.x * 1024 + threadIdx.x;
    float4 vv[4];
#pragma unroll
    for (int q = 0; q < 4; ++q) {
        int i = base + q * 256;
        vv[q] = (i < n4) ? ((const float4*)in)[i]
                         : make_float4(0.f, 0.f, 0.f, 0.f);
    }
    __nv_bfloat162* hp = (__nv_bfloat162*)hi;
    __nv_bfloat162* lp = (__nv_bfloat162*)lo;
#pragma unroll
    for (int q = 0; q < 4; ++q) {
        int i = base + q * 256;
        if (i >= n4) continue;
        float4 v = vv[q];
        __nv_bfloat16 h0 = __float2bfloat16(v.x);
        __nv_bfloat16 h1 = __float2bfloat16(v.y);
        __nv_bfloat16 h2 = __float2bfloat16(v.z);
        __nv_bfloat16 h3 = __float2bfloat16(v.w);
        hp[i * 2 + 0] = __halves2bfloat162(h0, h1);
        hp[i * 2 + 1] = __halves2bfloat162(h2, h3);
        lp[i * 2 + 0] = __halves2bfloat162(
            __float2bfloat16(v.x - __bfloat162float(h0)),
            __float2bfloat16(v.y - __bfloat162float(h1)));
        lp[i * 2 + 1] = __halves2bfloat162(
            __float2bfloat16(v.z - __bfloat162float(h2)),
            __float2bfloat16(v.w - __bfloat162float(h3)));
    }
}

// ---------------------------------------------------------------------------
// V transpose + split: V[seq][KV_DIM] fp32 -> Vt[d][seq] bf16 hi/lo
// ---------------------------------------------------------------------------
__global__ void vt_split(const float* __restrict__ V,
                         __nv_bfloat16* __restrict__ Vth,
                         __nv_bfloat16* __restrict__ Vtl) {
    __shared__ float tile[32][33];
    int s0 = blockIdx.x * 32, d0 = blockIdx.y * 32;
    int tx = threadIdx.x;
    for (int r = threadIdx.y; r < 32; r += 8)
        tile[r][tx] = V[(long)(s0 + r) * KV_DIM + d0 + tx];
    __syncthreads();
    for (int r = threadIdx.y; r < 32; r += 8) {
        float v = tile[tx][r];
        __nv_bfloat16 h = __float2bfloat16(v);
        long o = (long)(d0 + r) * SEQ + s0 + tx;
        Vth[o] = h;
        Vtl[o] = __float2bfloat16(v - __bfloat162float(h));
    }
}

// ---------------------------------------------------------------------------
// rope+split scalar helper (mma.sync fallback path only)
// ---------------------------------------------------------------------------
__device__ __forceinline__ void rope_pair_store(
    float v0, float v1, int row, int col, int N, float scale,
    const float* cs, const float* sn,
    __nv_bfloat16* Xh, __nv_bfloat16* Xl) {
    int p = (col & 127) >> 1;
    float c = cs[row * 64 + p], s = sn[row * 64 + p];
    float o0 = (v0 * c - v1 * s) * scale;
    float o1 = (v0 * s + v1 * c) * scale;
    uint32_t hh = bpack(o0, o1);
    __nv_bfloat162 hv = *(__nv_bfloat162*)&hh;
    uint32_t ll = bpack(o0 - __bfloat162float(hv.x),
                        o1 - __bfloat162float(hv.y));
    *(uint32_t*)&Xh[(long)row * N + col] = hh;
    *(uint32_t*)&Xl[(long)row * N + col] = ll;
}

// ---------------------------------------------------------------------------
// Dual-path GEMM (NT): 128x256 tile, tcgen05 (mma.sync fallback). R10-proven.
// ---------------------------------------------------------------------------
#define GT_ST_A 16384
#define GT_ST_B 32768
#define GT_STAGE (2*GT_ST_A + 2*GT_ST_B)
#define GT_SMEM (1024 + 2*GT_STAGE + 64)

__device__ __forceinline__ void gt_stage(
    const __nv_bfloat16* Ah, const __nv_bfloat16* Al,
    const __nv_bfloat16* Bh, const __nv_bfloat16* Bl,
    uint32_t sb, int m0, int n0, int K, int kc, int tid) {
#pragma unroll
    for (int i = 0; i < 4; ++i) {
        int c = tid + 256 * i;
        int row = c >> 3, col = c & 7;
        int so = row * 128 + ((col ^ (row & 7)) << 4);
        long ga = (long)(m0 + row) * K + kc + col * 8;
        cp16(sb + so,           Ah + ga);
        cp16(sb + GT_ST_A + so, Al + ga);
    }
#pragma unroll
    for (int i = 0; i < 8; ++i) {
        int c = tid + 256 * i;
        int row = c >> 3, col = c & 7;
        int so = row * 128 + ((col ^ (row & 7)) << 4);
        long gb = (long)(n0 + row) * K + kc + col * 8;
        cp16(sb + 2 * GT_ST_A + so,            Bh + gb);
        cp16(sb + 2 * GT_ST_A + GT_ST_B + so,  Bl + gb);
    }
    cp_commit();
}

__global__ __launch_bounds__(256, 1)
void gemm_tc(const __nv_bfloat16* __restrict__ Ah,
             const __nv_bfloat16* __restrict__ Al,
             const __nv_bfloat16* __restrict__ Bh_,
             const __nv_bfloat16* __restrict__ Bl_,
             float* __restrict__ C_,
             __nv_bfloat16* __restrict__ Ch,
             __nv_bfloat16* __restrict__ Cl,
             float scale,
             const __nv_bfloat16* __restrict__ Bh2,
             const __nv_bfloat16* __restrict__ Bl2,
             float* __restrict__ C2,
             const float* __restrict__ cs,
             const float* __restrict__ sn,
             int M, int N, int K) {
    extern __shared__ char smg_raw[];
    uint32_t u = smaddr(smg_raw);
    uint32_t t0 = (u + 1023u) & ~1023u;
    const int tid = threadIdx.x;
    const int wid = tid >> 5;
    const int lane = tid & 31;
    const int m0 = blockIdx.y * 128;
    const int nst = K >> 6;

    const __nv_bfloat16* Bh = Bh_;
    const __nv_bfloat16* Bl = Bl_;
    float* C = C_;
    bool second = false;
    int bx = blockIdx.x;
    if (C2 != nullptr) {
        int half = gridDim.x >> 1;
        if (bx >= half) { bx -= half; Bh = Bh2; Bl = Bl2; C = C2; second = true; }
    }
    const int n0 = bx * 256;
    const bool dosplit = (Ch != nullptr) && !second;

#if HAS_TCGEN05
    uint32_t ctrl = t0 + 2 * GT_STAGE;
    uint32_t mb[2] = {ctrl + 8, ctrl + 16};

    if (wid == 0) {
        TCGEN05_ALLOC(ctrl, 256);
        TCGEN05_RELINQ();
    }
    if (tid == 0) {
        MBARRIER_INIT(mb[0], 1);
        MBARRIER_INIT(mb[1], 1);
    }
    __syncthreads();
    uint32_t tmem;
    asm volatile("ld.shared.b32 %0, [%1];" : "=r"(tmem) : "r"(ctrl));

    gt_stage(Ah, Al, Bh, Bl, t0,            m0, n0, K, 0,  tid);
    gt_stage(Ah, Al, Bh, Bl, t0 + GT_STAGE, m0, n0, K, 64, tid);

    for (int t = 0; t < nst; ++t) {
        if (t + 1 < nst) asm volatile("cp.async.wait_group 1;");
        else             asm volatile("cp.async.wait_group 0;");
        FENCE_ASYNC();
        __syncthreads();

        if (tid == 0) {
            TCGEN05_FENCE_AFTER();
            uint32_t base = t0 + (t & 1) * GT_STAGE;
            uint64_t dAh = MAKE_SMEM_DESC(base);
            uint64_t dAl = MAKE_SMEM_DESC(base + GT_ST_A);
            uint64_t dBh = MAKE_SMEM_DESC(base + 2 * GT_ST_A);
            uint64_t dBl = MAKE_SMEM_DESC(base + 2 * GT_ST_A + GT_ST_B);
#pragma unroll
            for (int s = 0; s < 4; ++s) {
#pragma unroll
                for (int nh = 0; nh < 2; ++nh) {
                    uint64_t bo = (uint64_t)(2 * s + nh * 1024);
                    uint32_t dd = tmem + nh * 128;
                    umma_f16_ss(dd, dAh + 2 * s, dBh + bo, GEMM_IDESC,
                                (t == 0 && s == 0) ? 0u : 1u);
                    umma_f16_ss(dd, dAh + 2 * s, dBl + bo, GEMM_IDESC, 1u);
                    umma_f16_ss(dd, dAl + 2 * s, dBh + bo, GEMM_IDESC, 1u);
                }
            }
            TCGEN05_COMMIT(mb[t & 1]);
        }

        if (t + 2 < nst) {
            MBARRIER_WAIT_PARITY(mb[t & 1], (t >> 1) & 1);
            gt_stage(Ah, Al, Bh, Bl, t0 + (t & 1) * GT_STAGE, m0, n0, K,
                     (t + 2) * 64, tid);
        }
    }

    MBARRIER_WAIT_PARITY(mb[(nst - 1) & 1], ((nst - 1) >> 1) & 1);
    TCGEN05_FENCE_AFTER();

    {
        int row = m0 + (wid & 3) * 32 + lane;
        uint32_t cb = (wid >> 2) * 128;
#pragma unroll
        for (int cc = 0; cc < 4; ++cc) {
            uint32_t r[32];
            TCGEN05_LD_X32(r, tmem + cb + cc * 32);
            TCGEN05_WAIT_LD();
            int colbase = n0 + (int)cb + cc * 32;
            if (dosplit) {
                int p0 = (colbase & 127) >> 1;
                const float4* cs4 = (const float4*)(cs + row * 64 + p0);
                const float4* sn4 = (const float4*)(sn + row * 64 + p0);
                uint32_t hh[16], ll[16];
#pragma unroll
                for (int qv = 0; qv < 4; ++qv) {
                    float4 cv = cs4[qv];
                    float4 svv = sn4[qv];
                    float ca[4] = {cv.x, cv.y, cv.z, cv.w};
                    float sa[4] = {svv.x, svv.y, svv.z, svv.w};
#pragma unroll
                    for (int e = 0; e < 4; ++e) {
                        float v0 = __uint_as_float(r[qv * 8 + e * 2]);
                        float v1 = __uint_as_float(r[qv * 8 + e * 2 + 1]);
                        float o0 = (v0 * ca[e] - v1 * sa[e]) * scale;
                        float o1 = (v0 * sa[e] + v1 * ca[e]) * scale;
                        int j = qv * 4 + e;
                        hh[j] = bpack(o0, o1);
                        __nv_bfloat162 hv = *(__nv_bfloat162*)&hh[j];
                        ll[j] = bpack(o0 - __bfloat162float(hv.x),
                                      o1 - __bfloat162float(hv.y));
                    }
                }
                uint4* dh = (uint4*)&Ch[(long)row * N + colbase];
                uint4* dl = (uint4*)&Cl[(long)row * N + colbase];
#pragma unroll
                for (int qv = 0; qv < 4; ++qv) {
                    dh[qv] = make_uint4(hh[qv * 4], hh[qv * 4 + 1],
                                        hh[qv * 4 + 2], hh[qv * 4 + 3]);
                    dl[qv] = make_uint4(ll[qv * 4], ll[qv * 4 + 1],
                                        ll[qv * 4 + 2], ll[qv * 4 + 3]);
                }
            } else {
                float* dst = &C[(long)row * N + colbase];
#pragma unroll
                for (int q = 0; q < 8; ++q) {
                    *(float4*)(dst + q * 4) = make_float4(
                        __uint_as_float(r[q * 4 + 0]), __uint_as_float(r[q * 4 + 1]),
                        __uint_as_float(r[q * 4 + 2]), __uint_as_float(r[q * 4 + 3]));
                }
            }
        }
    }
    __syncthreads();
    if (wid == 0) TCGEN05_DEALLOC(tmem, 256);

#else
    const int wm = (wid >> 1) * 32;
    const int wn = (wid & 1) * 128;

    float acc[2][16][4];
#pragma unroll
    for (int i = 0; i < 2; ++i)
#pragma unroll
        for (int j = 0; j < 16; ++j)
#pragma unroll
            for (int q = 0; q < 4; ++q) acc[i][j][q] = 0.0f;

    for (int t = 0; t < nst; ++t) {
        gt_stage(Ah, Al, Bh, Bl, t0, m0, n0, K, t * 64, tid);
        asm volatile("cp.async.wait_group 0;");
        __syncthreads();

#pragma unroll
        for (int kb = 0; kb < 4; ++kb) {
            uint32_t ah[2][4], al[2][4];
#pragma unroll
            for (int mf = 0; mf < 2; ++mf) {
                int arow = wm + mf * 16 + (lane & 15);
                int col8 = kb * 2 + (lane >> 4);
                uint32_t off = arow * 128 + ((col8 ^ (arow & 7)) << 4);
                ldsm4(ah[mf][0], ah[mf][1], ah[mf][2], ah[mf][3], t0 + off);
                ldsm4(al[mf][0], al[mf][1], al[mf][2], al[mf][3],
                      t0 + GT_ST_A + off);
            }
#pragma unroll
            for (int np = 0; np < 8; ++np) {
                int brow = wn + np * 16 + (lane & 7) + ((lane >> 4) << 3);
                int col8 = kb * 2 + ((lane >> 3) & 1);
                uint32_t off = brow * 128 + ((col8 ^ (brow & 7)) << 4);
                uint32_t bh[4], bl[4];
                ldsm4(bh[0], bh[1], bh[2], bh[3], t0 + 2 * GT_ST_A + off);
                ldsm4(bl[0], bl[1], bl[2], bl[3],
                      t0 + 2 * GT_ST_A + GT_ST_B + off);
#pragma unroll
                for (int hf = 0; hf < 2; ++hf) {
                    int nf = np * 2 + hf;
#pragma unroll
                    for (int mf = 0; mf < 2; ++mf) {
                        mma16816(acc[mf][nf], ah[mf], bh[hf * 2], bh[hf * 2 + 1]);
                        mma16816(acc[mf][nf], ah[mf], bl[hf * 2], bl[hf * 2 + 1]);
                        mma16816(acc[mf][nf], al[mf], bh[hf * 2], bh[hf * 2 + 1]);
                    }
                }
            }
        }
        __syncthreads();
    }

#pragma unroll
    for (int mf = 0; mf < 2; ++mf) {
        int row = m0 + wm + mf * 16 + (lane >> 2);
#pragma unroll
        for (int nf = 0; nf < 16; ++nf) {
            int col = n0 + wn + nf * 8 + (lane & 3) * 2;
            if (dosplit) {
                rope_pair_store(acc[mf][nf][0], acc[mf][nf][1],
                                row, col, N, scale, cs, sn, Ch, Cl);
                rope_pair_store(acc[mf][nf][2], acc[mf][nf][3],
                                row + 8, col, N, scale, cs, sn, Ch, Cl);
            } else {
                *(float2*)&C[(long)row * N + col] =
                    make_float2(acc[mf][nf][0], acc[mf][nf][1]);
                *(float2*)&C[(long)(row + 8) * N + col] =
                    make_float2(acc[mf][nf][2], acc[mf][nf][3]);
            }
        }
    }
#endif
}

// ---------------------------------------------------------------------------
// tcgen05 flash attention (causal, GQA 4:1) — R10-proven structure.
// TMEM: S [0,64) | Ph [64,96) | Pl [96,128) | PV [128,256).
// ---------------------------------------------------------------------------
#define ATC_STAGE 65536
#define ATC_CTRL  (3 * 65536)
#define ATC_SMEM  (1024 + ATC_CTRL + 64 + 3072)
#define ATT_TS (64 * PADK)
#define ATT_SMEM_FB (8 * ATT_TS * 2)

__device__ __forceinline__ void atc_stage(
    const __nv_bfloat16* Kh, const __nv_bfloat16* Kl,
    const __nv_bfloat16* Vth, const __nv_bfloat16* Vtl,
    uint32_t sbase, int j0, int kvh, int tid) {
#pragma unroll
    for (int i = 0; i < 4; ++i) {
        int c = tid + 256 * i;
        int kr = c >> 4, kc = c & 15;
        int ch = kc >> 3, col = kc & 7;
        uint32_t so = sbase + ch * 8192 + kr * 128 + ((col ^ (kr & 7)) << 4);
        long g = (long)(j0 + kr) * KV_DIM + kvh * HD + kc * 8;
        cp16(so,          Kh + g);
        cp16(so + 16384,  Kl + g);
    }
#pragma unroll
    for (int i = 0; i < 4; ++i) {
        int c = tid + 256 * i;
        int vr = c >> 3, col = c & 7;
        uint32_t so = sbase + 32768 + vr * 128 + ((col ^ (vr & 7)) << 4);
        long g = (long)(kvh * HD + vr) * SEQ + j0 + col * 8;
        cp16(so,          Vth + g);
        cp16(so + 16384,  Vtl + g);
    }
    cp_commit();
}

__device__ __forceinline__ void attn_issue_fb(
    const __nv_bfloat16* Kh_, const __nv_bfloat16* Kl_,
    const __nv_bfloat16* Vh_, const __nv_bfloat16* Vl_,
    __nv_bfloat16* sKh, __nv_bfloat16* sKl,
    __nv_bfloat16* sVh, __nv_bfloat16* sVl,
    int j0, int kvh, int tid) {
#pragma unroll
    for (int i = 0; i < 4; ++i) {
        int c = tid + 256 * i;
        int row = c >> 4, c16 = c & 15;
        long g = (long)(j0 + row) * KV_DIM + kvh * HD + c16 * 8;
        int so = row * PADK + c16 * 8;
        cp16(smaddr(sKh + so), Kh_ + g);
        cp16(smaddr(sKl + so), Kl_ + g);
        cp16(smaddr(sVh + so), Vh_ + g);
        cp16(smaddr(sVl + so), Vl_ + g);
    }
    cp_commit();
}

__global__ __launch_bounds__(256, 1)
void attn_tc(const __nv_bfloat16* __restrict__ Qh,
             const __nv_bfloat16* __restrict__ Ql,
             const __nv_bfloat16* __restrict__ Kh,
             const __nv_bfloat16* __restrict__ Kl,
             const __nv_bfloat16* __restrict__ Vh,
             const __nv_bfloat16* __restrict__ Vl,
             const __nv_bfloat16* __restrict__ Vth,
             const __nv_bfloat16* __restrict__ Vtl,
             __nv_bfloat16* __restrict__ Oh,
             __nv_bfloat16* __restrict__ Ol) {
    extern __shared__ char smg_raw[];
    const int tid = threadIdx.x;
    const int lane = tid & 31;
    const int w = tid >> 5;
    const int h = blockIdx.y;
    const int kvh = h >> 2;
    const int qt = gridDim.x - 1 - blockIdx.x;
    const int q0 = qt * BQT;
    const int nt = 2 * qt + 2;

#if HAS_TCGEN05
    uint32_t u = smaddr(smg_raw);
    uint32_t t0 = (u + 1023u) & ~1023u;
    char* gb = smg_raw + (t0 - u);
    const int half = w >> 2;
    const int sp = w & 3;
    const int row = sp * 32 + lane;
    const int qrow = q0 + row;

    uint32_t ctrl = t0 + ATC_CTRL;
    uint32_t mbs = ctrl + 8, mbpv = ctrl + 16;
    float* red0 = (float*)(gb + ATC_CTRL + 64);
    float* red1 = red0 + 256;
    float* smm  = red1 + 256;
    float* sml  = smm + 128;

    if (w == 0) {
        TCGEN05_ALLOC(ctrl, 256);
        TCGEN05_RELINQ();
    }
    if (tid == 0) {
        MBARRIER_INIT(mbs, 1);
        MBARRIER_INIT(mbpv, 1);
    }
    if (tid < 128) { smm[tid] = -1e30f; sml[tid] = 0.0f; }
    __syncthreads();
    uint32_t tmem;
    asm volatile("ld.shared.b32 %0, [%1];" : "=r"(tmem) : "r"(ctrl));

#pragma unroll
    for (int i = 0; i < 8; ++i) {
        int c = tid + 256 * i;
        int r = c >> 4, kc = c & 15;
        int ch = kc >> 3, col = kc & 7;
        uint32_t so = t0 + ch * 16384 + r * 128 + ((col ^ (r & 7)) << 4);
        long g = (long)(q0 + r) * DIM + h * HD + kc * 8;
        cp16(so,          Qh + g);
        cp16(so + 32768,  Ql + g);
    }
    atc_stage(Kh, Kl, Vth, Vtl, t0 + ATC_STAGE,     0,  kvh, tid);
    atc_stage(Kh, Kl, Vth, Vtl, t0 + 2 * ATC_STAGE, 64, kvh, tid);

    float of[64];
#pragma unroll
    for (int j = 0; j < 64; ++j) of[j] = 0.0f;

    for (int t = 0; t < nt; ++t) {
        const int j0 = t * BKT;
        if (t >= 1 && t + 1 < nt)
            atc_stage(Kh, Kl, Vth, Vtl, t0 + ATC_STAGE * (1 + ((t + 1) & 1)),
                      (t + 1) * BKT, kvh, tid);
        if (t + 1 < nt) asm volatile("cp.async.wait_group 1;");
        else            asm volatile("cp.async.wait_group 0;");
        FENCE_ASYNC();
        __syncthreads();

        const uint32_t sbase = t0 + ATC_STAGE * (1 + (t & 1));

        if (tid == 0) {
            TCGEN05_FENCE_AFTER();
#pragma unroll
            for (int c = 0; c < 2; ++c) {
                uint64_t dQh = MAKE_SMEM_DESC(t0 + c * 16384);
                uint64_t dQl = MAKE_SMEM_DESC(t0 + 32768 + c * 16384);
                uint64_t dKh = MAKE_SMEM_DESC(sbase + c * 8192);
                uint64_t dKl = MAKE_SMEM_DESC(sbase + 16384 + c * 8192);
#pragma unroll
                for (int s = 0; s < 4; ++s) {
                    umma_f16_ss(tmem, dQh + 2 * s, dKh + 2 * s, IDESC_S,
                                (c == 0 && s == 0) ? 0u : 1u);
                    umma_f16_ss(tmem, dQh + 2 * s, dKl + 2 * s, IDESC_S, 1u);
                    umma_f16_ss(tmem, dQl + 2 * s, dKh + 2 * s, IDESC_S, 1u);
                }
            }
            TCGEN05_COMMIT(mbs);
        }
        MBARRIER_WAIT_PARITY(mbs, t & 1);
        TCGEN05_FENCE_AFTER();

        uint32_t sr[32];
        TCGEN05_LD_X32(sr, tmem + half * 32);
        TCGEN05_WAIT_LD();
        float sv[32];
#pragma unroll
        for (int j = 0; j < 32; ++j) sv[j] = __uint_as_float(sr[j]);
        if (t >= nt - 2) {
#pragma unroll
            for (int j = 0; j < 32; ++j)
                if (j0 + half * 32 + j > qrow) sv[j] = -1e30f;
        }
        float mymax = -1e30f;
#pragma unroll
        for (int j = 0; j < 32; ++j) mymax = fmaxf(mymax, sv[j]);
        red0[half * 128 + row] = mymax;
        __syncthreads();
        float mt = fmaxf(red0[row], red0[128 + row]);
        float mold = smm[row];
        float mn = fmaxf(mold, mt);
        float alpha = __expf(mold - mn);
        float mysum = 0.0f;
#pragma unroll
        for (int j = 0; j < 32; ++j) {
            sv[j] = __expf(sv[j] - mn);
            mysum += sv[j];
        }
        red1[half * 128 + row] = mysum;
        __syncthreads();
        if (half == 0) {
            sml[row] = sml[row] * alpha + red1[row] + red1[128 + row];
            smm[row] = mn;
        }

        uint32_t ph[16], pl[16];
#pragma unroll
        for (int j = 0; j < 16; ++j) {
            float a = sv[2 * j], b = sv[2 * j + 1];
            ph[j] = bpack(a, b);
            __nv_bfloat162 hv = *(__nv_bfloat162*)&ph[j];
            pl[j] = bpack(a - __bfloat162float(hv.x), b - __bfloat162float(hv.y));
        }
        uint32_t lo_off = (uint32_t)sp << 21;
        TCGEN05_ST_X16(tmem + 64 + half * 16 + lo_off, ph);
        TCGEN05_ST_X16(tmem + 96 + half * 16 + lo_off, pl);
        TCGEN05_WAIT_ST();
        TCGEN05_FENCE_BEFORE();
        __syncthreads();

        if (tid == 0) {
            TCGEN05_FENCE_AFTER();
            uint64_t dVh = MAKE_SMEM_DESC(sbase + 32768);
            uint64_t dVl = MAKE_SMEM_DESC(sbase + 49152);
#pragma unroll
            for (int ks = 0; ks < 4; ++ks) {
                umma_f16_ts(tmem + 128, tmem + 64 + ks * 8, dVh + 2 * ks,
                            IDESC_PV, ks == 0 ? 0u : 1u);
                umma_f16_ts(tmem + 128, tmem + 64 + ks * 8, dVl + 2 * ks,
                            IDESC_PV, 1u);
                umma_f16_ts(tmem + 128, tmem + 96 + ks * 8, dVh + 2 * ks,
                            IDESC_PV, 1u);
            }
            TCGEN05_COMMIT(mbpv);
        }
        MBARRIER_WAIT_PARITY(mbpv, t & 1);
        TCGEN05_FENCE_AFTER();

        uint32_t pv[32];
        TCGEN05_LD_X32(pv, tmem + 128 + half * 64);
        TCGEN05_WAIT_LD();
#pragma unroll
        for (int j = 0; j < 32; ++j)
            of[j] = of[j] * alpha + __uint_as_float(pv[j]);
        TCGEN05_LD_X32(pv, tmem + 128 + half * 64 + 32);
        TCGEN05_WAIT_LD();
#pragma unroll
        for (int j = 0; j < 32; ++j)
            of[32 + j] = of[32 + j] * alpha + __uint_as_float(pv[j]);
    }

    float inv = 1.0f / sml[row];
#pragma unroll
    for (int j = 0; j < 32; ++j) {
        float a = of[2 * j] * inv, b = of[2 * j + 1] * inv;
        uint32_t hh = bpack(a, b);
        __nv_bfloat162 hv = *(__nv_bfloat162*)&hh;
        uint32_t ll = bpack(a - __bfloat162float(hv.x),
                            b - __bfloat162float(hv.y));
        long o = (long)qrow * DIM + h * HD + half * 64 + 2 * j;
        *(uint32_t*)&Oh[o] = hh;
        *(uint32_t*)&Ol[o] = ll;
    }
    __syncthreads();
    if (w == 0) TCGEN05_DEALLOC(tmem, 256);

#else
    // ======================= mma.sync fallback ===============================
    __nv_bfloat16* sma = (__nv_bfloat16*)smg_raw;
    __nv_bfloat16* sKh[2] = {sma + 0 * ATT_TS, sma + 1 * ATT_TS};
    __nv_bfloat16* sKl[2] = {sma + 2 * ATT_TS, sma + 3 * ATT_TS};
    __nv_bfloat16* sVh[2] = {sma + 4 * ATT_TS, sma + 5 * ATT_TS};
    __nv_bfloat16* sVl[2] = {sma + 6 * ATT_TS, sma + 7 * ATT_TS};

    const int g = lane >> 2;
    const int qq = lane & 3;
    const int r0 = q0 + w * 16 + g;
    const int r1 = r0 + 8;
    uint32_t qfh[8][4], qfl[8][4];
#pragma unroll
    for (int k = 0; k < 8; ++k) {
        int c = h * HD + k * 16 + qq * 2;
        qfh[k][0] = *(const uint32_t*)&Qh[(long)r0 * DIM + c];
        qfh[k][1] = *(const uint32_t*)&Qh[(long)r1 * DIM + c];
        qfh[k][2] = *(const uint32_t*)&Qh[(long)r0 * DIM + c + 8];
        qfh[k][3] = *(const uint32_t*)&Qh[(long)r1 * DIM + c + 8];
        qfl[k][0] = *(const uint32_t*)&Ql[(long)r0 * DIM + c];
        qfl[k][1] = *(const uint32_t*)&Ql[(long)r1 * DIM + c];
        qfl[k][2] = *(const uint32_t*)&Ql[(long)r0 * DIM + c + 8];
        qfl[k][3] = *(const uint32_t*)&Ql[(long)r1 * DIM + c + 8];
    }

    float of[16][4];
#pragma unroll
    for (int i = 0; i < 16; ++i)
#pragma unroll
        for (int j = 0; j < 4; ++j) of[i][j] = 0.0f;
    float m0 = -1e30f, m1 = -1e30f, l0 = 0.0f, l1 = 0.0f;

    attn_issue_fb(Kh, Kl, Vh, Vl, sKh[0], sKl[0], sVh[0], sVl[0], 0, kvh, tid);

    for (int t = 0; t < nt; ++t) {
        if (t + 1 < nt) {
            int bb = (t + 1) & 1;
            attn_issue_fb(Kh, Kl, Vh, Vl, sKh[bb], sKl[bb], sVh[bb], sVl[bb],
                          (t + 1) * BKT, kvh, tid);
            asm volatile("cp.async.wait_group 1;");
        } else {
            asm volatile("cp.async.wait_group 0;");
        }
        __syncthreads();
        const int buf = t & 1;
        const int j0 = t * BKT;

        float sc[8][4];
#pragma unroll
        for (int i = 0; i < 8; ++i)
#pragma unroll
            for (int j = 0; j < 4; ++j) sc[i][j] = 0.0f;

#pragma unroll
        for (int k = 0; k < 8; ++k) {
#pragma unroll
            for (int np = 0; np < 4; ++np) {
                int brow = np * 16 + (lane & 7) + ((lane >> 4) << 3);
                int bcol = k * 16 + (((lane >> 3) & 1) << 3);
                uint32_t bh[4], bl[4];
                ldsm4(bh[0], bh[1], bh[2], bh[3],
                      smaddr(sKh[buf] + brow * PADK + bcol));
                ldsm4(bl[0], bl[1], bl[2], bl[3],
                      smaddr(sKl[buf] + brow * PADK + bcol));
#pragma unroll
                for (int hf = 0; hf < 2; ++hf) {
                    int nf = np * 2 + hf;
                    mma16816(sc[nf], qfh[k], bh[hf * 2], bh[hf * 2 + 1]);
                    mma16816(sc[nf], qfh[k], bl[hf * 2], bl[hf * 2 + 1]);
                    mma16816(sc[nf], qfl[k], bh[hf * 2], bh[hf * 2 + 1]);
                }
            }
        }

        if (t >= nt - 2) {
#pragma unroll
            for (int nf = 0; nf < 8; ++nf) {
                int cb = j0 + nf * 8 + qq * 2;
                if (cb > r0)     sc[nf][0] = -1e30f;
                if (cb + 1 > r0) sc[nf][1] = -1e30f;
                if (cb > r1)     sc[nf][2] = -1e30f;
                if (cb + 1 > r1) sc[nf][3] = -1e30f;
            }
        }

        float mt0 = -1e30f, mt1 = -1e30f;
#pragma unroll
        for (int nf = 0; nf < 8; ++nf) {
            mt0 = fmaxf(mt0, fmaxf(sc[nf][0], sc[nf][1]));
            mt1 = fmaxf(mt1, fmaxf(sc[nf][2], sc[nf][3]));
        }
        mt0 = fmaxf(mt0, __shfl_xor_sync(0xffffffff, mt0, 1));
        mt0 = fmaxf(mt0, __shfl_xor_sync(0xffffffff, mt0, 2));
        mt1 = fmaxf(mt1, __shfl_xor_sync(0xffffffff, mt1, 1));
        mt1 = fmaxf(mt1, __shfl_xor_sync(0xffffffff, mt1, 2));
        float mn0 = fmaxf(m0, mt0), mn1 = fmaxf(m1, mt1);
        float a0 = __expf(m0 - mn0), a1 = __expf(m1 - mn1);
        m0 = mn0; m1 = mn1;

        float rs0 = 0.0f, rs1 = 0.0f;
#pragma unroll
        for (int nf = 0; nf < 8; ++nf) {
            sc[nf][0] = __expf(sc[nf][0] - mn0); rs0 += sc[nf][0];
            sc[nf][1] = __expf(sc[nf][1] - mn0); rs0 += sc[nf][1];
            sc[nf][2] = __expf(sc[nf][2] - mn1); rs1 += sc[nf][2];
            sc[nf][3] = __expf(sc[nf][3] - mn1); rs1 += sc[nf][3];
        }
        rs0 += __shfl_xor_sync(0xffffffff, rs0, 1);
        rs0 += __shfl_xor_sync(0xffffffff, rs0, 2);
        rs1 += __shfl_xor_sync(0xffffffff, rs1, 1);
        rs1 += __shfl_xor_sync(0xffffffff, rs1, 2);
        l0 = l0 * a0 + rs0;
        l1 = l1 * a1 + rs1;

#pragma unroll
        for (int nf = 0; nf < 16; ++nf) {
            of[nf][0] *= a0; of[nf][1] *= a0;
            of[nf][2] *= a1; of[nf][3] *= a1;
        }

#pragma unroll
        for (int ks = 0; ks < 4; ++ks) {
            uint32_t ph[4], pl[4];
            {
                float s00 = sc[2 * ks][0],     s01 = sc[2 * ks][1];
                float s02 = sc[2 * ks][2],     s03 = sc[2 * ks][3];
                float s10 = sc[2 * ks + 1][0], s11 = sc[2 * ks + 1][1];
                float s12 = sc[2 * ks + 1][2], s13 = sc[2 * ks + 1][3];
                ph[0] = bpack(s00, s01); ph[1] = bpack(s02, s03);
                ph[2] = bpack(s10, s11); ph[3] = bpack(s12, s13);
                __nv_bfloat162* hp;
                hp = (__nv_bfloat162*)&ph[0];
                pl[0] = bpack(s00 - __bfloat162float(hp->x), s01 - __bfloat162float(hp->y));
                hp = (__nv_bfloat162*)&ph[1];
                pl[1] = bpack(s02 - __bfloat162float(hp->x), s03 - __bfloat162float(hp->y));
                hp = (__nv_bfloat162*)&ph[2];
                pl[2] = bpack(s10 - __bfloat162float(hp->x), s11 - __bfloat162float(hp->y));
                hp = (__nv_bfloat162*)&ph[3];
                pl[3] = bpack(s12 - __bfloat162float(hp->x), s13 - __bfloat162float(hp->y));
            }
            int vrow = ks * 16 + (lane & 7) + (((lane >> 3) & 1) << 3);
#pragma unroll
            for (int nn = 0; nn < 8; ++nn) {
                int vcol = nn * 16 + ((lane >> 4) << 3);
                uint32_t vh[4], vl[4];
                ldsm4t(vh[0], vh[1], vh[2], vh[3],
                       smaddr(sVh[buf] + vrow * PADK + vcol));
                ldsm4t(vl[0], vl[1], vl[2], vl[3],
                       smaddr(sVl[buf] + vrow * PADK + vcol));
                mma16816(of[nn * 2], ph, vh[0], vh[1]);
                mma16816(of[nn * 2], ph, vl[0], vl[1]);
                mma16816(of[nn * 2], pl, vh[0], vh[1]);
                mma16816(of[nn * 2 + 1], ph, vh[2], vh[3]);
                mma16816(of[nn * 2 + 1], ph, vl[2], vl[3]);
                mma16816(of[nn * 2 + 1], pl, vh[2], vh[3]);
            }
        }
        __syncthreads();
    }

    float inv0 = 1.0f / l0, inv1 = 1.0f / l1;
#pragma unroll
    for (int nf = 0; nf < 16; ++nf) {
        int col = h * HD + nf * 8 + qq * 2;
        {
            float a = of[nf][0] * inv0, b = of[nf][1] * inv0;
            uint32_t hh = bpack(a, b);
            __nv_bfloat162 hv = *(__nv_bfloat162*)&hh;
            uint32_t ll = bpack(a - __bfloat162float(hv.x),
                                b - __bfloat162float(hv.y));
            *(uint32_t*)&Oh[(long)r0 * DIM + col] = hh;
            *(uint32_t*)&Ol[(long)r0 * DIM + col] = ll;
        }
        {
            float a = of[nf][2] * inv1, b = of[nf][3] * inv1;
            uint32_t hh = bpack(a, b);
            __nv_bfloat162 hv = *(__nv_bfloat162*)&hh;
            uint32_t ll = bpack(a - __bfloat162float(hv.x),
                                b - __bfloat162float(hv.y));
            *(uint32_t*)&Oh[(long)r1 * DIM + col] = hh;
            *(uint32_t*)&Ol[(long)r1 * DIM + col] = ll;
        }
    }
#endif
}

// ---------------------------------------------------------------------------
// Launcher
// ---------------------------------------------------------------------------
extern "C" void kernel_launch(void* const* d_in, const int* in_sizes, int n_in,
                              void* d_out, int out_size) {
    const float* x  = (const float*)d_in[0];
    const float* wq = (const float*)d_in[1];
    const float* wk = (const float*)d_in[2];
    const float* wv = (const float*)d_in[3];
    const float* wo = (const float*)d_in[4];
    const float* fc = (const float*)d_in[5];
    const float* fs = (const float*)d_in[6];
    float* out = (float*)d_out;

    float* Vp;
    cudaGetSymbolAddress((void**)&Vp, g_V);

    __nv_bfloat16 *xh, *xl, *wqh, *wql, *wkh, *wkl, *wvh, *wvl, *woh, *wol, *oh, *ol;
    __nv_bfloat16 *qh, *ql, *kh, *kl, *vh, *vl, *vth, *vtl;
    cudaGetSymbolAddress((void**)&xh,  g_xh);  cudaGetSymbolAddress((void**)&xl,  g_xl);
    cudaGetSymbolAddress((void**)&wqh, g_wqh); cudaGetSymbolAddress((void**)&wql, g_wql);
    cudaGetSymbolAddress((void**)&wkh, g_wkh); cudaGetSymbolAddress((void**)&wkl, g_wkl);
    cudaGetSymbolAddress((void**)&wvh, g_wvh); cudaGetSymbolAddress((void**)&wvl, g_wvl);
    cudaGetSymbolAddress((void**)&woh, g_woh); cudaGetSymbolAddress((void**)&wol, g_wol);
    cudaGetSymbolAddress((void**)&oh,  g_oh);  cudaGetSymbolAddress((void**)&ol,  g_ol);
    cudaGetSymbolAddress((void**)&qh,  g_Qh);  cudaGetSymbolAddress((void**)&ql,  g_Ql);
    cudaGetSymbolAddress((void**)&kh,  g_Kh);  cudaGetSymbolAddress((void**)&kl,  g_Kl);
    cudaGetSymbolAddress((void**)&vh,  g_Vh);  cudaGetSymbolAddress((void**)&vl,  g_Vl);
    cudaGetSymbolAddress((void**)&vth, g_Vth); cudaGetSymbolAddress((void**)&vtl, g_Vtl);

    cudaFuncSetAttribute(gemm_tc,
                         cudaFuncAttributeMaxDynamicSharedMemorySize, GT_SMEM);
    int att_smem = ATC_SMEM > ATT_SMEM_FB ? ATC_SMEM : ATT_SMEM_FB;
    cudaFuncSetAttribute(attn_tc,
                         cudaFuncAttributeMaxDynamicSharedMemorySize, att_smem);

    auto launch_split = [](const float* in, __nv_bfloat16* hi, __nv_bfloat16* lo, int n) {
        int n4 = n / 4;
        int nblk = (n4 + 1023) / 1024;        // 1024 float4 per block
        split_bf16<<<nblk, 256>>>(in, hi, lo, n4);
    };
    launch_split(x,  xh,  xl,  SEQ * DIM);
    launch_split(wq, wqh, wql, DIM * DIM);
    launch_split(wk, wkh, wkl, KV_DIM * DIM);
    launch_split(wv, wvh, wvl, KV_DIM * DIM);
    launch_split(wo, woh, wol, DIM * DIM);

    const float qscale = 0.08838834764831845f;

    // Q projection: fused RoPE + scale + hi/lo split epilogue (vectorized)
    gemm_tc<<<dim3(DIM / 256, SEQ / 128), 256, GT_SMEM>>>(
        xh, xl, wqh, wql, nullptr, qh, ql, qscale,
        nullptr, nullptr, nullptr, fc, fs, SEQ, DIM, DIM);
    // K (rope-split) + V (fp32) fused launch
    gemm_tc<<<dim3(2 * KV_DIM / 256, SEQ / 128), 256, GT_SMEM>>>(
        xh, xl, wkh, wkl, nullptr, kh, kl, 1.0f,
        wvh, wvl, Vp, fc, fs, SEQ, KV_DIM, DIM);

    // V splits (plain + transposed)
    launch_split(Vp, vh, vl, SEQ * KV_DIM);
    vt_split<<<dim3(SEQ / 32, KV_DIM / 32), dim3(32, 8)>>>(Vp, vth, vtl);

    // Flash attention (tcgen05, R10 structure) -> bf16 hi/lo output
    attn_tc<<<dim3(SEQ / BQT, NH), 256, att_smem>>>(
        qh, ql, kh, kl, vh, vl, vth, vtl, oh, ol);

    // Output projection (fp32 out)
    gemm_tc<<<dim3(DIM / 256, SEQ / 128), 256, GT_SMEM>>>(
        oh, ol, woh, wol, out, nullptr, nullptr, 0.0f,
        nullptr, nullptr, nullptr, fc, fs, SEQ, DIM, DIM);
}

// round 15
// speedup vs baseline: 1.2092x; 1.0033x over previous
#include <cuda_runtime.h>
#include <cuda_bf16.h>
#include <stdint.h>

#define SEQ    2048
#define DIM    4096
#define NH     32
#define NKV    8
#define HD     128
#define KV_DIM 1024
#define BQT    128
#define BKT    64
#define PADK   136

#if defined(__CUDA_ARCH_FEAT_SM103_ALL) || defined(__CUDA_ARCH_FEAT_SM100_ALL)
#define HAS_TCGEN05 1
#else
#define HAS_TCGEN05 0
#endif

// ---------------------------------------------------------------------------
// Static device scratch
// ---------------------------------------------------------------------------
__device__ float g_V[SEQ * KV_DIM];

__device__ __nv_bfloat16 g_xh[SEQ * DIM],     g_xl[SEQ * DIM];
__device__ __nv_bfloat16 g_wqh[DIM * DIM],    g_wql[DIM * DIM];
__device__ __nv_bfloat16 g_wkh[KV_DIM * DIM], g_wkl[KV_DIM * DIM];
__device__ __nv_bfloat16 g_wvh[KV_DIM * DIM], g_wvl[KV_DIM * DIM];
__device__ __nv_bfloat16 g_woh[DIM * DIM],    g_wol[DIM * DIM];
__device__ __nv_bfloat16 g_oh[SEQ * DIM],     g_ol[SEQ * DIM];

__device__ __nv_bfloat16 g_Qh[SEQ * DIM],     g_Ql[SEQ * DIM];
__device__ __nv_bfloat16 g_Kh[SEQ * KV_DIM],  g_Kl[SEQ * KV_DIM];
__device__ __nv_bfloat16 g_Vh[SEQ * KV_DIM],  g_Vl[SEQ * KV_DIM];
__device__ __nv_bfloat16 g_Vth[KV_DIM * SEQ], g_Vtl[KV_DIM * SEQ];  // [d][seq]

// ---------------------------------------------------------------------------
// Helpers
// ---------------------------------------------------------------------------
__device__ __forceinline__ uint32_t smaddr(const void* p) {
    return (uint32_t)__cvta_generic_to_shared(p);
}
__device__ __forceinline__ void cp16(uint32_t s, const void* g) {
    asm volatile("cp.async.cg.shared.global [%0], [%1], 16;" :: "r"(s), "l"(g));
}
__device__ __forceinline__ void cp_commit() {
    asm volatile("cp.async.commit_group;");
}
__device__ __forceinline__ void ldsm4(uint32_t& r0, uint32_t& r1,
                                      uint32_t& r2, uint32_t& r3, uint32_t a) {
    asm volatile("ldmatrix.sync.aligned.m8n8.x4.shared.b16 {%0,%1,%2,%3}, [%4];"
                 : "=r"(r0), "=r"(r1), "=r"(r2), "=r"(r3) : "r"(a));
}
__device__ __forceinline__ void ldsm4t(uint32_t& r0, uint32_t& r1,
                                       uint32_t& r2, uint32_t& r3, uint32_t a) {
    asm volatile("ldmatrix.sync.aligned.m8n8.x4.trans.shared.b16 {%0,%1,%2,%3}, [%4];"
                 : "=r"(r0), "=r"(r1), "=r"(r2), "=r"(r3) : "r"(a));
}
__device__ __forceinline__ void mma16816(float* c, const uint32_t* a,
                                         uint32_t b0, uint32_t b1) {
    asm volatile(
        "mma.sync.aligned.m16n8k16.row.col.f32.bf16.bf16.f32 "
        "{%0,%1,%2,%3},{%4,%5,%6,%7},{%8,%9},{%0,%1,%2,%3};"
        : "+f"(c[0]), "+f"(c[1]), "+f"(c[2]), "+f"(c[3])
        : "r"(a[0]), "r"(a[1]), "r"(a[2]), "r"(a[3]), "r"(b0), "r"(b1));
}
__device__ __forceinline__ uint32_t bpack(float a, float b) {
    __nv_bfloat162 v;
    v.x = __float2bfloat16(a);
    v.y = __float2bfloat16(b);
    return *(uint32_t*)&v;
}

// ---- tcgen05 -----------------------------------------------------------------
static constexpr uint64_t SMEM_DESC_BASE_SW128 =
    (uint64_t(2)  << 61) | (uint64_t(1) << 46) |
    (uint64_t(64) << 32) | (uint64_t(1) << 16);
#define MAKE_SMEM_DESC(base_addr) \
    (SMEM_DESC_BASE_SW128 | ((uint64_t)((base_addr) >> 4) & 0x3FFF))

#define MBARRIER_INIT(mbar, count) \
    asm volatile("mbarrier.init.shared.b64 [%0], %1;" \
                 :: "r"((uint32_t)(mbar)), "r"((uint32_t)(count)) : "memory")
#define FENCE_ASYNC() \
    asm volatile("fence.proxy.async.shared::cta;" ::: "memory")

#define MBARRIER_WAIT_PARITY(mbar_smem_addr, phase_parity) do { \
    uint32_t _mbar = (uint32_t)(mbar_smem_addr); \
    uint32_t _parity = (uint32_t)(phase_parity); \
    uint32_t _done; \
    asm volatile( \
        "{\n\t.reg .pred p;\n\t" \
        "mbarrier.try_wait.parity.acquire.cta.shared::cta.b64 p, [%1], %2;\n\t" \
        "selp.b32 %0, 1, 0, p;\n\t}" \
        : "=r"(_done) : "r"(_mbar), "r"(_parity) : "memory"); \
    if (!_done) { \
        asm volatile( \
            "{\n\t.reg .pred P1;\n\t" \
            "WAIT_LOOP_%=:\n\t" \
            "mbarrier.try_wait.parity.acquire.cta.shared::cta.b64 P1, [%0], %1, 0x989680;\n\t" \
            "@P1 bra.uni WAIT_DONE_%=;\n\t" \
            "bra.uni WAIT_LOOP_%=;\n\t" \
            "WAIT_DONE_%=:\n\t}" \
            :: "r"(_mbar), "r"(_parity) : "memory"); \
    } \
} while(0)

#if HAS_TCGEN05
#define TCGEN05_ALLOC(smem_result_addr, nCols) \
    asm volatile("tcgen05.alloc.cta_group::1.sync.aligned.shared::cta.b32 [%0], %1;" \
                 :: "r"((uint32_t)(smem_result_addr)), "r"((uint32_t)(nCols)) : "memory")
#define TCGEN05_DEALLOC(tmem_addr, nCols) \
    asm volatile("tcgen05.dealloc.cta_group::1.sync.aligned.b32 %0, %1;" \
                 :: "r"(tmem_addr), "r"((uint32_t)(nCols)))
#define TCGEN05_RELINQ() \
    asm volatile("tcgen05.relinquish_alloc_permit.cta_group::1.sync.aligned;")
#define TCGEN05_COMMIT(mbar) \
    asm volatile("tcgen05.commit.cta_group::1.mbarrier::arrive::one.shared::cluster.b64 [%0];" \
                 :: "r"((uint32_t)(mbar)) : "memory")
#define TCGEN05_FENCE_AFTER() \
    asm volatile("tcgen05.fence::after_thread_sync;" ::: "memory")
#define TCGEN05_FENCE_BEFORE() \
    asm volatile("tcgen05.fence::before_thread_sync;" ::: "memory")
#define TCGEN05_WAIT_LD() \
    asm volatile("tcgen05.wait::ld.sync.aligned;" ::: "memory")
#define TCGEN05_WAIT_ST() \
    asm volatile("tcgen05.wait::st.sync.aligned;" ::: "memory")
#define TCGEN05_LD_X32(r, tmem_addr) \
    asm volatile( \
        "tcgen05.ld.sync.aligned.32x32b.x32.b32 " \
        "{%0, %1, %2, %3, %4, %5, %6, %7, " \
        " %8, %9, %10, %11, %12, %13, %14, %15, " \
        " %16, %17, %18, %19, %20, %21, %22, %23, " \
        " %24, %25, %26, %27, %28, %29, %30, %31}, [%32];" \
        : "=r"((r)[0]),  "=r"((r)[1]),  "=r"((r)[2]),  "=r"((r)[3]), \
          "=r"((r)[4]),  "=r"((r)[5]),  "=r"((r)[6]),  "=r"((r)[7]), \
          "=r"((r)[8]),  "=r"((r)[9]),  "=r"((r)[10]), "=r"((r)[11]), \
          "=r"((r)[12]), "=r"((r)[13]), "=r"((r)[14]), "=r"((r)[15]), \
          "=r"((r)[16]), "=r"((r)[17]), "=r"((r)[18]), "=r"((r)[19]), \
          "=r"((r)[20]), "=r"((r)[21]), "=r"((r)[22]), "=r"((r)[23]), \
          "=r"((r)[24]), "=r"((r)[25]), "=r"((r)[26]), "=r"((r)[27]), \
          "=r"((r)[28]), "=r"((r)[29]), "=r"((r)[30]), "=r"((r)[31]) \
        : "r"(tmem_addr))
#define TCGEN05_ST_X16(tmem_addr, r) \
    asm volatile( \
        "tcgen05.st.sync.aligned.32x32b.x16.b32 [%0], " \
        "{%1, %2, %3, %4, %5, %6, %7, %8, " \
        " %9, %10, %11, %12, %13, %14, %15, %16};" \
        :: "r"(tmem_addr), \
           "r"((r)[0]),  "r"((r)[1]),  "r"((r)[2]),  "r"((r)[3]), \
           "r"((r)[4]),  "r"((r)[5]),  "r"((r)[6]),  "r"((r)[7]), \
           "r"((r)[8]),  "r"((r)[9]),  "r"((r)[10]), "r"((r)[11]), \
           "r"((r)[12]), "r"((r)[13]), "r"((r)[14]), "r"((r)[15]) \
        : "memory")

__device__ __forceinline__ void umma_f16_ss(uint32_t d, uint64_t a, uint64_t b,
                                            uint32_t idesc, uint32_t en) {
    asm volatile(
        "{\n\t.reg .pred p;\n\t"
        "setp.ne.u32 p, %5, 0;\n\t"
        "tcgen05.mma.cta_group::1.kind::f16 [%0], %1, %2, %3, {%4,%4,%4,%4}, p;\n\t}"
        :: "r"(d), "l"(a), "l"(b), "r"(idesc), "r"(0u), "r"(en) : "memory");
}
__device__ __forceinline__ void umma_f16_ts(uint32_t d, uint32_t a_tmem,
                                            uint64_t b, uint32_t idesc,
                                            uint32_t en) {
    asm volatile(
        "{\n\t.reg .pred p;\n\t"
        "setp.ne.u32 p, %5, 0;\n\t"
        "tcgen05.mma.cta_group::1.kind::f16 [%0], [%1], %2, %3, {%4,%4,%4,%4}, p;\n\t}"
        :: "r"(d), "r"(a_tmem), "l"(b), "r"(idesc), "r"(0u), "r"(en) : "memory");
}
#endif

// idescs: F32 accum, bf16 A/B, M=128; N variants
#define GEMM_IDESC ((1u<<4)|(1u<<7)|(1u<<10)|((128u/8)<<17)|((128u/16)<<24))
#define IDESC_S    ((1u<<4)|(1u<<7)|(1u<<10)|((64u/8)<<17)|((128u/16)<<24))
#define IDESC_PV   GEMM_IDESC

// ---------------------------------------------------------------------------
// split core: one block handles 2048 float4 at block-coalesced offsets
// (thread t -> t + q*256, q = 0..7): coalesced lanes, MLP 8.
// ---------------------------------------------------------------------------
__device__ __forceinline__ void split_block(const float* __restrict__ in,
                                            __nv_bfloat16* __restrict__ hi,
                                            __nv_bfloat16* __restrict__ lo,
                                            int base4) {
    int base = base4 + threadIdx.x;
    float4 vv[8];
#pragma unroll
    for (int q = 0; q < 8; ++q)
        vv[q] = ((const float4*)in)[base + q * 256];
    __nv_bfloat162* hp = (__nv_bfloat162*)hi;
    __nv_bfloat162* lp = (__nv_bfloat162*)lo;
#pragma unroll
    for (int q = 0; q < 8; ++q) {
        int i = base + q * 256;
        float4 v = vv[q];
        __nv_bfloat16 h0 = __float2bfloat16(v.x);
        __nv_bfloat16 h1 = __float2bfloat16(v.y);
        __nv_bfloat16 h2 = __float2bfloat16(v.z);
        __nv_bfloat16 h3 = __float2bfloat16(v.w);
        hp[i * 2 + 0] = __halves2bfloat162(h0, h1);
        hp[i * 2 + 1] = __halves2bfloat162(h2, h3);
        lp[i * 2 + 0] = __halves2bfloat162(
            __float2bfloat16(v.x - __bfloat162float(h0)),
            __float2bfloat16(v.y - __bfloat162float(h1)));
        lp[i * 2 + 1] = __halves2bfloat162(
            __float2bfloat16(v.z - __bfloat162float(h2)),
            __float2bfloat16(v.w - __bfloat162float(h3)));
    }
}

// Fused split of x, wq, wk, wv, wo in one launch.
// Segment sizes (float4): x 2M, wq 4M, wk 1M, wv 1M, wo 4M -> 2048-aligned.
// Blocks: x [0,1024) wq [1024,3072) wk [3072,3584) wv [3584,4096) wo [4096,6144)
__global__ void split_all(
    const float* __restrict__ x,  __nv_bfloat16* __restrict__ xh,  __nv_bfloat16* __restrict__ xl,
    const float* __restrict__ wq, __nv_bfloat16* __restrict__ wqh, __nv_bfloat16* __restrict__ wql,
    const float* __restrict__ wk, __nv_bfloat16* __restrict__ wkh, __nv_bfloat16* __restrict__ wkl,
    const float* __restrict__ wv, __nv_bfloat16* __restrict__ wvh, __nv_bfloat16* __restrict__ wvl,
    const float* __restrict__ wo, __nv_bfloat16* __restrict__ woh, __nv_bfloat16* __restrict__ wol) {
    int b = blockIdx.x;
    if (b < 1024)       split_block(x,  xh,  xl,  b * 2048);
    else if (b < 3072)  split_block(wq, wqh, wql, (b - 1024) * 2048);
    else if (b < 3584)  split_block(wk, wkh, wkl, (b - 3072) * 2048);
    else if (b < 4096)  split_block(wv, wvh, wvl, (b - 3584) * 2048);
    else                split_block(wo, woh, wol, (b - 4096) * 2048);
}

// V split (post-GEMM): same core, standalone
__global__ void split_v(const float* __restrict__ in,
                        __nv_bfloat16* __restrict__ hi,
                        __nv_bfloat16* __restrict__ lo) {
    split_block(in, hi, lo, blockIdx.x * 2048);
}

// ---------------------------------------------------------------------------
// V transpose + split: V[seq][KV_DIM] fp32 -> Vt[d][seq] bf16 hi/lo
// ---------------------------------------------------------------------------
__global__ void vt_split(const float* __restrict__ V,
                         __nv_bfloat16* __restrict__ Vth,
                         __nv_bfloat16* __restrict__ Vtl) {
    __shared__ float tile[32][33];
    int s0 = blockIdx.x * 32, d0 = blockIdx.y * 32;
    int tx = threadIdx.x;
    for (int r = threadIdx.y; r < 32; r += 8)
        tile[r][tx] = V[(long)(s0 + r) * KV_DIM + d0 + tx];
    __syncthreads();
    for (int r = threadIdx.y; r < 32; r += 8) {
        float v = tile[tx][r];
        __nv_bfloat16 h = __float2bfloat16(v);
        long o = (long)(d0 + r) * SEQ + s0 + tx;
        Vth[o] = h;
        Vtl[o] = __float2bfloat16(v - __bfloat162float(h));
    }
}

// ---------------------------------------------------------------------------
// rope+split scalar helper (mma.sync fallback path only)
// ---------------------------------------------------------------------------
__device__ __forceinline__ void rope_pair_store(
    float v0, float v1, int row, int col, int N, float scale,
    const float* cs, const float* sn,
    __nv_bfloat16* Xh, __nv_bfloat16* Xl) {
    int p = (col & 127) >> 1;
    float c = cs[row * 64 + p], s = sn[row * 64 + p];
    float o0 = (v0 * c - v1 * s) * scale;
    float o1 = (v0 * s + v1 * c) * scale;
    uint32_t hh = bpack(o0, o1);
    __nv_bfloat162 hv = *(__nv_bfloat162*)&hh;
    uint32_t ll = bpack(o0 - __bfloat162float(hv.x),
                        o1 - __bfloat162float(hv.y));
    *(uint32_t*)&Xh[(long)row * N + col] = hh;
    *(uint32_t*)&Xl[(long)row * N + col] = ll;
}

// ---------------------------------------------------------------------------
// Dual-path GEMM (NT): 128x256 tile, tcgen05 (mma.sync fallback). R10-proven.
// ---------------------------------------------------------------------------
#define GT_ST_A 16384
#define GT_ST_B 32768
#define GT_STAGE (2*GT_ST_A + 2*GT_ST_B)
#define GT_SMEM (1024 + 2*GT_STAGE + 64)

__device__ __forceinline__ void gt_stage(
    const __nv_bfloat16* Ah, const __nv_bfloat16* Al,
    const __nv_bfloat16* Bh, const __nv_bfloat16* Bl,
    uint32_t sb, int m0, int n0, int K, int kc, int tid) {
#pragma unroll
    for (int i = 0; i < 4; ++i) {
        int c = tid + 256 * i;
        int row = c >> 3, col = c & 7;
        int so = row * 128 + ((col ^ (row & 7)) << 4);
        long ga = (long)(m0 + row) * K + kc + col * 8;
        cp16(sb + so,           Ah + ga);
        cp16(sb + GT_ST_A + so, Al + ga);
    }
#pragma unroll
    for (int i = 0; i < 8; ++i) {
        int c = tid + 256 * i;
        int row = c >> 3, col = c & 7;
        int so = row * 128 + ((col ^ (row & 7)) << 4);
        long gb = (long)(n0 + row) * K + kc + col * 8;
        cp16(sb + 2 * GT_ST_A + so,            Bh + gb);
        cp16(sb + 2 * GT_ST_A + GT_ST_B + so,  Bl + gb);
    }
    cp_commit();
}

__global__ __launch_bounds__(256, 1)
void gemm_tc(const __nv_bfloat16* __restrict__ Ah,
             const __nv_bfloat16* __restrict__ Al,
             const __nv_bfloat16* __restrict__ Bh_,
             const __nv_bfloat16* __restrict__ Bl_,
             float* __restrict__ C_,
             __nv_bfloat16* __restrict__ Ch,
             __nv_bfloat16* __restrict__ Cl,
             float scale,
             const __nv_bfloat16* __restrict__ Bh2,
             const __nv_bfloat16* __restrict__ Bl2,
             float* __restrict__ C2,
             const float* __restrict__ cs,
             const float* __restrict__ sn,
             int M, int N, int K) {
    extern __shared__ char smg_raw[];
    uint32_t u = smaddr(smg_raw);
    uint32_t t0 = (u + 1023u) & ~1023u;
    const int tid = threadIdx.x;
    const int wid = tid >> 5;
    const int lane = tid & 31;
    const int m0 = blockIdx.y * 128;
    const int nst = K >> 6;

    const __nv_bfloat16* Bh = Bh_;
    const __nv_bfloat16* Bl = Bl_;
    float* C = C_;
    bool second = false;
    int bx = blockIdx.x;
    if (C2 != nullptr) {
        int half = gridDim.x >> 1;
        if (bx >= half) { bx -= half; Bh = Bh2; Bl = Bl2; C = C2; second = true; }
    }
    const int n0 = bx * 256;
    const bool dosplit = (Ch != nullptr) && !second;

#if HAS_TCGEN05
    uint32_t ctrl = t0 + 2 * GT_STAGE;
    uint32_t mb[2] = {ctrl + 8, ctrl + 16};

    if (wid == 0) {
        TCGEN05_ALLOC(ctrl, 256);
        TCGEN05_RELINQ();
    }
    if (tid == 0) {
        MBARRIER_INIT(mb[0], 1);
        MBARRIER_INIT(mb[1], 1);
    }
    __syncthreads();
    uint32_t tmem;
    asm volatile("ld.shared.b32 %0, [%1];" : "=r"(tmem) : "r"(ctrl));

    gt_stage(Ah, Al, Bh, Bl, t0,            m0, n0, K, 0,  tid);
    gt_stage(Ah, Al, Bh, Bl, t0 + GT_STAGE, m0, n0, K, 64, tid);

    for (int t = 0; t < nst; ++t) {
        if (t + 1 < nst) asm volatile("cp.async.wait_group 1;");
        else             asm volatile("cp.async.wait_group 0;");
        FENCE_ASYNC();
        __syncthreads();

        if (tid == 0) {
            TCGEN05_FENCE_AFTER();
            uint32_t base = t0 + (t & 1) * GT_STAGE;
            uint64_t dAh = MAKE_SMEM_DESC(base);
            uint64_t dAl = MAKE_SMEM_DESC(base + GT_ST_A);
            uint64_t dBh = MAKE_SMEM_DESC(base + 2 * GT_ST_A);
            uint64_t dBl = MAKE_SMEM_DESC(base + 2 * GT_ST_A + GT_ST_B);
#pragma unroll
            for (int s = 0; s < 4; ++s) {
#pragma unroll
                for (int nh = 0; nh < 2; ++nh) {
                    uint64_t bo = (uint64_t)(2 * s + nh * 1024);
                    uint32_t dd = tmem + nh * 128;
                    umma_f16_ss(dd, dAh + 2 * s, dBh + bo, GEMM_IDESC,
                                (t == 0 && s == 0) ? 0u : 1u);
                    umma_f16_ss(dd, dAh + 2 * s, dBl + bo, GEMM_IDESC, 1u);
                    umma_f16_ss(dd, dAl + 2 * s, dBh + bo, GEMM_IDESC, 1u);
                }
            }
            TCGEN05_COMMIT(mb[t & 1]);
        }

        if (t + 2 < nst) {
            MBARRIER_WAIT_PARITY(mb[t & 1], (t >> 1) & 1);
            gt_stage(Ah, Al, Bh, Bl, t0 + (t & 1) * GT_STAGE, m0, n0, K,
                     (t + 2) * 64, tid);
        }
    }

    MBARRIER_WAIT_PARITY(mb[(nst - 1) & 1], ((nst - 1) >> 1) & 1);
    TCGEN05_FENCE_AFTER();

    {
        int row = m0 + (wid & 3) * 32 + lane;
        uint32_t cb = (wid >> 2) * 128;
#pragma unroll
        for (int cc = 0; cc < 4; ++cc) {
            uint32_t r[32];
            TCGEN05_LD_X32(r, tmem + cb + cc * 32);
            TCGEN05_WAIT_LD();
            int colbase = n0 + (int)cb + cc * 32;
            if (dosplit) {
                int p0 = (colbase & 127) >> 1;
                const float4* cs4 = (const float4*)(cs + row * 64 + p0);
                const float4* sn4 = (const float4*)(sn + row * 64 + p0);
                uint32_t hh[16], ll[16];
#pragma unroll
                for (int qv = 0; qv < 4; ++qv) {
                    float4 cv = cs4[qv];
                    float4 svv = sn4[qv];
                    float ca[4] = {cv.x, cv.y, cv.z, cv.w};
                    float sa[4] = {svv.x, svv.y, svv.z, svv.w};
#pragma unroll
                    for (int e = 0; e < 4; ++e) {
                        float v0 = __uint_as_float(r[qv * 8 + e * 2]);
                        float v1 = __uint_as_float(r[qv * 8 + e * 2 + 1]);
                        float o0 = (v0 * ca[e] - v1 * sa[e]) * scale;
                        float o1 = (v0 * sa[e] + v1 * ca[e]) * scale;
                        int j = qv * 4 + e;
                        hh[j] = bpack(o0, o1);
                        __nv_bfloat162 hv = *(__nv_bfloat162*)&hh[j];
                        ll[j] = bpack(o0 - __bfloat162float(hv.x),
                                      o1 - __bfloat162float(hv.y));
                    }
                }
                uint4* dh = (uint4*)&Ch[(long)row * N + colbase];
                uint4* dl = (uint4*)&Cl[(long)row * N + colbase];
#pragma unroll
                for (int qv = 0; qv < 4; ++qv) {
                    dh[qv] = make_uint4(hh[qv * 4], hh[qv * 4 + 1],
                                        hh[qv * 4 + 2], hh[qv * 4 + 3]);
                    dl[qv] = make_uint4(ll[qv * 4], ll[qv * 4 + 1],
                                        ll[qv * 4 + 2], ll[qv * 4 + 3]);
                }
            } else {
                float* dst = &C[(long)row * N + colbase];
#pragma unroll
                for (int q = 0; q < 8; ++q) {
                    *(float4*)(dst + q * 4) = make_float4(
                        __uint_as_float(r[q * 4 + 0]), __uint_as_float(r[q * 4 + 1]),
                        __uint_as_float(r[q * 4 + 2]), __uint_as_float(r[q * 4 + 3]));
                }
            }
        }
    }
    __syncthreads();
    if (wid == 0) TCGEN05_DEALLOC(tmem, 256);

#else
    const int wm = (wid >> 1) * 32;
    const int wn = (wid & 1) * 128;

    float acc[2][16][4];
#pragma unroll
    for (int i = 0; i < 2; ++i)
#pragma unroll
        for (int j = 0; j < 16; ++j)
#pragma unroll
            for (int q = 0; q < 4; ++q) acc[i][j][q] = 0.0f;

    for (int t = 0; t < nst; ++t) {
        gt_stage(Ah, Al, Bh, Bl, t0, m0, n0, K, t * 64, tid);
        asm volatile("cp.async.wait_group 0;");
        __syncthreads();

#pragma unroll
        for (int kb = 0; kb < 4; ++kb) {
            uint32_t ah[2][4], al[2][4];
#pragma unroll
            for (int mf = 0; mf < 2; ++mf) {
                int arow = wm + mf * 16 + (lane & 15);
                int col8 = kb * 2 + (lane >> 4);
                uint32_t off = arow * 128 + ((col8 ^ (arow & 7)) << 4);
                ldsm4(ah[mf][0], ah[mf][1], ah[mf][2], ah[mf][3], t0 + off);
                ldsm4(al[mf][0], al[mf][1], al[mf][2], al[mf][3],
                      t0 + GT_ST_A + off);
            }
#pragma unroll
            for (int np = 0; np < 8; ++np) {
                int brow = wn + np * 16 + (lane & 7) + ((lane >> 4) << 3);
                int col8 = kb * 2 + ((lane >> 3) & 1);
                uint32_t off = brow * 128 + ((col8 ^ (brow & 7)) << 4);
                uint32_t bh[4], bl[4];
                ldsm4(bh[0], bh[1], bh[2], bh[3], t0 + 2 * GT_ST_A + off);
                ldsm4(bl[0], bl[1], bl[2], bl[3],
                      t0 + 2 * GT_ST_A + GT_ST_B + off);
#pragma unroll
                for (int hf = 0; hf < 2; ++hf) {
                    int nf = np * 2 + hf;
#pragma unroll
                    for (int mf = 0; mf < 2; ++mf) {
                        mma16816(acc[mf][nf], ah[mf], bh[hf * 2], bh[hf * 2 + 1]);
                        mma16816(acc[mf][nf], ah[mf], bl[hf * 2], bl[hf * 2 + 1]);
                        mma16816(acc[mf][nf], al[mf], bh[hf * 2], bh[hf * 2 + 1]);
                    }
                }
            }
        }
        __syncthreads();
    }

#pragma unroll
    for (int mf = 0; mf < 2; ++mf) {
        int row = m0 + wm + mf * 16 + (lane >> 2);
#pragma unroll
        for (int nf = 0; nf < 16; ++nf) {
            int col = n0 + wn + nf * 8 + (lane & 3) * 2;
            if (dosplit) {
                rope_pair_store(acc[mf][nf][0], acc[mf][nf][1],
                                row, col, N, scale, cs, sn, Ch, Cl);
                rope_pair_store(acc[mf][nf][2], acc[mf][nf][3],
                                row + 8, col, N, scale, cs, sn, Ch, Cl);
            } else {
                *(float2*)&C[(long)row * N + col] =
                    make_float2(acc[mf][nf][0], acc[mf][nf][1]);
                *(float2*)&C[(long)(row + 8) * N + col] =
                    make_float2(acc[mf][nf][2], acc[mf][nf][3]);
            }
        }
    }
#endif
}

// ---------------------------------------------------------------------------
// tcgen05 flash attention (causal, GQA 4:1) — R10-proven structure.
// TMEM: S [0,64) | Ph [64,96) | Pl [96,128) | PV [128,256).
// ---------------------------------------------------------------------------
#define ATC_STAGE 65536
#define ATC_CTRL  (3 * 65536)
#define ATC_SMEM  (1024 + ATC_CTRL + 64 + 3072)
#define ATT_TS (64 * PADK)
#define ATT_SMEM_FB (8 * ATT_TS * 2)

__device__ __forceinline__ void atc_stage(
    const __nv_bfloat16* Kh, const __nv_bfloat16* Kl,
    const __nv_bfloat16* Vth, const __nv_bfloat16* Vtl,
    uint32_t sbase, int j0, int kvh, int tid) {
#pragma unroll
    for (int i = 0; i < 4; ++i) {
        int c = tid + 256 * i;
        int kr = c >> 4, kc = c & 15;
        int ch = kc >> 3, col = kc & 7;
        uint32_t so = sbase + ch * 8192 + kr * 128 + ((col ^ (kr & 7)) << 4);
        long g = (long)(j0 + kr) * KV_DIM + kvh * HD + kc * 8;
        cp16(so,          Kh + g);
        cp16(so + 16384,  Kl + g);
    }
#pragma unroll
    for (int i = 0; i < 4; ++i) {
        int c = tid + 256 * i;
        int vr = c >> 3, col = c & 7;
        uint32_t so = sbase + 32768 + vr * 128 + ((col ^ (vr & 7)) << 4);
        long g = (long)(kvh * HD + vr) * SEQ + j0 + col * 8;
        cp16(so,          Vth + g);
        cp16(so + 16384,  Vtl + g);
    }
    cp_commit();
}

__device__ __forceinline__ void attn_issue_fb(
    const __nv_bfloat16* Kh_, const __nv_bfloat16* Kl_,
    const __nv_bfloat16* Vh_, const __nv_bfloat16* Vl_,
    __nv_bfloat16* sKh, __nv_bfloat16* sKl,
    __nv_bfloat16* sVh, __nv_bfloat16* sVl,
    int j0, int kvh, int tid) {
#pragma unroll
    for (int i = 0; i < 4; ++i) {
        int c = tid + 256 * i;
        int row = c >> 4, c16 = c & 15;
        long g = (long)(j0 + row) * KV_DIM + kvh * HD + c16 * 8;
        int so = row * PADK + c16 * 8;
        cp16(smaddr(sKh + so), Kh_ + g);
        cp16(smaddr(sKl + so), Kl_ + g);
        cp16(smaddr(sVh + so), Vh_ + g);
        cp16(smaddr(sVl + so), Vl_ + g);
    }
    cp_commit();
}

__global__ __launch_bounds__(256, 1)
void attn_tc(const __nv_bfloat16* __restrict__ Qh,
             const __nv_bfloat16* __restrict__ Ql,
             const __nv_bfloat16* __restrict__ Kh,
             const __nv_bfloat16* __restrict__ Kl,
             const __nv_bfloat16* __restrict__ Vh,
             const __nv_bfloat16* __restrict__ Vl,
             const __nv_bfloat16* __restrict__ Vth,
             const __nv_bfloat16* __restrict__ Vtl,
             __nv_bfloat16* __restrict__ Oh,
             __nv_bfloat16* __restrict__ Ol) {
    extern __shared__ char smg_raw[];
    const int tid = threadIdx.x;
    const int lane = tid & 31;
    const int w = tid >> 5;
    const int h = blockIdx.y;
    const int kvh = h >> 2;
    const int qt = gridDim.x - 1 - blockIdx.x;
    const int q0 = qt * BQT;
    const int nt = 2 * qt + 2;

#if HAS_TCGEN05
    uint32_t u = smaddr(smg_raw);
    uint32_t t0 = (u + 1023u) & ~1023u;
    char* gb = smg_raw + (t0 - u);
    const int half = w >> 2;
    const int sp = w & 3;
    const int row = sp * 32 + lane;
    const int qrow = q0 + row;

    uint32_t ctrl = t0 + ATC_CTRL;
    uint32_t mbs = ctrl + 8, mbpv = ctrl + 16;
    float* red0 = (float*)(gb + ATC_CTRL + 64);
    float* red1 = red0 + 256;
    float* smm  = red1 + 256;
    float* sml  = smm + 128;

    if (w == 0) {
        TCGEN05_ALLOC(ctrl, 256);
        TCGEN05_RELINQ();
    }
    if (tid == 0) {
        MBARRIER_INIT(mbs, 1);
        MBARRIER_INIT(mbpv, 1);
    }
    if (tid < 128) { smm[tid] = -1e30f; sml[tid] = 0.0f; }
    __syncthreads();
    uint32_t tmem;
    asm volatile("ld.shared.b32 %0, [%1];" : "=r"(tmem) : "r"(ctrl));

#pragma unroll
    for (int i = 0; i < 8; ++i) {
        int c = tid + 256 * i;
        int r = c >> 4, kc = c & 15;
        int ch = kc >> 3, col = kc & 7;
        uint32_t so = t0 + ch * 16384 + r * 128 + ((col ^ (r & 7)) << 4);
        long g = (long)(q0 + r) * DIM + h * HD + kc * 8;
        cp16(so,          Qh + g);
        cp16(so + 32768,  Ql + g);
    }
    atc_stage(Kh, Kl, Vth, Vtl, t0 + ATC_STAGE,     0,  kvh, tid);
    atc_stage(Kh, Kl, Vth, Vtl, t0 + 2 * ATC_STAGE, 64, kvh, tid);

    float of[64];
#pragma unroll
    for (int j = 0; j < 64; ++j) of[j] = 0.0f;

    for (int t = 0; t < nt; ++t) {
        const int j0 = t * BKT;
        if (t >= 1 && t + 1 < nt)
            atc_stage(Kh, Kl, Vth, Vtl, t0 + ATC_STAGE * (1 + ((t + 1) & 1)),
                      (t + 1) * BKT, kvh, tid);
        if (t + 1 < nt) asm volatile("cp.async.wait_group 1;");
        else            asm volatile("cp.async.wait_group 0;");
        FENCE_ASYNC();
        __syncthreads();

        const uint32_t sbase = t0 + ATC_STAGE * (1 + (t & 1));

        if (tid == 0) {
            TCGEN05_FENCE_AFTER();
#pragma unroll
            for (int c = 0; c < 2; ++c) {
                uint64_t dQh = MAKE_SMEM_DESC(t0 + c * 16384);
                uint64_t dQl = MAKE_SMEM_DESC(t0 + 32768 + c * 16384);
                uint64_t dKh = MAKE_SMEM_DESC(sbase + c * 8192);
                uint64_t dKl = MAKE_SMEM_DESC(sbase + 16384 + c * 8192);
#pragma unroll
                for (int s = 0; s < 4; ++s) {
                    umma_f16_ss(tmem, dQh + 2 * s, dKh + 2 * s, IDESC_S,
                                (c == 0 && s == 0) ? 0u : 1u);
                    umma_f16_ss(tmem, dQh + 2 * s, dKl + 2 * s, IDESC_S, 1u);
                    umma_f16_ss(tmem, dQl + 2 * s, dKh + 2 * s, IDESC_S, 1u);
                }
            }
            TCGEN05_COMMIT(mbs);
        }
        MBARRIER_WAIT_PARITY(mbs, t & 1);
        TCGEN05_FENCE_AFTER();

        uint32_t sr[32];
        TCGEN05_LD_X32(sr, tmem + half * 32);
        TCGEN05_WAIT_LD();
        float sv[32];
#pragma unroll
        for (int j = 0; j < 32; ++j) sv[j] = __uint_as_float(sr[j]);
        if (t >= nt - 2) {
#pragma unroll
            for (int j = 0; j < 32; ++j)
                if (j0 + half * 32 + j > qrow) sv[j] = -1e30f;
        }
        float mymax = -1e30f;
#pragma unroll
        for (int j = 0; j < 32; ++j) mymax = fmaxf(mymax, sv[j]);
        red0[half * 128 + row] = mymax;
        __syncthreads();
        float mt = fmaxf(red0[row], red0[128 + row]);
        float mold = smm[row];
        float mn = fmaxf(mold, mt);
        float alpha = __expf(mold - mn);
        float mysum = 0.0f;
#pragma unroll
        for (int j = 0; j < 32; ++j) {
            sv[j] = __expf(sv[j] - mn);
            mysum += sv[j];
        }
        red1[half * 128 + row] = mysum;
        __syncthreads();
        if (half == 0) {
            sml[row] = sml[row] * alpha + red1[row] + red1[128 + row];
            smm[row] = mn;
        }

        uint32_t ph[16], pl[16];
#pragma unroll
        for (int j = 0; j < 16; ++j) {
            float a = sv[2 * j], b = sv[2 * j + 1];
            ph[j] = bpack(a, b);
            __nv_bfloat162 hv = *(__nv_bfloat162*)&ph[j];
            pl[j] = bpack(a - __bfloat162float(hv.x), b - __bfloat162float(hv.y));
        }
        uint32_t lo_off = (uint32_t)sp << 21;
        TCGEN05_ST_X16(tmem + 64 + half * 16 + lo_off, ph);
        TCGEN05_ST_X16(tmem + 96 + half * 16 + lo_off, pl);
        TCGEN05_WAIT_ST();
        TCGEN05_FENCE_BEFORE();
        __syncthreads();

        if (tid == 0) {
            TCGEN05_FENCE_AFTER();
            uint64_t dVh = MAKE_SMEM_DESC(sbase + 32768);
            uint64_t dVl = MAKE_SMEM_DESC(sbase + 49152);
#pragma unroll
            for (int ks = 0; ks < 4; ++ks) {
                umma_f16_ts(tmem + 128, tmem + 64 + ks * 8, dVh + 2 * ks,
                            IDESC_PV, ks == 0 ? 0u : 1u);
                umma_f16_ts(tmem + 128, tmem + 64 + ks * 8, dVl + 2 * ks,
                            IDESC_PV, 1u);
                umma_f16_ts(tmem + 128, tmem + 96 + ks * 8, dVh + 2 * ks,
                            IDESC_PV, 1u);
            }
            TCGEN05_COMMIT(mbpv);
        }
        MBARRIER_WAIT_PARITY(mbpv, t & 1);
        TCGEN05_FENCE_AFTER();

        uint32_t pv[32];
        TCGEN05_LD_X32(pv, tmem + 128 + half * 64);
        TCGEN05_WAIT_LD();
#pragma unroll
        for (int j = 0; j < 32; ++j)
            of[j] = of[j] * alpha + __uint_as_float(pv[j]);
        TCGEN05_LD_X32(pv, tmem + 128 + half * 64 + 32);
        TCGEN05_WAIT_LD();
#pragma unroll
        for (int j = 0; j < 32; ++j)
            of[32 + j] = of[32 + j] * alpha + __uint_as_float(pv[j]);
    }

    float inv = 1.0f / sml[row];
#pragma unroll
    for (int j = 0; j < 32; ++j) {
        float a = of[2 * j] * inv, b = of[2 * j + 1] * inv;
        uint32_t hh = bpack(a, b);
        __nv_bfloat162 hv = *(__nv_bfloat162*)&hh;
        uint32_t ll = bpack(a - __bfloat162float(hv.x),
                            b - __bfloat162float(hv.y));
        long o = (long)qrow * DIM + h * HD + half * 64 + 2 * j;
        *(uint32_t*)&Oh[o] = hh;
        *(uint32_t*)&Ol[o] = ll;
    }
    __syncthreads();
    if (w == 0) TCGEN05_DEALLOC(tmem, 256);

#else
    // ======================= mma.sync fallback ===============================
    __nv_bfloat16* sma = (__nv_bfloat16*)smg_raw;
    __nv_bfloat16* sKh[2] = {sma + 0 * ATT_TS, sma + 1 * ATT_TS};
    __nv_bfloat16* sKl[2] = {sma + 2 * ATT_TS, sma + 3 * ATT_TS};
    __nv_bfloat16* sVh[2] = {sma + 4 * ATT_TS, sma + 5 * ATT_TS};
    __nv_bfloat16* sVl[2] = {sma + 6 * ATT_TS, sma + 7 * ATT_TS};

    const int g = lane >> 2;
    const int qq = lane & 3;
    const int r0 = q0 + w * 16 + g;
    const int r1 = r0 + 8;
    uint32_t qfh[8][4], qfl[8][4];
#pragma unroll
    for (int k = 0; k < 8; ++k) {
        int c = h * HD + k * 16 + qq * 2;
        qfh[k][0] = *(const uint32_t*)&Qh[(long)r0 * DIM + c];
        qfh[k][1] = *(const uint32_t*)&Qh[(long)r1 * DIM + c];
        qfh[k][2] = *(const uint32_t*)&Qh[(long)r0 * DIM + c + 8];
        qfh[k][3] = *(const uint32_t*)&Qh[(long)r1 * DIM + c + 8];
        qfl[k][0] = *(const uint32_t*)&Ql[(long)r0 * DIM + c];
        qfl[k][1] = *(const uint32_t*)&Ql[(long)r1 * DIM + c];
        qfl[k][2] = *(const uint32_t*)&Ql[(long)r0 * DIM + c + 8];
        qfl[k][3] = *(const uint32_t*)&Ql[(long)r1 * DIM + c + 8];
    }

    float of[16][4];
#pragma unroll
    for (int i = 0; i < 16; ++i)
#pragma unroll
        for (int j = 0; j < 4; ++j) of[i][j] = 0.0f;
    float m0 = -1e30f, m1 = -1e30f, l0 = 0.0f, l1 = 0.0f;

    attn_issue_fb(Kh, Kl, Vh, Vl, sKh[0], sKl[0], sVh[0], sVl[0], 0, kvh, tid);

    for (int t = 0; t < nt; ++t) {
        if (t + 1 < nt) {
            int bb = (t + 1) & 1;
            attn_issue_fb(Kh, Kl, Vh, Vl, sKh[bb], sKl[bb], sVh[bb], sVl[bb],
                          (t + 1) * BKT, kvh, tid);
            asm volatile("cp.async.wait_group 1;");
        } else {
            asm volatile("cp.async.wait_group 0;");
        }
        __syncthreads();
        const int buf = t & 1;
        const int j0 = t * BKT;

        float sc[8][4];
#pragma unroll
        for (int i = 0; i < 8; ++i)
#pragma unroll
            for (int j = 0; j < 4; ++j) sc[i][j] = 0.0f;

#pragma unroll
        for (int k = 0; k < 8; ++k) {
#pragma unroll
            for (int np = 0; np < 4; ++np) {
                int brow = np * 16 + (lane & 7) + ((lane >> 4) << 3);
                int bcol = k * 16 + (((lane >> 3) & 1) << 3);
                uint32_t bh[4], bl[4];
                ldsm4(bh[0], bh[1], bh[2], bh[3],
                      smaddr(sKh[buf] + brow * PADK + bcol));
                ldsm4(bl[0], bl[1], bl[2], bl[3],
                      smaddr(sKl[buf] + brow * PADK + bcol));
#pragma unroll
                for (int hf = 0; hf < 2; ++hf) {
                    int nf = np * 2 + hf;
                    mma16816(sc[nf], qfh[k], bh[hf * 2], bh[hf * 2 + 1]);
                    mma16816(sc[nf], qfh[k], bl[hf * 2], bl[hf * 2 + 1]);
                    mma16816(sc[nf], qfl[k], bh[hf * 2], bh[hf * 2 + 1]);
                }
            }
        }

        if (t >= nt - 2) {
#pragma unroll
            for (int nf = 0; nf < 8; ++nf) {
                int cb = j0 + nf * 8 + qq * 2;
                if (cb > r0)     sc[nf][0] = -1e30f;
                if (cb + 1 > r0) sc[nf][1] = -1e30f;
                if (cb > r1)     sc[nf][2] = -1e30f;
                if (cb + 1 > r1) sc[nf][3] = -1e30f;
            }
        }

        float mt0 = -1e30f, mt1 = -1e30f;
#pragma unroll
        for (int nf = 0; nf < 8; ++nf) {
            mt0 = fmaxf(mt0, fmaxf(sc[nf][0], sc[nf][1]));
            mt1 = fmaxf(mt1, fmaxf(sc[nf][2], sc[nf][3]));
        }
        mt0 = fmaxf(mt0, __shfl_xor_sync(0xffffffff, mt0, 1));
        mt0 = fmaxf(mt0, __shfl_xor_sync(0xffffffff, mt0, 2));
        mt1 = fmaxf(mt1, __shfl_xor_sync(0xffffffff, mt1, 1));
        mt1 = fmaxf(mt1, __shfl_xor_sync(0xffffffff, mt1, 2));
        float mn0 = fmaxf(m0, mt0), mn1 = fmaxf(m1, mt1);
        float a0 = __expf(m0 - mn0), a1 = __expf(m1 - mn1);
        m0 = mn0; m1 = mn1;

        float rs0 = 0.0f, rs1 = 0.0f;
#pragma unroll
        for (int nf = 0; nf < 8; ++nf) {
            sc[nf][0] = __expf(sc[nf][0] - mn0); rs0 += sc[nf][0];
            sc[nf][1] = __expf(sc[nf][1] - mn0); rs0 += sc[nf][1];
            sc[nf][2] = __expf(sc[nf][2] - mn1); rs1 += sc[nf][2];
            sc[nf][3] = __expf(sc[nf][3] - mn1); rs1 += sc[nf][3];
        }
        rs0 += __shfl_xor_sync(0xffffffff, rs0, 1);
        rs0 += __shfl_xor_sync(0xffffffff, rs0, 2);
        rs1 += __shfl_xor_sync(0xffffffff, rs1, 1);
        rs1 += __shfl_xor_sync(0xffffffff, rs1, 2);
        l0 = l0 * a0 + rs0;
        l1 = l1 * a1 + rs1;

#pragma unroll
        for (int nf = 0; nf < 16; ++nf) {
            of[nf][0] *= a0; of[nf][1] *= a0;
            of[nf][2] *= a1; of[nf][3] *= a1;
        }

#pragma unroll
        for (int ks = 0; ks < 4; ++ks) {
            uint32_t ph[4], pl[4];
            {
                float s00 = sc[2 * ks][0],     s01 = sc[2 * ks][1];
                float s02 = sc[2 * ks][2],     s03 = sc[2 * ks][3];
                float s10 = sc[2 * ks + 1][0], s11 = sc[2 * ks + 1][1];
                float s12 = sc[2 * ks + 1][2], s13 = sc[2 * ks + 1][3];
                ph[0] = bpack(s00, s01); ph[1] = bpack(s02, s03);
                ph[2] = bpack(s10, s11); ph[3] = bpack(s12, s13);
                __nv_bfloat162* hp;
                hp = (__nv_bfloat162*)&ph[0];
                pl[0] = bpack(s00 - __bfloat162float(hp->x), s01 - __bfloat162float(hp->y));
                hp = (__nv_bfloat162*)&ph[1];
                pl[1] = bpack(s02 - __bfloat162float(hp->x), s03 - __bfloat162float(hp->y));
                hp = (__nv_bfloat162*)&ph[2];
                pl[2] = bpack(s10 - __bfloat162float(hp->x), s11 - __bfloat162float(hp->y));
                hp = (__nv_bfloat162*)&ph[3];
                pl[3] = bpack(s12 - __bfloat162float(hp->x), s13 - __bfloat162float(hp->y));
            }
            int vrow = ks * 16 + (lane & 7) + (((lane >> 3) & 1) << 3);
#pragma unroll
            for (int nn = 0; nn < 8; ++nn) {
                int vcol = nn * 16 + ((lane >> 4) << 3);
                uint32_t vh[4], vl[4];
                ldsm4t(vh[0], vh[1], vh[2], vh[3],
                       smaddr(sVh[buf] + vrow * PADK + vcol));
                ldsm4t(vl[0], vl[1], vl[2], vl[3],
                       smaddr(sVl[buf] + vrow * PADK + vcol));
                mma16816(of[nn * 2], ph, vh[0], vh[1]);
                mma16816(of[nn * 2], ph, vl[0], vl[1]);
                mma16816(of[nn * 2], pl, vh[0], vh[1]);
                mma16816(of[nn * 2 + 1], ph, vh[2], vh[3]);
                mma16816(of[nn * 2 + 1], ph, vl[2], vl[3]);
                mma16816(of[nn * 2 + 1], pl, vh[2], vh[3]);
            }
        }
        __syncthreads();
    }

    float inv0 = 1.0f / l0, inv1 = 1.0f / l1;
#pragma unroll
    for (int nf = 0; nf < 16; ++nf) {
        int col = h * HD + nf * 8 + qq * 2;
        {
            float a = of[nf][0] * inv0, b = of[nf][1] * inv0;
            uint32_t hh = bpack(a, b);
            __nv_bfloat162 hv = *(__nv_bfloat162*)&hh;
            uint32_t ll = bpack(a - __bfloat162float(hv.x),
                                b - __bfloat162float(hv.y));
            *(uint32_t*)&Oh[(long)r0 * DIM + col] = hh;
            *(uint32_t*)&Ol[(long)r0 * DIM + col] = ll;
        }
        {
            float a = of[nf][2] * inv1, b = of[nf][3] * inv1;
            uint32_t hh = bpack(a, b);
            __nv_bfloat162 hv = *(__nv_bfloat162*)&hh;
            uint32_t ll = bpack(a - __bfloat162float(hv.x),
                                b - __bfloat162float(hv.y));
            *(uint32_t*)&Oh[(long)r1 * DIM + col] = hh;
            *(uint32_t*)&Ol[(long)r1 * DIM + col] = ll;
        }
    }
#endif
}

// ---------------------------------------------------------------------------
// Launcher
// ---------------------------------------------------------------------------
extern "C" void kernel_launch(void* const* d_in, const int* in_sizes, int n_in,
                              void* d_out, int out_size) {
    const float* x  = (const float*)d_in[0];
    const float* wq = (const float*)d_in[1];
    const float* wk = (const float*)d_in[2];
    const float* wv = (const float*)d_in[3];
    const float* wo = (const float*)d_in[4];
    const float* fc = (const float*)d_in[5];
    const float* fs = (const float*)d_in[6];
    float* out = (float*)d_out;

    float* Vp;
    cudaGetSymbolAddress((void**)&Vp, g_V);

    __nv_bfloat16 *xh, *xl, *wqh, *wql, *wkh, *wkl, *wvh, *wvl, *woh, *wol, *oh, *ol;
    __nv_bfloat16 *qh, *ql, *kh, *kl, *vh, *vl, *vth, *vtl;
    cudaGetSymbolAddress((void**)&xh,  g_xh);  cudaGetSymbolAddress((void**)&xl,  g_xl);
    cudaGetSymbolAddress((void**)&wqh, g_wqh); cudaGetSymbolAddress((void**)&wql, g_wql);
    cudaGetSymbolAddress((void**)&wkh, g_wkh); cudaGetSymbolAddress((void**)&wkl, g_wkl);
    cudaGetSymbolAddress((void**)&wvh, g_wvh); cudaGetSymbolAddress((void**)&wvl, g_wvl);
    cudaGetSymbolAddress((void**)&woh, g_woh); cudaGetSymbolAddress((void**)&wol, g_wol);
    cudaGetSymbolAddress((void**)&oh,  g_oh);  cudaGetSymbolAddress((void**)&ol,  g_ol);
    cudaGetSymbolAddress((void**)&qh,  g_Qh);  cudaGetSymbolAddress((void**)&ql,  g_Ql);
    cudaGetSymbolAddress((void**)&kh,  g_Kh);  cudaGetSymbolAddress((void**)&kl,  g_Kl);
    cudaGetSymbolAddress((void**)&vh,  g_Vh);  cudaGetSymbolAddress((void**)&vl,  g_Vl);
    cudaGetSymbolAddress((void**)&vth, g_Vth); cudaGetSymbolAddress((void**)&vtl, g_Vtl);

    cudaFuncSetAttribute(gemm_tc,
                         cudaFuncAttributeMaxDynamicSharedMemorySize, GT_SMEM);
    int att_smem = ATC_SMEM > ATT_SMEM_FB ? ATC_SMEM : ATT_SMEM_FB;
    cudaFuncSetAttribute(attn_tc,
                         cudaFuncAttributeMaxDynamicSharedMemorySize, att_smem);

    // Fused splits of x + all four weights (one launch, 6144 blocks)
    split_all<<<6144, 256>>>(x, xh, xl, wq, wqh, wql, wk, wkh, wkl,
                             wv, wvh, wvl, wo, woh, wol);

    const float qscale = 0.08838834764831845f;

    // Q projection: fused RoPE + scale + hi/lo split epilogue (vectorized)
    gemm_tc<<<dim3(DIM / 256, SEQ / 128), 256, GT_SMEM>>>(
        xh, xl, wqh, wql, nullptr, qh, ql, qscale,
        nullptr, nullptr, nullptr, fc, fs, SEQ, DIM, DIM);
    // K (rope-split) + V (fp32) fused launch
    gemm_tc<<<dim3(2 * KV_DIM / 256, SEQ / 128), 256, GT_SMEM>>>(
        xh, xl, wkh, wkl, nullptr, kh, kl, 1.0f,
        wvh, wvl, Vp, fc, fs, SEQ, KV_DIM, DIM);

    // V splits (plain + transposed)
    split_v<<<(SEQ * KV_DIM / 4) / 2048, 256>>>(Vp, vh, vl);
    vt_split<<<dim3(SEQ / 32, KV_DIM / 32), dim3(32, 8)>>>(Vp, vth, vtl);

    // Flash attention (tcgen05, R10 structure) -> bf16 hi/lo output
    attn_tc<<<dim3(SEQ / BQT, NH), 256, att_smem>>>(
        qh, ql, kh, kl, vh, vl, vth, vtl, oh, ol);

    // Output projection (fp32 out)
    gemm_tc<<<dim3(DIM / 256, SEQ / 128), 256, GT_SMEM>>>(
        oh, ol, woh, wol, out, nullptr, nullptr, 0.0f,
        nullptr, nullptr, nullptr, fc, fs, SEQ, DIM, DIM);
}

// round 16
// speedup vs baseline: 1.2150x; 1.0047x over previous
#include <cuda_runtime.h>
#include <cuda_bf16.h>
#include <stdint.h>

#define SEQ    2048
#define DIM    4096
#define NH     32
#define NKV    8
#define HD     128
#define KV_DIM 1024
#define BQT    128
#define BKT    64
#define PADK   136

#if defined(__CUDA_ARCH_FEAT_SM103_ALL) || defined(__CUDA_ARCH_FEAT_SM100_ALL)
#define HAS_TCGEN05 1
#else
#define HAS_TCGEN05 0
#endif

// ---------------------------------------------------------------------------
// Static device scratch
// ---------------------------------------------------------------------------
__device__ float g_V[SEQ * KV_DIM];

__device__ __nv_bfloat16 g_xh[SEQ * DIM],     g_xl[SEQ * DIM];
__device__ __nv_bfloat16 g_wqh[DIM * DIM],    g_wql[DIM * DIM];
__device__ __nv_bfloat16 g_wkh[KV_DIM * DIM], g_wkl[KV_DIM * DIM];
__device__ __nv_bfloat16 g_wvh[KV_DIM * DIM], g_wvl[KV_DIM * DIM];
__device__ __nv_bfloat16 g_woh[DIM * DIM],    g_wol[DIM * DIM];
__device__ __nv_bfloat16 g_oh[SEQ * DIM],     g_ol[SEQ * DIM];

__device__ __nv_bfloat16 g_Qh[SEQ * DIM],     g_Ql[SEQ * DIM];
__device__ __nv_bfloat16 g_Kh[SEQ * KV_DIM],  g_Kl[SEQ * KV_DIM];
__device__ __nv_bfloat16 g_Vh[SEQ * KV_DIM],  g_Vl[SEQ * KV_DIM];
__device__ __nv_bfloat16 g_Vth[KV_DIM * SEQ], g_Vtl[KV_DIM * SEQ];  // [d][seq]

// ---------------------------------------------------------------------------
// Helpers
// ---------------------------------------------------------------------------
__device__ __forceinline__ uint32_t smaddr(const void* p) {
    return (uint32_t)__cvta_generic_to_shared(p);
}
__device__ __forceinline__ void cp16(uint32_t s, const void* g) {
    asm volatile("cp.async.cg.shared.global [%0], [%1], 16;" :: "r"(s), "l"(g));
}
__device__ __forceinline__ void cp_commit() {
    asm volatile("cp.async.commit_group;");
}
__device__ __forceinline__ void ldsm4(uint32_t& r0, uint32_t& r1,
                                      uint32_t& r2, uint32_t& r3, uint32_t a) {
    asm volatile("ldmatrix.sync.aligned.m8n8.x4.shared.b16 {%0,%1,%2,%3}, [%4];"
                 : "=r"(r0), "=r"(r1), "=r"(r2), "=r"(r3) : "r"(a));
}
__device__ __forceinline__ void ldsm4t(uint32_t& r0, uint32_t& r1,
                                       uint32_t& r2, uint32_t& r3, uint32_t a) {
    asm volatile("ldmatrix.sync.aligned.m8n8.x4.trans.shared.b16 {%0,%1,%2,%3}, [%4];"
                 : "=r"(r0), "=r"(r1), "=r"(r2), "=r"(r3) : "r"(a));
}
__device__ __forceinline__ void mma16816(float* c, const uint32_t* a,
                                         uint32_t b0, uint32_t b1) {
    asm volatile(
        "mma.sync.aligned.m16n8k16.row.col.f32.bf16.bf16.f32 "
        "{%0,%1,%2,%3},{%4,%5,%6,%7},{%8,%9},{%0,%1,%2,%3};"
        : "+f"(c[0]), "+f"(c[1]), "+f"(c[2]), "+f"(c[3])
        : "r"(a[0]), "r"(a[1]), "r"(a[2]), "r"(a[3]), "r"(b0), "r"(b1));
}
__device__ __forceinline__ uint32_t bpack(float a, float b) {
    __nv_bfloat162 v;
    v.x = __float2bfloat16(a);
    v.y = __float2bfloat16(b);
    return *(uint32_t*)&v;
}

// ---- tcgen05 -----------------------------------------------------------------
static constexpr uint64_t SMEM_DESC_BASE_SW128 =
    (uint64_t(2)  << 61) | (uint64_t(1) << 46) |
    (uint64_t(64) << 32) | (uint64_t(1) << 16);
#define MAKE_SMEM_DESC(base_addr) \
    (SMEM_DESC_BASE_SW128 | ((uint64_t)((base_addr) >> 4) & 0x3FFF))

#define MBARRIER_INIT(mbar, count) \
    asm volatile("mbarrier.init.shared.b64 [%0], %1;" \
                 :: "r"((uint32_t)(mbar)), "r"((uint32_t)(count)) : "memory")
#define FENCE_ASYNC() \
    asm volatile("fence.proxy.async.shared::cta;" ::: "memory")

#define MBARRIER_WAIT_PARITY(mbar_smem_addr, phase_parity) do { \
    uint32_t _mbar = (uint32_t)(mbar_smem_addr); \
    uint32_t _parity = (uint32_t)(phase_parity); \
    uint32_t _done; \
    asm volatile( \
        "{\n\t.reg .pred p;\n\t" \
        "mbarrier.try_wait.parity.acquire.cta.shared::cta.b64 p, [%1], %2;\n\t" \
        "selp.b32 %0, 1, 0, p;\n\t}" \
        : "=r"(_done) : "r"(_mbar), "r"(_parity) : "memory"); \
    if (!_done) { \
        asm volatile( \
            "{\n\t.reg .pred P1;\n\t" \
            "WAIT_LOOP_%=:\n\t" \
            "mbarrier.try_wait.parity.acquire.cta.shared::cta.b64 P1, [%0], %1, 0x989680;\n\t" \
            "@P1 bra.uni WAIT_DONE_%=;\n\t" \
            "bra.uni WAIT_LOOP_%=;\n\t" \
            "WAIT_DONE_%=:\n\t}" \
            :: "r"(_mbar), "r"(_parity) : "memory"); \
    } \
} while(0)

#if HAS_TCGEN05
#define TCGEN05_ALLOC(smem_result_addr, nCols) \
    asm volatile("tcgen05.alloc.cta_group::1.sync.aligned.shared::cta.b32 [%0], %1;" \
                 :: "r"((uint32_t)(smem_result_addr)), "r"((uint32_t)(nCols)) : "memory")
#define TCGEN05_DEALLOC(tmem_addr, nCols) \
    asm volatile("tcgen05.dealloc.cta_group::1.sync.aligned.b32 %0, %1;" \
                 :: "r"(tmem_addr), "r"((uint32_t)(nCols)))
#define TCGEN05_RELINQ() \
    asm volatile("tcgen05.relinquish_alloc_permit.cta_group::1.sync.aligned;")
#define TCGEN05_COMMIT(mbar) \
    asm volatile("tcgen05.commit.cta_group::1.mbarrier::arrive::one.shared::cluster.b64 [%0];" \
                 :: "r"((uint32_t)(mbar)) : "memory")
#define TCGEN05_FENCE_AFTER() \
    asm volatile("tcgen05.fence::after_thread_sync;" ::: "memory")
#define TCGEN05_FENCE_BEFORE() \
    asm volatile("tcgen05.fence::before_thread_sync;" ::: "memory")
#define TCGEN05_WAIT_LD() \
    asm volatile("tcgen05.wait::ld.sync.aligned;" ::: "memory")
#define TCGEN05_WAIT_ST() \
    asm volatile("tcgen05.wait::st.sync.aligned;" ::: "memory")
#define TCGEN05_LD_X32(r, tmem_addr) \
    asm volatile( \
        "tcgen05.ld.sync.aligned.32x32b.x32.b32 " \
        "{%0, %1, %2, %3, %4, %5, %6, %7, " \
        " %8, %9, %10, %11, %12, %13, %14, %15, " \
        " %16, %17, %18, %19, %20, %21, %22, %23, " \
        " %24, %25, %26, %27, %28, %29, %30, %31}, [%32];" \
        : "=r"((r)[0]),  "=r"((r)[1]),  "=r"((r)[2]),  "=r"((r)[3]), \
          "=r"((r)[4]),  "=r"((r)[5]),  "=r"((r)[6]),  "=r"((r)[7]), \
          "=r"((r)[8]),  "=r"((r)[9]),  "=r"((r)[10]), "=r"((r)[11]), \
          "=r"((r)[12]), "=r"((r)[13]), "=r"((r)[14]), "=r"((r)[15]), \
          "=r"((r)[16]), "=r"((r)[17]), "=r"((r)[18]), "=r"((r)[19]), \
          "=r"((r)[20]), "=r"((r)[21]), "=r"((r)[22]), "=r"((r)[23]), \
          "=r"((r)[24]), "=r"((r)[25]), "=r"((r)[26]), "=r"((r)[27]), \
          "=r"((r)[28]), "=r"((r)[29]), "=r"((r)[30]), "=r"((r)[31]) \
        : "r"(tmem_addr))
#define TCGEN05_ST_X16(tmem_addr, r) \
    asm volatile( \
        "tcgen05.st.sync.aligned.32x32b.x16.b32 [%0], " \
        "{%1, %2, %3, %4, %5, %6, %7, %8, " \
        " %9, %10, %11, %12, %13, %14, %15, %16};" \
        :: "r"(tmem_addr), \
           "r"((r)[0]),  "r"((r)[1]),  "r"((r)[2]),  "r"((r)[3]), \
           "r"((r)[4]),  "r"((r)[5]),  "r"((r)[6]),  "r"((r)[7]), \
           "r"((r)[8]),  "r"((r)[9]),  "r"((r)[10]), "r"((r)[11]), \
           "r"((r)[12]), "r"((r)[13]), "r"((r)[14]), "r"((r)[15]) \
        : "memory")

__device__ __forceinline__ void umma_f16_ss(uint32_t d, uint64_t a, uint64_t b,
                                            uint32_t idesc, uint32_t en) {
    asm volatile(
        "{\n\t.reg .pred p;\n\t"
        "setp.ne.u32 p, %5, 0;\n\t"
        "tcgen05.mma.cta_group::1.kind::f16 [%0], %1, %2, %3, {%4,%4,%4,%4}, p;\n\t}"
        :: "r"(d), "l"(a), "l"(b), "r"(idesc), "r"(0u), "r"(en) : "memory");
}
__device__ __forceinline__ void umma_f16_ts(uint32_t d, uint32_t a_tmem,
                                            uint64_t b, uint32_t idesc,
                                            uint32_t en) {
    asm volatile(
        "{\n\t.reg .pred p;\n\t"
        "setp.ne.u32 p, %5, 0;\n\t"
        "tcgen05.mma.cta_group::1.kind::f16 [%0], [%1], %2, %3, {%4,%4,%4,%4}, p;\n\t}"
        :: "r"(d), "r"(a_tmem), "l"(b), "r"(idesc), "r"(0u), "r"(en) : "memory");
}
#endif

// idescs: F32 accum, bf16 A/B, M=128; N variants
#define GEMM_IDESC ((1u<<4)|(1u<<7)|(1u<<10)|((128u/8)<<17)|((128u/16)<<24))
#define IDESC_S    ((1u<<4)|(1u<<7)|(1u<<10)|((64u/8)<<17)|((128u/16)<<24))
#define IDESC_PV   GEMM_IDESC

// ---------------------------------------------------------------------------
// split core: one block handles 2048 float4 at block-coalesced offsets
// ---------------------------------------------------------------------------
__device__ __forceinline__ void split_block(const float* __restrict__ in,
                                            __nv_bfloat16* __restrict__ hi,
                                            __nv_bfloat16* __restrict__ lo,
                                            int base4) {
    int base = base4 + threadIdx.x;
    float4 vv[8];
#pragma unroll
    for (int q = 0; q < 8; ++q)
        vv[q] = ((const float4*)in)[base + q * 256];
    __nv_bfloat162* hp = (__nv_bfloat162*)hi;
    __nv_bfloat162* lp = (__nv_bfloat162*)lo;
#pragma unroll
    for (int q = 0; q < 8; ++q) {
        int i = base + q * 256;
        float4 v = vv[q];
        __nv_bfloat16 h0 = __float2bfloat16(v.x);
        __nv_bfloat16 h1 = __float2bfloat16(v.y);
        __nv_bfloat16 h2 = __float2bfloat16(v.z);
        __nv_bfloat16 h3 = __float2bfloat16(v.w);
        hp[i * 2 + 0] = __halves2bfloat162(h0, h1);
        hp[i * 2 + 1] = __halves2bfloat162(h2, h3);
        lp[i * 2 + 0] = __halves2bfloat162(
            __float2bfloat16(v.x - __bfloat162float(h0)),
            __float2bfloat16(v.y - __bfloat162float(h1)));
        lp[i * 2 + 1] = __halves2bfloat162(
            __float2bfloat16(v.z - __bfloat162float(h2)),
            __float2bfloat16(v.w - __bfloat162float(h3)));
    }
}

// Fused split of x, wq, wk, wv, wo in one launch (blocks: 1024/2048/512/512/2048)
__global__ void split_all(
    const float* __restrict__ x,  __nv_bfloat16* __restrict__ xh,  __nv_bfloat16* __restrict__ xl,
    const float* __restrict__ wq, __nv_bfloat16* __restrict__ wqh, __nv_bfloat16* __restrict__ wql,
    const float* __restrict__ wk, __nv_bfloat16* __restrict__ wkh, __nv_bfloat16* __restrict__ wkl,
    const float* __restrict__ wv, __nv_bfloat16* __restrict__ wvh, __nv_bfloat16* __restrict__ wvl,
    const float* __restrict__ wo, __nv_bfloat16* __restrict__ woh, __nv_bfloat16* __restrict__ wol) {
    int b = blockIdx.x;
    if (b < 1024)       split_block(x,  xh,  xl,  b * 2048);
    else if (b < 3072)  split_block(wq, wqh, wql, (b - 1024) * 2048);
    else if (b < 3584)  split_block(wk, wkh, wkl, (b - 3072) * 2048);
    else if (b < 4096)  split_block(wv, wvh, wvl, (b - 3584) * 2048);
    else                split_block(wo, woh, wol, (b - 4096) * 2048);
}

// V split (post-GEMM)
__global__ void split_v(const float* __restrict__ in,
                        __nv_bfloat16* __restrict__ hi,
                        __nv_bfloat16* __restrict__ lo) {
    split_block(in, hi, lo, blockIdx.x * 2048);
}

// ---------------------------------------------------------------------------
// V transpose + split: V[seq][KV_DIM] fp32 -> Vt[d][seq] bf16 hi/lo
// ---------------------------------------------------------------------------
__global__ void vt_split(const float* __restrict__ V,
                         __nv_bfloat16* __restrict__ Vth,
                         __nv_bfloat16* __restrict__ Vtl) {
    __shared__ float tile[32][33];
    int s0 = blockIdx.x * 32, d0 = blockIdx.y * 32;
    int tx = threadIdx.x;
    for (int r = threadIdx.y; r < 32; r += 8)
        tile[r][tx] = V[(long)(s0 + r) * KV_DIM + d0 + tx];
    __syncthreads();
    for (int r = threadIdx.y; r < 32; r += 8) {
        float v = tile[tx][r];
        __nv_bfloat16 h = __float2bfloat16(v);
        long o = (long)(d0 + r) * SEQ + s0 + tx;
        Vth[o] = h;
        Vtl[o] = __float2bfloat16(v - __bfloat162float(h));
    }
}

// ---------------------------------------------------------------------------
// rope+split scalar helper (mma.sync fallback path only)
// ---------------------------------------------------------------------------
__device__ __forceinline__ void rope_pair_store(
    float v0, float v1, int row, int col, int N, float scale,
    const float* cs, const float* sn,
    __nv_bfloat16* Xh, __nv_bfloat16* Xl) {
    int p = (col & 127) >> 1;
    float c = cs[row * 64 + p], s = sn[row * 64 + p];
    float o0 = (v0 * c - v1 * s) * scale;
    float o1 = (v0 * s + v1 * c) * scale;
    uint32_t hh = bpack(o0, o1);
    __nv_bfloat162 hv = *(__nv_bfloat162*)&hh;
    uint32_t ll = bpack(o0 - __bfloat162float(hv.x),
                        o1 - __bfloat162float(hv.y));
    *(uint32_t*)&Xh[(long)row * N + col] = hh;
    *(uint32_t*)&Xl[(long)row * N + col] = ll;
}

// ---------------------------------------------------------------------------
// Segmented GEMM (NT): 128x256 tile, tcgen05 (mma.sync fallback). R10 core.
// Up to 3 B/output segments along blockIdx.x:
//   seg1 [0,s1):      B1, N1 cols; rope-split out (C1h/C1l, scale1) or fp32 C1
//   seg2 [s1,s1+s2):  B2, N2 cols; rope-split out (C2h/C2l, scale 1)
//   seg3 [s1+s2,..):  B3, N2 cols; fp32 out C3
// ---------------------------------------------------------------------------
#define GT_ST_A 16384
#define GT_ST_B 32768
#define GT_STAGE (2*GT_ST_A + 2*GT_ST_B)
#define GT_SMEM (1024 + 2*GT_STAGE + 64)

__device__ __forceinline__ void gt_stage(
    const __nv_bfloat16* Ah, const __nv_bfloat16* Al,
    const __nv_bfloat16* Bh, const __nv_bfloat16* Bl,
    uint32_t sb, int m0, int n0, int K, int kc, int tid) {
#pragma unroll
    for (int i = 0; i < 4; ++i) {
        int c = tid + 256 * i;
        int row = c >> 3, col = c & 7;
        int so = row * 128 + ((col ^ (row & 7)) << 4);
        long ga = (long)(m0 + row) * K + kc + col * 8;
        cp16(sb + so,           Ah + ga);
        cp16(sb + GT_ST_A + so, Al + ga);
    }
#pragma unroll
    for (int i = 0; i < 8; ++i) {
        int c = tid + 256 * i;
        int row = c >> 3, col = c & 7;
        int so = row * 128 + ((col ^ (row & 7)) << 4);
        long gb = (long)(n0 + row) * K + kc + col * 8;
        cp16(sb + 2 * GT_ST_A + so,            Bh + gb);
        cp16(sb + 2 * GT_ST_A + GT_ST_B + so,  Bl + gb);
    }
    cp_commit();
}

__global__ __launch_bounds__(256, 1)
void gemm_tc(const __nv_bfloat16* __restrict__ Ah,
             const __nv_bfloat16* __restrict__ Al,
             const __nv_bfloat16* __restrict__ B1h,
             const __nv_bfloat16* __restrict__ B1l,
             float* __restrict__ C1f,
             __nv_bfloat16* __restrict__ C1h,
             __nv_bfloat16* __restrict__ C1l,
             float scale1,
             const __nv_bfloat16* __restrict__ B2h,
             const __nv_bfloat16* __restrict__ B2l,
             __nv_bfloat16* __restrict__ C2h,
             __nv_bfloat16* __restrict__ C2l,
             const __nv_bfloat16* __restrict__ B3h,
             const __nv_bfloat16* __restrict__ B3l,
             float* __restrict__ C3f,
             int s1, int s2,
             const float* __restrict__ cs,
             const float* __restrict__ sn,
             int N1, int N2, int K) {
    extern __shared__ char smg_raw[];
    uint32_t u = smaddr(smg_raw);
    uint32_t t0 = (u + 1023u) & ~1023u;
    const int tid = threadIdx.x;
    const int wid = tid >> 5;
    const int lane = tid & 31;
    const int m0 = blockIdx.y * 128;
    const int nst = K >> 6;

    // segment select
    const __nv_bfloat16* Bh;
    const __nv_bfloat16* Bl;
    float* Cf = nullptr;
    __nv_bfloat16* Ch = nullptr;
    __nv_bfloat16* Cl = nullptr;
    float scale = 1.0f;
    int N;
    int bx = blockIdx.x;
    if (bx < s1) {
        Bh = B1h; Bl = B1l; Cf = C1f; Ch = C1h; Cl = C1l; scale = scale1; N = N1;
    } else if (bx < s1 + s2) {
        bx -= s1;
        Bh = B2h; Bl = B2l; Ch = C2h; Cl = C2l; N = N2;
    } else {
        bx -= s1 + s2;
        Bh = B3h; Bl = B3l; Cf = C3f; N = N2;
    }
    const int n0 = bx * 256;
    const bool dosplit = (Ch != nullptr);

#if HAS_TCGEN05
    uint32_t ctrl = t0 + 2 * GT_STAGE;
    uint32_t mb[2] = {ctrl + 8, ctrl + 16};

    if (wid == 0) {
        TCGEN05_ALLOC(ctrl, 256);
        TCGEN05_RELINQ();
    }
    if (tid == 0) {
        MBARRIER_INIT(mb[0], 1);
        MBARRIER_INIT(mb[1], 1);
    }
    __syncthreads();
    uint32_t tmem;
    asm volatile("ld.shared.b32 %0, [%1];" : "=r"(tmem) : "r"(ctrl));

    gt_stage(Ah, Al, Bh, Bl, t0,            m0, n0, K, 0,  tid);
    gt_stage(Ah, Al, Bh, Bl, t0 + GT_STAGE, m0, n0, K, 64, tid);

    for (int t = 0; t < nst; ++t) {
        if (t + 1 < nst) asm volatile("cp.async.wait_group 1;");
        else             asm volatile("cp.async.wait_group 0;");
        FENCE_ASYNC();
        __syncthreads();

        if (tid == 0) {
            TCGEN05_FENCE_AFTER();
            uint32_t base = t0 + (t & 1) * GT_STAGE;
            uint64_t dAh = MAKE_SMEM_DESC(base);
            uint64_t dAl = MAKE_SMEM_DESC(base + GT_ST_A);
            uint64_t dBh = MAKE_SMEM_DESC(base + 2 * GT_ST_A);
            uint64_t dBl = MAKE_SMEM_DESC(base + 2 * GT_ST_A + GT_ST_B);
#pragma unroll
            for (int s = 0; s < 4; ++s) {
#pragma unroll
                for (int nh = 0; nh < 2; ++nh) {
                    uint64_t bo = (uint64_t)(2 * s + nh * 1024);
                    uint32_t dd = tmem + nh * 128;
                    umma_f16_ss(dd, dAh + 2 * s, dBh + bo, GEMM_IDESC,
                                (t == 0 && s == 0) ? 0u : 1u);
                    umma_f16_ss(dd, dAh + 2 * s, dBl + bo, GEMM_IDESC, 1u);
                    umma_f16_ss(dd, dAl + 2 * s, dBh + bo, GEMM_IDESC, 1u);
                }
            }
            TCGEN05_COMMIT(mb[t & 1]);
        }

        if (t + 2 < nst) {
            MBARRIER_WAIT_PARITY(mb[t & 1], (t >> 1) & 1);
            gt_stage(Ah, Al, Bh, Bl, t0 + (t & 1) * GT_STAGE, m0, n0, K,
                     (t + 2) * 64, tid);
        }
    }

    MBARRIER_WAIT_PARITY(mb[(nst - 1) & 1], ((nst - 1) >> 1) & 1);
    TCGEN05_FENCE_AFTER();

    {
        int row = m0 + (wid & 3) * 32 + lane;
        uint32_t cb = (wid >> 2) * 128;
#pragma unroll
        for (int cc = 0; cc < 4; ++cc) {
            uint32_t r[32];
            TCGEN05_LD_X32(r, tmem + cb + cc * 32);
            TCGEN05_WAIT_LD();
            int colbase = n0 + (int)cb + cc * 32;
            if (dosplit) {
                int p0 = (colbase & 127) >> 1;
                const float4* cs4 = (const float4*)(cs + row * 64 + p0);
                const float4* sn4 = (const float4*)(sn + row * 64 + p0);
                uint32_t hh[16], ll[16];
#pragma unroll
                for (int qv = 0; qv < 4; ++qv) {
                    float4 cv = cs4[qv];
                    float4 svv = sn4[qv];
                    float ca[4] = {cv.x, cv.y, cv.z, cv.w};
                    float sa[4] = {svv.x, svv.y, svv.z, svv.w};
#pragma unroll
                    for (int e = 0; e < 4; ++e) {
                        float v0 = __uint_as_float(r[qv * 8 + e * 2]);
                        float v1 = __uint_as_float(r[qv * 8 + e * 2 + 1]);
                        float o0 = (v0 * ca[e] - v1 * sa[e]) * scale;
                        float o1 = (v0 * sa[e] + v1 * ca[e]) * scale;
                        int j = qv * 4 + e;
                        hh[j] = bpack(o0, o1);
                        __nv_bfloat162 hv = *(__nv_bfloat162*)&hh[j];
                        ll[j] = bpack(o0 - __bfloat162float(hv.x),
                                      o1 - __bfloat162float(hv.y));
                    }
                }
                uint4* dh = (uint4*)&Ch[(long)row * N + colbase];
                uint4* dl = (uint4*)&Cl[(long)row * N + colbase];
#pragma unroll
                for (int qv = 0; qv < 4; ++qv) {
                    dh[qv] = make_uint4(hh[qv * 4], hh[qv * 4 + 1],
                                        hh[qv * 4 + 2], hh[qv * 4 + 3]);
                    dl[qv] = make_uint4(ll[qv * 4], ll[qv * 4 + 1],
                                        ll[qv * 4 + 2], ll[qv * 4 + 3]);
                }
            } else {
                float* dst = &Cf[(long)row * N + colbase];
#pragma unroll
                for (int q = 0; q < 8; ++q) {
                    *(float4*)(dst + q * 4) = make_float4(
                        __uint_as_float(r[q * 4 + 0]), __uint_as_float(r[q * 4 + 1]),
                        __uint_as_float(r[q * 4 + 2]), __uint_as_float(r[q * 4 + 3]));
                }
            }
        }
    }
    __syncthreads();
    if (wid == 0) TCGEN05_DEALLOC(tmem, 256);

#else
    const int wm = (wid >> 1) * 32;
    const int wn = (wid & 1) * 128;

    float acc[2][16][4];
#pragma unroll
    for (int i = 0; i < 2; ++i)
#pragma unroll
        for (int j = 0; j < 16; ++j)
#pragma unroll
            for (int q = 0; q < 4; ++q) acc[i][j][q] = 0.0f;

    for (int t = 0; t < nst; ++t) {
        gt_stage(Ah, Al, Bh, Bl, t0, m0, n0, K, t * 64, tid);
        asm volatile("cp.async.wait_group 0;");
        __syncthreads();

#pragma unroll
        for (int kb = 0; kb < 4; ++kb) {
            uint32_t ah[2][4], al[2][4];
#pragma unroll
            for (int mf = 0; mf < 2; ++mf) {
                int arow = wm + mf * 16 + (lane & 15);
                int col8 = kb * 2 + (lane >> 4);
                uint32_t off = arow * 128 + ((col8 ^ (arow & 7)) << 4);
                ldsm4(ah[mf][0], ah[mf][1], ah[mf][2], ah[mf][3], t0 + off);
                ldsm4(al[mf][0], al[mf][1], al[mf][2], al[mf][3],
                      t0 + GT_ST_A + off);
            }
#pragma unroll
            for (int np = 0; np < 8; ++np) {
                int brow = wn + np * 16 + (lane & 7) + ((lane >> 4) << 3);
                int col8 = kb * 2 + ((lane >> 3) & 1);
                uint32_t off = brow * 128 + ((col8 ^ (brow & 7)) << 4);
                uint32_t bh[4], bl[4];
                ldsm4(bh[0], bh[1], bh[2], bh[3], t0 + 2 * GT_ST_A + off);
                ldsm4(bl[0], bl[1], bl[2], bl[3],
                      t0 + 2 * GT_ST_A + GT_ST_B + off);
#pragma unroll
                for (int hf = 0; hf < 2; ++hf) {
                    int nf = np * 2 + hf;
#pragma unroll
                    for (int mf = 0; mf < 2; ++mf) {
                        mma16816(acc[mf][nf], ah[mf], bh[hf * 2], bh[hf * 2 + 1]);
                        mma16816(acc[mf][nf], ah[mf], bl[hf * 2], bl[hf * 2 + 1]);
                        mma16816(acc[mf][nf], al[mf], bh[hf * 2], bh[hf * 2 + 1]);
                    }
                }
            }
        }
        __syncthreads();
    }

#pragma unroll
    for (int mf = 0; mf < 2; ++mf) {
        int row = m0 + wm + mf * 16 + (lane >> 2);
#pragma unroll
        for (int nf = 0; nf < 16; ++nf) {
            int col = n0 + wn + nf * 8 + (lane & 3) * 2;
            if (dosplit) {
                rope_pair_store(acc[mf][nf][0], acc[mf][nf][1],
                                row, col, N, scale, cs, sn, Ch, Cl);
                rope_pair_store(acc[mf][nf][2], acc[mf][nf][3],
                                row + 8, col, N, scale, cs, sn, Ch, Cl);
            } else {
                *(float2*)&Cf[(long)row * N + col] =
                    make_float2(acc[mf][nf][0], acc[mf][nf][1]);
                *(float2*)&Cf[(long)(row + 8) * N + col] =
                    make_float2(acc[mf][nf][2], acc[mf][nf][3]);
            }
        }
    }
#endif
}

// ---------------------------------------------------------------------------
// tcgen05 flash attention (causal, GQA 4:1) — R10-proven structure.
// TMEM: S [0,64) | Ph [64,96) | Pl [96,128) | PV [128,256).
// ---------------------------------------------------------------------------
#define ATC_STAGE 65536
#define ATC_CTRL  (3 * 65536)
#define ATC_SMEM  (1024 + ATC_CTRL + 64 + 3072)
#define ATT_TS (64 * PADK)
#define ATT_SMEM_FB (8 * ATT_TS * 2)

__device__ __forceinline__ void atc_stage(
    const __nv_bfloat16* Kh, const __nv_bfloat16* Kl,
    const __nv_bfloat16* Vth, const __nv_bfloat16* Vtl,
    uint32_t sbase, int j0, int kvh, int tid) {
#pragma unroll
    for (int i = 0; i < 4; ++i) {
        int c = tid + 256 * i;
        int kr = c >> 4, kc = c & 15;
        int ch = kc >> 3, col = kc & 7;
        uint32_t so = sbase + ch * 8192 + kr * 128 + ((col ^ (kr & 7)) << 4);
        long g = (long)(j0 + kr) * KV_DIM + kvh * HD + kc * 8;
        cp16(so,          Kh + g);
        cp16(so + 16384,  Kl + g);
    }
#pragma unroll
    for (int i = 0; i < 4; ++i) {
        int c = tid + 256 * i;
        int vr = c >> 3, col = c & 7;
        uint32_t so = sbase + 32768 + vr * 128 + ((col ^ (vr & 7)) << 4);
        long g = (long)(kvh * HD + vr) * SEQ + j0 + col * 8;
        cp16(so,          Vth + g);
        cp16(so + 16384,  Vtl + g);
    }
    cp_commit();
}

__device__ __forceinline__ void attn_issue_fb(
    const __nv_bfloat16* Kh_, const __nv_bfloat16* Kl_,
    const __nv_bfloat16* Vh_, const __nv_bfloat16* Vl_,
    __nv_bfloat16* sKh, __nv_bfloat16* sKl,
    __nv_bfloat16* sVh, __nv_bfloat16* sVl,
    int j0, int kvh, int tid) {
#pragma unroll
    for (int i = 0; i < 4; ++i) {
        int c = tid + 256 * i;
        int row = c >> 4, c16 = c & 15;
        long g = (long)(j0 + row) * KV_DIM + kvh * HD + c16 * 8;
        int so = row * PADK + c16 * 8;
        cp16(smaddr(sKh + so), Kh_ + g);
        cp16(smaddr(sKl + so), Kl_ + g);
        cp16(smaddr(sVh + so), Vh_ + g);
        cp16(smaddr(sVl + so), Vl_ + g);
    }
    cp_commit();
}

__global__ __launch_bounds__(256, 1)
void attn_tc(const __nv_bfloat16* __restrict__ Qh,
             const __nv_bfloat16* __restrict__ Ql,
             const __nv_bfloat16* __restrict__ Kh,
             const __nv_bfloat16* __restrict__ Kl,
             const __nv_bfloat16* __restrict__ Vh,
             const __nv_bfloat16* __restrict__ Vl,
             const __nv_bfloat16* __restrict__ Vth,
             const __nv_bfloat16* __restrict__ Vtl,
             __nv_bfloat16* __restrict__ Oh,
             __nv_bfloat16* __restrict__ Ol) {
    extern __shared__ char smg_raw[];
    const int tid = threadIdx.x;
    const int lane = tid & 31;
    const int w = tid >> 5;
    const int h = blockIdx.y;
    const int kvh = h >> 2;
    const int qt = gridDim.x - 1 - blockIdx.x;
    const int q0 = qt * BQT;
    const int nt = 2 * qt + 2;

#if HAS_TCGEN05
    uint32_t u = smaddr(smg_raw);
    uint32_t t0 = (u + 1023u) & ~1023u;
    char* gb = smg_raw + (t0 - u);
    const int half = w >> 2;
    const int sp = w & 3;
    const int row = sp * 32 + lane;
    const int qrow = q0 + row;

    uint32_t ctrl = t0 + ATC_CTRL;
    uint32_t mbs = ctrl + 8, mbpv = ctrl + 16;
    float* red0 = (float*)(gb + ATC_CTRL + 64);
    float* red1 = red0 + 256;
    float* smm  = red1 + 256;
    float* sml  = smm + 128;

    if (w == 0) {
        TCGEN05_ALLOC(ctrl, 256);
        TCGEN05_RELINQ();
    }
    if (tid == 0) {
        MBARRIER_INIT(mbs, 1);
        MBARRIER_INIT(mbpv, 1);
    }
    if (tid < 128) { smm[tid] = -1e30f; sml[tid] = 0.0f; }
    __syncthreads();
    uint32_t tmem;
    asm volatile("ld.shared.b32 %0, [%1];" : "=r"(tmem) : "r"(ctrl));

#pragma unroll
    for (int i = 0; i < 8; ++i) {
        int c = tid + 256 * i;
        int r = c >> 4, kc = c & 15;
        int ch = kc >> 3, col = kc & 7;
        uint32_t so = t0 + ch * 16384 + r * 128 + ((col ^ (r & 7)) << 4);
        long g = (long)(q0 + r) * DIM + h * HD + kc * 8;
        cp16(so,          Qh + g);
        cp16(so + 32768,  Ql + g);
    }
    atc_stage(Kh, Kl, Vth, Vtl, t0 + ATC_STAGE,     0,  kvh, tid);
    atc_stage(Kh, Kl, Vth, Vtl, t0 + 2 * ATC_STAGE, 64, kvh, tid);

    float of[64];
#pragma unroll
    for (int j = 0; j < 64; ++j) of[j] = 0.0f;

    for (int t = 0; t < nt; ++t) {
        const int j0 = t * BKT;
        if (t >= 1 && t + 1 < nt)
            atc_stage(Kh, Kl, Vth, Vtl, t0 + ATC_STAGE * (1 + ((t + 1) & 1)),
                      (t + 1) * BKT, kvh, tid);
        if (t + 1 < nt) asm volatile("cp.async.wait_group 1;");
        else            asm volatile("cp.async.wait_group 0;");
        FENCE_ASYNC();
        __syncthreads();

        const uint32_t sbase = t0 + ATC_STAGE * (1 + (t & 1));

        if (tid == 0) {
            TCGEN05_FENCE_AFTER();
#pragma unroll
            for (int c = 0; c < 2; ++c) {
                uint64_t dQh = MAKE_SMEM_DESC(t0 + c * 16384);
                uint64_t dQl = MAKE_SMEM_DESC(t0 + 32768 + c * 16384);
                uint64_t dKh = MAKE_SMEM_DESC(sbase + c * 8192);
                uint64_t dKl = MAKE_SMEM_DESC(sbase + 16384 + c * 8192);
#pragma unroll
                for (int s = 0; s < 4; ++s) {
                    umma_f16_ss(tmem, dQh + 2 * s, dKh + 2 * s, IDESC_S,
                                (c == 0 && s == 0) ? 0u : 1u);
                    umma_f16_ss(tmem, dQh + 2 * s, dKl + 2 * s, IDESC_S, 1u);
                    umma_f16_ss(tmem, dQl + 2 * s, dKh + 2 * s, IDESC_S, 1u);
                }
            }
            TCGEN05_COMMIT(mbs);
        }
        MBARRIER_WAIT_PARITY(mbs, t & 1);
        TCGEN05_FENCE_AFTER();

        uint32_t sr[32];
        TCGEN05_LD_X32(sr, tmem + half * 32);
        TCGEN05_WAIT_LD();
        float sv[32];
#pragma unroll
        for (int j = 0; j < 32; ++j) sv[j] = __uint_as_float(sr[j]);
        if (t >= nt - 2) {
#pragma unroll
            for (int j = 0; j < 32; ++j)
                if (j0 + half * 32 + j > qrow) sv[j] = -1e30f;
        }
        float mymax = -1e30f;
#pragma unroll
        for (int j = 0; j < 32; ++j) mymax = fmaxf(mymax, sv[j]);
        red0[half * 128 + row] = mymax;
        __syncthreads();
        float mt = fmaxf(red0[row], red0[128 + row]);
        float mold = smm[row];
        float mn = fmaxf(mold, mt);
        float alpha = __expf(mold - mn);
        float mysum = 0.0f;
#pragma unroll
        for (int j = 0; j < 32; ++j) {
            sv[j] = __expf(sv[j] - mn);
            mysum += sv[j];
        }
        red1[half * 128 + row] = mysum;
        __syncthreads();
        if (half == 0) {
            sml[row] = sml[row] * alpha + red1[row] + red1[128 + row];
            smm[row] = mn;
        }

        uint32_t ph[16], pl[16];
#pragma unroll
        for (int j = 0; j < 16; ++j) {
            float a = sv[2 * j], b = sv[2 * j + 1];
            ph[j] = bpack(a, b);
            __nv_bfloat162 hv = *(__nv_bfloat162*)&ph[j];
            pl[j] = bpack(a - __bfloat162float(hv.x), b - __bfloat162float(hv.y));
        }
        uint32_t lo_off = (uint32_t)sp << 21;
        TCGEN05_ST_X16(tmem + 64 + half * 16 + lo_off, ph);
        TCGEN05_ST_X16(tmem + 96 + half * 16 + lo_off, pl);
        TCGEN05_WAIT_ST();
        TCGEN05_FENCE_BEFORE();
        __syncthreads();

        if (tid == 0) {
            TCGEN05_FENCE_AFTER();
            uint64_t dVh = MAKE_SMEM_DESC(sbase + 32768);
            uint64_t dVl = MAKE_SMEM_DESC(sbase + 49152);
#pragma unroll
            for (int ks = 0; ks < 4; ++ks) {
                umma_f16_ts(tmem + 128, tmem + 64 + ks * 8, dVh + 2 * ks,
                            IDESC_PV, ks == 0 ? 0u : 1u);
                umma_f16_ts(tmem + 128, tmem + 64 + ks * 8, dVl + 2 * ks,
                            IDESC_PV, 1u);
                umma_f16_ts(tmem + 128, tmem + 96 + ks * 8, dVh + 2 * ks,
                            IDESC_PV, 1u);
            }
            TCGEN05_COMMIT(mbpv);
        }
        MBARRIER_WAIT_PARITY(mbpv, t & 1);
        TCGEN05_FENCE_AFTER();

        uint32_t pv[32];
        TCGEN05_LD_X32(pv, tmem + 128 + half * 64);
        TCGEN05_WAIT_LD();
#pragma unroll
        for (int j = 0; j < 32; ++j)
            of[j] = of[j] * alpha + __uint_as_float(pv[j]);
        TCGEN05_LD_X32(pv, tmem + 128 + half * 64 + 32);
        TCGEN05_WAIT_LD();
#pragma unroll
        for (int j = 0; j < 32; ++j)
            of[32 + j] = of[32 + j] * alpha + __uint_as_float(pv[j]);
    }

    float inv = 1.0f / sml[row];
#pragma unroll
    for (int j = 0; j < 32; ++j) {
        float a = of[2 * j] * inv, b = of[2 * j + 1] * inv;
        uint32_t hh = bpack(a, b);
        __nv_bfloat162 hv = *(__nv_bfloat162*)&hh;
        uint32_t ll = bpack(a - __bfloat162float(hv.x),
                            b - __bfloat162float(hv.y));
        long o = (long)qrow * DIM + h * HD + half * 64 + 2 * j;
        *(uint32_t*)&Oh[o] = hh;
        *(uint32_t*)&Ol[o] = ll;
    }
    __syncthreads();
    if (w == 0) TCGEN05_DEALLOC(tmem, 256);

#else
    // ======================= mma.sync fallback ===============================
    __nv_bfloat16* sma = (__nv_bfloat16*)smg_raw;
    __nv_bfloat16* sKh[2] = {sma + 0 * ATT_TS, sma + 1 * ATT_TS};
    __nv_bfloat16* sKl[2] = {sma + 2 * ATT_TS, sma + 3 * ATT_TS};
    __nv_bfloat16* sVh[2] = {sma + 4 * ATT_TS, sma + 5 * ATT_TS};
    __nv_bfloat16* sVl[2] = {sma + 6 * ATT_TS, sma + 7 * ATT_TS};

    const int g = lane >> 2;
    const int qq = lane & 3;
    const int r0 = q0 + w * 16 + g;
    const int r1 = r0 + 8;
    uint32_t qfh[8][4], qfl[8][4];
#pragma unroll
    for (int k = 0; k < 8; ++k) {
        int c = h * HD + k * 16 + qq * 2;
        qfh[k][0] = *(const uint32_t*)&Qh[(long)r0 * DIM + c];
        qfh[k][1] = *(const uint32_t*)&Qh[(long)r1 * DIM + c];
        qfh[k][2] = *(const uint32_t*)&Qh[(long)r0 * DIM + c + 8];
        qfh[k][3] = *(const uint32_t*)&Qh[(long)r1 * DIM + c + 8];
        qfl[k][0] = *(const uint32_t*)&Ql[(long)r0 * DIM + c];
        qfl[k][1] = *(const uint32_t*)&Ql[(long)r1 * DIM + c];
        qfl[k][2] = *(const uint32_t*)&Ql[(long)r0 * DIM + c + 8];
        qfl[k][3] = *(const uint32_t*)&Ql[(long)r1 * DIM + c + 8];
    }

    float of[16][4];
#pragma unroll
    for (int i = 0; i < 16; ++i)
#pragma unroll
        for (int j = 0; j < 4; ++j) of[i][j] = 0.0f;
    float m0 = -1e30f, m1 = -1e30f, l0 = 0.0f, l1 = 0.0f;

    attn_issue_fb(Kh, Kl, Vh, Vl, sKh[0], sKl[0], sVh[0], sVl[0], 0, kvh, tid);

    for (int t = 0; t < nt; ++t) {
        if (t + 1 < nt) {
            int bb = (t + 1) & 1;
            attn_issue_fb(Kh, Kl, Vh, Vl, sKh[bb], sKl[bb], sVh[bb], sVl[bb],
                          (t + 1) * BKT, kvh, tid);
            asm volatile("cp.async.wait_group 1;");
        } else {
            asm volatile("cp.async.wait_group 0;");
        }
        __syncthreads();
        const int buf = t & 1;
        const int j0 = t * BKT;

        float sc[8][4];
#pragma unroll
        for (int i = 0; i < 8; ++i)
#pragma unroll
            for (int j = 0; j < 4; ++j) sc[i][j] = 0.0f;

#pragma unroll
        for (int k = 0; k < 8; ++k) {
#pragma unroll
            for (int np = 0; np < 4; ++np) {
                int brow = np * 16 + (lane & 7) + ((lane >> 4) << 3);
                int bcol = k * 16 + (((lane >> 3) & 1) << 3);
                uint32_t bh[4], bl[4];
                ldsm4(bh[0], bh[1], bh[2], bh[3],
                      smaddr(sKh[buf] + brow * PADK + bcol));
                ldsm4(bl[0], bl[1], bl[2], bl[3],
                      smaddr(sKl[buf] + brow * PADK + bcol));
#pragma unroll
                for (int hf = 0; hf < 2; ++hf) {
                    int nf = np * 2 + hf;
                    mma16816(sc[nf], qfh[k], bh[hf * 2], bh[hf * 2 + 1]);
                    mma16816(sc[nf], qfh[k], bl[hf * 2], bl[hf * 2 + 1]);
                    mma16816(sc[nf], qfl[k], bh[hf * 2], bh[hf * 2 + 1]);
                }
            }
        }

        if (t >= nt - 2) {
#pragma unroll
            for (int nf = 0; nf < 8; ++nf) {
                int cb = j0 + nf * 8 + qq * 2;
                if (cb > r0)     sc[nf][0] = -1e30f;
                if (cb + 1 > r0) sc[nf][1] = -1e30f;
                if (cb > r1)     sc[nf][2] = -1e30f;
                if (cb + 1 > r1) sc[nf][3] = -1e30f;
            }
        }

        float mt0 = -1e30f, mt1 = -1e30f;
#pragma unroll
        for (int nf = 0; nf < 8; ++nf) {
            mt0 = fmaxf(mt0, fmaxf(sc[nf][0], sc[nf][1]));
            mt1 = fmaxf(mt1, fmaxf(sc[nf][2], sc[nf][3]));
        }
        mt0 = fmaxf(mt0, __shfl_xor_sync(0xffffffff, mt0, 1));
        mt0 = fmaxf(mt0, __shfl_xor_sync(0xffffffff, mt0, 2));
        mt1 = fmaxf(mt1, __shfl_xor_sync(0xffffffff, mt1, 1));
        mt1 = fmaxf(mt1, __shfl_xor_sync(0xffffffff, mt1, 2));
        float mn0 = fmaxf(m0, mt0), mn1 = fmaxf(m1, mt1);
        float a0 = __expf(m0 - mn0), a1 = __expf(m1 - mn1);
        m0 = mn0; m1 = mn1;

        float rs0 = 0.0f, rs1 = 0.0f;
#pragma unroll
        for (int nf = 0; nf < 8; ++nf) {
            sc[nf][0] = __expf(sc[nf][0] - mn0); rs0 += sc[nf][0];
            sc[nf][1] = __expf(sc[nf][1] - mn0); rs0 += sc[nf][1];
            sc[nf][2] = __expf(sc[nf][2] - mn1); rs1 += sc[nf][2];
            sc[nf][3] = __expf(sc[nf][3] - mn1); rs1 += sc[nf][3];
        }
        rs0 += __shfl_xor_sync(0xffffffff, rs0, 1);
        rs0 += __shfl_xor_sync(0xffffffff, rs0, 2);
        rs1 += __shfl_xor_sync(0xffffffff, rs1, 1);
        rs1 += __shfl_xor_sync(0xffffffff, rs1, 2);
        l0 = l0 * a0 + rs0;
        l1 = l1 * a1 + rs1;

#pragma unroll
        for (int nf = 0; nf < 16; ++nf) {
            of[nf][0] *= a0; of[nf][1] *= a0;
            of[nf][2] *= a1; of[nf][3] *= a1;
        }

#pragma unroll
        for (int ks = 0; ks < 4; ++ks) {
            uint32_t ph[4], pl[4];
            {
                float s00 = sc[2 * ks][0],     s01 = sc[2 * ks][1];
                float s02 = sc[2 * ks][2],     s03 = sc[2 * ks][3];
                float s10 = sc[2 * ks + 1][0], s11 = sc[2 * ks + 1][1];
                float s12 = sc[2 * ks + 1][2], s13 = sc[2 * ks + 1][3];
                ph[0] = bpack(s00, s01); ph[1] = bpack(s02, s03);
                ph[2] = bpack(s10, s11); ph[3] = bpack(s12, s13);
                __nv_bfloat162* hp;
                hp = (__nv_bfloat162*)&ph[0];
                pl[0] = bpack(s00 - __bfloat162float(hp->x), s01 - __bfloat162float(hp->y));
                hp = (__nv_bfloat162*)&ph[1];
                pl[1] = bpack(s02 - __bfloat162float(hp->x), s03 - __bfloat162float(hp->y));
                hp = (__nv_bfloat162*)&ph[2];
                pl[2] = bpack(s10 - __bfloat162float(hp->x), s11 - __bfloat162float(hp->y));
                hp = (__nv_bfloat162*)&ph[3];
                pl[3] = bpack(s12 - __bfloat162float(hp->x), s13 - __bfloat162float(hp->y));
            }
            int vrow = ks * 16 + (lane & 7) + (((lane >> 3) & 1) << 3);
#pragma unroll
            for (int nn = 0; nn < 8; ++nn) {
                int vcol = nn * 16 + ((lane >> 4) << 3);
                uint32_t vh[4], vl[4];
                ldsm4t(vh[0], vh[1], vh[2], vh[3],
                       smaddr(sVh[buf] + vrow * PADK + vcol));
                ldsm4t(vl[0], vl[1], vl[2], vl[3],
                       smaddr(sVl[buf] + vrow * PADK + vcol));
                mma16816(of[nn * 2], ph, vh[0], vh[1]);
                mma16816(of[nn * 2], ph, vl[0], vl[1]);
                mma16816(of[nn * 2], pl, vh[0], vh[1]);
                mma16816(of[nn * 2 + 1], ph, vh[2], vh[3]);
                mma16816(of[nn * 2 + 1], ph, vl[2], vl[3]);
                mma16816(of[nn * 2 + 1], pl, vh[2], vh[3]);
            }
        }
        __syncthreads();
    }

    float inv0 = 1.0f / l0, inv1 = 1.0f / l1;
#pragma unroll
    for (int nf = 0; nf < 16; ++nf) {
        int col = h * HD + nf * 8 + qq * 2;
        {
            float a = of[nf][0] * inv0, b = of[nf][1] * inv0;
            uint32_t hh = bpack(a, b);
            __nv_bfloat162 hv = *(__nv_bfloat162*)&hh;
            uint32_t ll = bpack(a - __bfloat162float(hv.x),
                                b - __bfloat162float(hv.y));
            *(uint32_t*)&Oh[(long)r0 * DIM + col] = hh;
            *(uint32_t*)&Ol[(long)r0 * DIM + col] = ll;
        }
        {
            float a = of[nf][2] * inv1, b = of[nf][3] * inv1;
            uint32_t hh = bpack(a, b);
            __nv_bfloat162 hv = *(__nv_bfloat162*)&hh;
            uint32_t ll = bpack(a - __bfloat162float(hv.x),
                                b - __bfloat162float(hv.y));
            *(uint32_t*)&Oh[(long)r1 * DIM + col] = hh;
            *(uint32_t*)&Ol[(long)r1 * DIM + col] = ll;
        }
    }
#endif
}

// ---------------------------------------------------------------------------
// Launcher
// ---------------------------------------------------------------------------
extern "C" void kernel_launch(void* const* d_in, const int* in_sizes, int n_in,
                              void* d_out, int out_size) {
    const float* x  = (const float*)d_in[0];
    const float* wq = (const float*)d_in[1];
    const float* wk = (const float*)d_in[2];
    const float* wv = (const float*)d_in[3];
    const float* wo = (const float*)d_in[4];
    const float* fc = (const float*)d_in[5];
    const float* fs = (const float*)d_in[6];
    float* out = (float*)d_out;

    float* Vp;
    cudaGetSymbolAddress((void**)&Vp, g_V);

    __nv_bfloat16 *xh, *xl, *wqh, *wql, *wkh, *wkl, *wvh, *wvl, *woh, *wol, *oh, *ol;
    __nv_bfloat16 *qh, *ql, *kh, *kl, *vh, *vl, *vth, *vtl;
    cudaGetSymbolAddress((void**)&xh,  g_xh);  cudaGetSymbolAddress((void**)&xl,  g_xl);
    cudaGetSymbolAddress((void**)&wqh, g_wqh); cudaGetSymbolAddress((void**)&wql, g_wql);
    cudaGetSymbolAddress((void**)&wkh, g_wkh); cudaGetSymbolAddress((void**)&wkl, g_wkl);
    cudaGetSymbolAddress((void**)&wvh, g_wvh); cudaGetSymbolAddress((void**)&wvl, g_wvl);
    cudaGetSymbolAddress((void**)&woh, g_woh); cudaGetSymbolAddress((void**)&wol, g_wol);
    cudaGetSymbolAddress((void**)&oh,  g_oh);  cudaGetSymbolAddress((void**)&ol,  g_ol);
    cudaGetSymbolAddress((void**)&qh,  g_Qh);  cudaGetSymbolAddress((void**)&ql,  g_Ql);
    cudaGetSymbolAddress((void**)&kh,  g_Kh);  cudaGetSymbolAddress((void**)&kl,  g_Kl);
    cudaGetSymbolAddress((void**)&vh,  g_Vh);  cudaGetSymbolAddress((void**)&vl,  g_Vl);
    cudaGetSymbolAddress((void**)&vth, g_Vth); cudaGetSymbolAddress((void**)&vtl, g_Vtl);

    cudaFuncSetAttribute(gemm_tc,
                         cudaFuncAttributeMaxDynamicSharedMemorySize, GT_SMEM);
    int att_smem = ATC_SMEM > ATT_SMEM_FB ? ATC_SMEM : ATT_SMEM_FB;
    cudaFuncSetAttribute(attn_tc,
                         cudaFuncAttributeMaxDynamicSharedMemorySize, att_smem);

    // Fused splits of x + all four weights (one launch, 6144 blocks)
    split_all<<<6144, 256>>>(x, xh, xl, wq, wqh, wql, wk, wkh, wkl,
                             wv, wvh, wvl, wo, woh, wol);

    const float qscale = 0.08838834764831845f;

    // Fused Q + K + V projections: one launch, 3 segments (16 + 4 + 4 tiles)
    // seg1: Q rope-split (N=DIM); seg2: K rope-split (N=KV_DIM);
    // seg3: V fp32 (N=KV_DIM)
    gemm_tc<<<dim3(24, SEQ / 128), 256, GT_SMEM>>>(
        xh, xl,
        wqh, wql, nullptr, qh, ql, qscale,
        wkh, wkl, kh, kl,
        wvh, wvl, Vp,
        16, 4, fc, fs, DIM, KV_DIM, DIM);

    // V splits (plain + transposed)
    split_v<<<(SEQ * KV_DIM / 4) / 2048, 256>>>(Vp, vh, vl);
    vt_split<<<dim3(SEQ / 32, KV_DIM / 32), dim3(32, 8)>>>(Vp, vth, vtl);

    // Flash attention (tcgen05, R10 structure) -> bf16 hi/lo output
    attn_tc<<<dim3(SEQ / BQT, NH), 256, att_smem>>>(
        qh, ql, kh, kl, vh, vl, vth, vtl, oh, ol);

    // Output projection (fp32 out) — segments 2,3 empty
    gemm_tc<<<dim3(16, SEQ / 128), 256, GT_SMEM>>>(
        oh, ol,
        woh, wol, out, nullptr, nullptr, 0.0f,
        nullptr, nullptr, nullptr, nullptr,
        nullptr, nullptr, nullptr,
        16, 0, fc, fs, DIM, KV_DIM, DIM);
}

// round 17
// speedup vs baseline: 1.2174x; 1.0020x over previous
#include <cuda_runtime.h>
#include <cuda_bf16.h>
#include <stdint.h>

#define SEQ    2048
#define DIM    4096
#define NH     32
#define NKV    8
#define HD     128
#define KV_DIM 1024
#define BQT    128
#define BKT    64
#define PADK   136

#if defined(__CUDA_ARCH_FEAT_SM103_ALL) || defined(__CUDA_ARCH_FEAT_SM100_ALL)
#define HAS_TCGEN05 1
#else
#define HAS_TCGEN05 0
#endif

// ---------------------------------------------------------------------------
// Static device scratch
// ---------------------------------------------------------------------------
__device__ float g_V[SEQ * KV_DIM];

__device__ __nv_bfloat16 g_xh[SEQ * DIM],     g_xl[SEQ * DIM];
__device__ __nv_bfloat16 g_wqh[DIM * DIM],    g_wql[DIM * DIM];
__device__ __nv_bfloat16 g_wkh[KV_DIM * DIM], g_wkl[KV_DIM * DIM];
__device__ __nv_bfloat16 g_wvh[KV_DIM * DIM], g_wvl[KV_DIM * DIM];
__device__ __nv_bfloat16 g_woh[DIM * DIM],    g_wol[DIM * DIM];
__device__ __nv_bfloat16 g_oh[SEQ * DIM],     g_ol[SEQ * DIM];

__device__ __nv_bfloat16 g_Qh[SEQ * DIM],     g_Ql[SEQ * DIM];
__device__ __nv_bfloat16 g_Kh[SEQ * KV_DIM],  g_Kl[SEQ * KV_DIM];
__device__ __nv_bfloat16 g_Vh[SEQ * KV_DIM],  g_Vl[SEQ * KV_DIM];
__device__ __nv_bfloat16 g_Vth[KV_DIM * SEQ], g_Vtl[KV_DIM * SEQ];  // [d][seq]

// ---------------------------------------------------------------------------
// Helpers
// ---------------------------------------------------------------------------
__device__ __forceinline__ uint32_t smaddr(const void* p) {
    return (uint32_t)__cvta_generic_to_shared(p);
}
__device__ __forceinline__ void cp16(uint32_t s, const void* g) {
    asm volatile("cp.async.cg.shared.global [%0], [%1], 16;" :: "r"(s), "l"(g));
}
__device__ __forceinline__ void cp_commit() {
    asm volatile("cp.async.commit_group;");
}
__device__ __forceinline__ void ldsm4(uint32_t& r0, uint32_t& r1,
                                      uint32_t& r2, uint32_t& r3, uint32_t a) {
    asm volatile("ldmatrix.sync.aligned.m8n8.x4.shared.b16 {%0,%1,%2,%3}, [%4];"
                 : "=r"(r0), "=r"(r1), "=r"(r2), "=r"(r3) : "r"(a));
}
__device__ __forceinline__ void ldsm4t(uint32_t& r0, uint32_t& r1,
                                       uint32_t& r2, uint32_t& r3, uint32_t a) {
    asm volatile("ldmatrix.sync.aligned.m8n8.x4.trans.shared.b16 {%0,%1,%2,%3}, [%4];"
                 : "=r"(r0), "=r"(r1), "=r"(r2), "=r"(r3) : "r"(a));
}
__device__ __forceinline__ void mma16816(float* c, const uint32_t* a,
                                         uint32_t b0, uint32_t b1) {
    asm volatile(
        "mma.sync.aligned.m16n8k16.row.col.f32.bf16.bf16.f32 "
        "{%0,%1,%2,%3},{%4,%5,%6,%7},{%8,%9},{%0,%1,%2,%3};"
        : "+f"(c[0]), "+f"(c[1]), "+f"(c[2]), "+f"(c[3])
        : "r"(a[0]), "r"(a[1]), "r"(a[2]), "r"(a[3]), "r"(b0), "r"(b1));
}
__device__ __forceinline__ uint32_t bpack(float a, float b) {
    __nv_bfloat162 v;
    v.x = __float2bfloat16(a);
    v.y = __float2bfloat16(b);
    return *(uint32_t*)&v;
}

// ---- tcgen05 -----------------------------------------------------------------
static constexpr uint64_t SMEM_DESC_BASE_SW128 =
    (uint64_t(2)  << 61) | (uint64_t(1) << 46) |
    (uint64_t(64) << 32) | (uint64_t(1) << 16);
#define MAKE_SMEM_DESC(base_addr) \
    (SMEM_DESC_BASE_SW128 | ((uint64_t)((base_addr) >> 4) & 0x3FFF))

#define MBARRIER_INIT(mbar, count) \
    asm volatile("mbarrier.init.shared.b64 [%0], %1;" \
                 :: "r"((uint32_t)(mbar)), "r"((uint32_t)(count)) : "memory")
#define FENCE_ASYNC() \
    asm volatile("fence.proxy.async.shared::cta;" ::: "memory")

#define MBARRIER_WAIT_PARITY(mbar_smem_addr, phase_parity) do { \
    uint32_t _mbar = (uint32_t)(mbar_smem_addr); \
    uint32_t _parity = (uint32_t)(phase_parity); \
    uint32_t _done; \
    asm volatile( \
        "{\n\t.reg .pred p;\n\t" \
        "mbarrier.try_wait.parity.acquire.cta.shared::cta.b64 p, [%1], %2;\n\t" \
        "selp.b32 %0, 1, 0, p;\n\t}" \
        : "=r"(_done) : "r"(_mbar), "r"(_parity) : "memory"); \
    if (!_done) { \
        asm volatile( \
            "{\n\t.reg .pred P1;\n\t" \
            "WAIT_LOOP_%=:\n\t" \
            "mbarrier.try_wait.parity.acquire.cta.shared::cta.b64 P1, [%0], %1, 0x989680;\n\t" \
            "@P1 bra.uni WAIT_DONE_%=;\n\t" \
            "bra.uni WAIT_LOOP_%=;\n\t" \
            "WAIT_DONE_%=:\n\t}" \
            :: "r"(_mbar), "r"(_parity) : "memory"); \
    } \
} while(0)

#if HAS_TCGEN05
#define TCGEN05_ALLOC(smem_result_addr, nCols) \
    asm volatile("tcgen05.alloc.cta_group::1.sync.aligned.shared::cta.b32 [%0], %1;" \
                 :: "r"((uint32_t)(smem_result_addr)), "r"((uint32_t)(nCols)) : "memory")
#define TCGEN05_DEALLOC(tmem_addr, nCols) \
    asm volatile("tcgen05.dealloc.cta_group::1.sync.aligned.b32 %0, %1;" \
                 :: "r"(tmem_addr), "r"((uint32_t)(nCols)))
#define TCGEN05_RELINQ() \
    asm volatile("tcgen05.relinquish_alloc_permit.cta_group::1.sync.aligned;")
#define TCGEN05_COMMIT(mbar) \
    asm volatile("tcgen05.commit.cta_group::1.mbarrier::arrive::one.shared::cluster.b64 [%0];" \
                 :: "r"((uint32_t)(mbar)) : "memory")
#define TCGEN05_FENCE_AFTER() \
    asm volatile("tcgen05.fence::after_thread_sync;" ::: "memory")
#define TCGEN05_FENCE_BEFORE() \
    asm volatile("tcgen05.fence::before_thread_sync;" ::: "memory")
#define TCGEN05_WAIT_LD() \
    asm volatile("tcgen05.wait::ld.sync.aligned;" ::: "memory")
#define TCGEN05_WAIT_ST() \
    asm volatile("tcgen05.wait::st.sync.aligned;" ::: "memory")
#define TCGEN05_LD_X32(r, tmem_addr) \
    asm volatile( \
        "tcgen05.ld.sync.aligned.32x32b.x32.b32 " \
        "{%0, %1, %2, %3, %4, %5, %6, %7, " \
        " %8, %9, %10, %11, %12, %13, %14, %15, " \
        " %16, %17, %18, %19, %20, %21, %22, %23, " \
        " %24, %25, %26, %27, %28, %29, %30, %31}, [%32];" \
        : "=r"((r)[0]),  "=r"((r)[1]),  "=r"((r)[2]),  "=r"((r)[3]), \
          "=r"((r)[4]),  "=r"((r)[5]),  "=r"((r)[6]),  "=r"((r)[7]), \
          "=r"((r)[8]),  "=r"((r)[9]),  "=r"((r)[10]), "=r"((r)[11]), \
          "=r"((r)[12]), "=r"((r)[13]), "=r"((r)[14]), "=r"((r)[15]), \
          "=r"((r)[16]), "=r"((r)[17]), "=r"((r)[18]), "=r"((r)[19]), \
          "=r"((r)[20]), "=r"((r)[21]), "=r"((r)[22]), "=r"((r)[23]), \
          "=r"((r)[24]), "=r"((r)[25]), "=r"((r)[26]), "=r"((r)[27]), \
          "=r"((r)[28]), "=r"((r)[29]), "=r"((r)[30]), "=r"((r)[31]) \
        : "r"(tmem_addr))
#define TCGEN05_ST_X16(tmem_addr, r) \
    asm volatile( \
        "tcgen05.st.sync.aligned.32x32b.x16.b32 [%0], " \
        "{%1, %2, %3, %4, %5, %6, %7, %8, " \
        " %9, %10, %11, %12, %13, %14, %15, %16};" \
        :: "r"(tmem_addr), \
           "r"((r)[0]),  "r"((r)[1]),  "r"((r)[2]),  "r"((r)[3]), \
           "r"((r)[4]),  "r"((r)[5]),  "r"((r)[6]),  "r"((r)[7]), \
           "r"((r)[8]),  "r"((r)[9]),  "r"((r)[10]), "r"((r)[11]), \
           "r"((r)[12]), "r"((r)[13]), "r"((r)[14]), "r"((r)[15]) \
        : "memory")

__device__ __forceinline__ void umma_f16_ss(uint32_t d, uint64_t a, uint64_t b,
                                            uint32_t idesc, uint32_t en) {
    asm volatile(
        "{\n\t.reg .pred p;\n\t"
        "setp.ne.u32 p, %5, 0;\n\t"
        "tcgen05.mma.cta_group::1.kind::f16 [%0], %1, %2, %3, {%4,%4,%4,%4}, p;\n\t}"
        :: "r"(d), "l"(a), "l"(b), "r"(idesc), "r"(0u), "r"(en) : "memory");
}
__device__ __forceinline__ void umma_f16_ts(uint32_t d, uint32_t a_tmem,
                                            uint64_t b, uint32_t idesc,
                                            uint32_t en) {
    asm volatile(
        "{\n\t.reg .pred p;\n\t"
        "setp.ne.u32 p, %5, 0;\n\t"
        "tcgen05.mma.cta_group::1.kind::f16 [%0], [%1], %2, %3, {%4,%4,%4,%4}, p;\n\t}"
        :: "r"(d), "r"(a_tmem), "l"(b), "r"(idesc), "r"(0u), "r"(en) : "memory");
}
#endif

// idescs: F32 accum, bf16 A/B, M=128; N variants
#define GEMM_IDESC ((1u<<4)|(1u<<7)|(1u<<10)|((128u/8)<<17)|((128u/16)<<24))
#define IDESC_S    ((1u<<4)|(1u<<7)|(1u<<10)|((64u/8)<<17)|((128u/16)<<24))
#define IDESC_PV   GEMM_IDESC

// ---------------------------------------------------------------------------
// split core: one block handles 2048 float4 at block-coalesced offsets
// ---------------------------------------------------------------------------
__device__ __forceinline__ void split_block(const float* __restrict__ in,
                                            __nv_bfloat16* __restrict__ hi,
                                            __nv_bfloat16* __restrict__ lo,
                                            int base4) {
    int base = base4 + threadIdx.x;
    float4 vv[8];
#pragma unroll
    for (int q = 0; q < 8; ++q)
        vv[q] = ((const float4*)in)[base + q * 256];
    __nv_bfloat162* hp = (__nv_bfloat162*)hi;
    __nv_bfloat162* lp = (__nv_bfloat162*)lo;
#pragma unroll
    for (int q = 0; q < 8; ++q) {
        int i = base + q * 256;
        float4 v = vv[q];
        __nv_bfloat16 h0 = __float2bfloat16(v.x);
        __nv_bfloat16 h1 = __float2bfloat16(v.y);
        __nv_bfloat16 h2 = __float2bfloat16(v.z);
        __nv_bfloat16 h3 = __float2bfloat16(v.w);
        hp[i * 2 + 0] = __halves2bfloat162(h0, h1);
        hp[i * 2 + 1] = __halves2bfloat162(h2, h3);
        lp[i * 2 + 0] = __halves2bfloat162(
            __float2bfloat16(v.x - __bfloat162float(h0)),
            __float2bfloat16(v.y - __bfloat162float(h1)));
        lp[i * 2 + 1] = __halves2bfloat162(
            __float2bfloat16(v.z - __bfloat162float(h2)),
            __float2bfloat16(v.w - __bfloat162float(h3)));
    }
}

// Fused split of x, wq, wk, wv, wo in one launch (blocks: 1024/2048/512/512/2048)
__global__ void split_all(
    const float* __restrict__ x,  __nv_bfloat16* __restrict__ xh,  __nv_bfloat16* __restrict__ xl,
    const float* __restrict__ wq, __nv_bfloat16* __restrict__ wqh, __nv_bfloat16* __restrict__ wql,
    const float* __restrict__ wk, __nv_bfloat16* __restrict__ wkh, __nv_bfloat16* __restrict__ wkl,
    const float* __restrict__ wv, __nv_bfloat16* __restrict__ wvh, __nv_bfloat16* __restrict__ wvl,
    const float* __restrict__ wo, __nv_bfloat16* __restrict__ woh, __nv_bfloat16* __restrict__ wol) {
    int b = blockIdx.x;
    if (b < 1024)       split_block(x,  xh,  xl,  b * 2048);
    else if (b < 3072)  split_block(wq, wqh, wql, (b - 1024) * 2048);
    else if (b < 3584)  split_block(wk, wkh, wkl, (b - 3072) * 2048);
    else if (b < 4096)  split_block(wv, wvh, wvl, (b - 3584) * 2048);
    else                split_block(wo, woh, wol, (b - 4096) * 2048);
}

// ---------------------------------------------------------------------------
// Fused V split: V[seq][KV_DIM] fp32 -> Vh/Vl (row-major) + Vth/Vtl ([d][seq])
// Reads V once per 32x32 tile.
// ---------------------------------------------------------------------------
__global__ void v_split_all(const float* __restrict__ V,
                            __nv_bfloat16* __restrict__ Vh,
                            __nv_bfloat16* __restrict__ Vl,
                            __nv_bfloat16* __restrict__ Vth,
                            __nv_bfloat16* __restrict__ Vtl) {
    __shared__ float tile[32][33];
    int s0 = blockIdx.x * 32, d0 = blockIdx.y * 32;
    int tx = threadIdx.x;
    for (int r = threadIdx.y; r < 32; r += 8) {
        long gi = (long)(s0 + r) * KV_DIM + d0 + tx;
        float v = V[gi];
        tile[r][tx] = v;
        __nv_bfloat16 h = __float2bfloat16(v);
        Vh[gi] = h;
        Vl[gi] = __float2bfloat16(v - __bfloat162float(h));
    }
    __syncthreads();
    for (int r = threadIdx.y; r < 32; r += 8) {
        float v = tile[tx][r];
        __nv_bfloat16 h = __float2bfloat16(v);
        long o = (long)(d0 + r) * SEQ + s0 + tx;
        Vth[o] = h;
        Vtl[o] = __float2bfloat16(v - __bfloat162float(h));
    }
}

// ---------------------------------------------------------------------------
// rope+split scalar helper (mma.sync fallback path only)
// ---------------------------------------------------------------------------
__device__ __forceinline__ void rope_pair_store(
    float v0, float v1, int row, int col, int N, float scale,
    const float* cs, const float* sn,
    __nv_bfloat16* Xh, __nv_bfloat16* Xl) {
    int p = (col & 127) >> 1;
    float c = cs[row * 64 + p], s = sn[row * 64 + p];
    float o0 = (v0 * c - v1 * s) * scale;
    float o1 = (v0 * s + v1 * c) * scale;
    uint32_t hh = bpack(o0, o1);
    __nv_bfloat162 hv = *(__nv_bfloat162*)&hh;
    uint32_t ll = bpack(o0 - __bfloat162float(hv.x),
                        o1 - __bfloat162float(hv.y));
    *(uint32_t*)&Xh[(long)row * N + col] = hh;
    *(uint32_t*)&Xl[(long)row * N + col] = ll;
}

// ---------------------------------------------------------------------------
// Segmented GEMM (NT): 128x256 tile, tcgen05 (mma.sync fallback). R16-proven.
// ---------------------------------------------------------------------------
#define GT_ST_A 16384
#define GT_ST_B 32768
#define GT_STAGE (2*GT_ST_A + 2*GT_ST_B)
#define GT_SMEM (1024 + 2*GT_STAGE + 64)

__device__ __forceinline__ void gt_stage(
    const __nv_bfloat16* Ah, const __nv_bfloat16* Al,
    const __nv_bfloat16* Bh, const __nv_bfloat16* Bl,
    uint32_t sb, int m0, int n0, int K, int kc, int tid) {
#pragma unroll
    for (int i = 0; i < 4; ++i) {
        int c = tid + 256 * i;
        int row = c >> 3, col = c & 7;
        int so = row * 128 + ((col ^ (row & 7)) << 4);
        long ga = (long)(m0 + row) * K + kc + col * 8;
        cp16(sb + so,           Ah + ga);
        cp16(sb + GT_ST_A + so, Al + ga);
    }
#pragma unroll
    for (int i = 0; i < 8; ++i) {
        int c = tid + 256 * i;
        int row = c >> 3, col = c & 7;
        int so = row * 128 + ((col ^ (row & 7)) << 4);
        long gb = (long)(n0 + row) * K + kc + col * 8;
        cp16(sb + 2 * GT_ST_A + so,            Bh + gb);
        cp16(sb + 2 * GT_ST_A + GT_ST_B + so,  Bl + gb);
    }
    cp_commit();
}

__global__ __launch_bounds__(256, 1)
void gemm_tc(const __nv_bfloat16* __restrict__ Ah,
             const __nv_bfloat16* __restrict__ Al,
             const __nv_bfloat16* __restrict__ B1h,
             const __nv_bfloat16* __restrict__ B1l,
             float* __restrict__ C1f,
             __nv_bfloat16* __restrict__ C1h,
             __nv_bfloat16* __restrict__ C1l,
             float scale1,
             const __nv_bfloat16* __restrict__ B2h,
             const __nv_bfloat16* __restrict__ B2l,
             __nv_bfloat16* __restrict__ C2h,
             __nv_bfloat16* __restrict__ C2l,
             const __nv_bfloat16* __restrict__ B3h,
             const __nv_bfloat16* __restrict__ B3l,
             float* __restrict__ C3f,
             int s1, int s2,
             const float* __restrict__ cs,
             const float* __restrict__ sn,
             int N1, int N2, int K) {
    extern __shared__ char smg_raw[];
    uint32_t u = smaddr(smg_raw);
    uint32_t t0 = (u + 1023u) & ~1023u;
    const int tid = threadIdx.x;
    const int wid = tid >> 5;
    const int lane = tid & 31;
    const int m0 = blockIdx.y * 128;
    const int nst = K >> 6;

    // segment select
    const __nv_bfloat16* Bh;
    const __nv_bfloat16* Bl;
    float* Cf = nullptr;
    __nv_bfloat16* Ch = nullptr;
    __nv_bfloat16* Cl = nullptr;
    float scale = 1.0f;
    int N;
    int bx = blockIdx.x;
    if (bx < s1) {
        Bh = B1h; Bl = B1l; Cf = C1f; Ch = C1h; Cl = C1l; scale = scale1; N = N1;
    } else if (bx < s1 + s2) {
        bx -= s1;
        Bh = B2h; Bl = B2l; Ch = C2h; Cl = C2l; N = N2;
    } else {
        bx -= s1 + s2;
        Bh = B3h; Bl = B3l; Cf = C3f; N = N2;
    }
    const int n0 = bx * 256;
    const bool dosplit = (Ch != nullptr);

#if HAS_TCGEN05
    uint32_t ctrl = t0 + 2 * GT_STAGE;
    uint32_t mb[2] = {ctrl + 8, ctrl + 16};

    if (wid == 0) {
        TCGEN05_ALLOC(ctrl, 256);
        TCGEN05_RELINQ();
    }
    if (tid == 0) {
        MBARRIER_INIT(mb[0], 1);
        MBARRIER_INIT(mb[1], 1);
    }
    __syncthreads();
    uint32_t tmem;
    asm volatile("ld.shared.b32 %0, [%1];" : "=r"(tmem) : "r"(ctrl));

    gt_stage(Ah, Al, Bh, Bl, t0,            m0, n0, K, 0,  tid);
    gt_stage(Ah, Al, Bh, Bl, t0 + GT_STAGE, m0, n0, K, 64, tid);

    for (int t = 0; t < nst; ++t) {
        if (t + 1 < nst) asm volatile("cp.async.wait_group 1;");
        else             asm volatile("cp.async.wait_group 0;");
        FENCE_ASYNC();
        __syncthreads();

        if (tid == 0) {
            TCGEN05_FENCE_AFTER();
            uint32_t base = t0 + (t & 1) * GT_STAGE;
            uint64_t dAh = MAKE_SMEM_DESC(base);
            uint64_t dAl = MAKE_SMEM_DESC(base + GT_ST_A);
            uint64_t dBh = MAKE_SMEM_DESC(base + 2 * GT_ST_A);
            uint64_t dBl = MAKE_SMEM_DESC(base + 2 * GT_ST_A + GT_ST_B);
#pragma unroll
            for (int s = 0; s < 4; ++s) {
#pragma unroll
                for (int nh = 0; nh < 2; ++nh) {
                    uint64_t bo = (uint64_t)(2 * s + nh * 1024);
                    uint32_t dd = tmem + nh * 128;
                    umma_f16_ss(dd, dAh + 2 * s, dBh + bo, GEMM_IDESC,
                                (t == 0 && s == 0) ? 0u : 1u);
                    umma_f16_ss(dd, dAh + 2 * s, dBl + bo, GEMM_IDESC, 1u);
                    umma_f16_ss(dd, dAl + 2 * s, dBh + bo, GEMM_IDESC, 1u);
                }
            }
            TCGEN05_COMMIT(mb[t & 1]);
        }

        if (t + 2 < nst) {
            MBARRIER_WAIT_PARITY(mb[t & 1], (t >> 1) & 1);
            gt_stage(Ah, Al, Bh, Bl, t0 + (t & 1) * GT_STAGE, m0, n0, K,
                     (t + 2) * 64, tid);
        }
    }

    MBARRIER_WAIT_PARITY(mb[(nst - 1) & 1], ((nst - 1) >> 1) & 1);
    TCGEN05_FENCE_AFTER();

    {
        int row = m0 + (wid & 3) * 32 + lane;
        uint32_t cb = (wid >> 2) * 128;
#pragma unroll
        for (int cc = 0; cc < 4; ++cc) {
            uint32_t r[32];
            TCGEN05_LD_X32(r, tmem + cb + cc * 32);
            TCGEN05_WAIT_LD();
            int colbase = n0 + (int)cb + cc * 32;
            if (dosplit) {
                int p0 = (colbase & 127) >> 1;
                const float4* cs4 = (const float4*)(cs + row * 64 + p0);
                const float4* sn4 = (const float4*)(sn + row * 64 + p0);
                uint32_t hh[16], ll[16];
#pragma unroll
                for (int qv = 0; qv < 4; ++qv) {
                    float4 cv = cs4[qv];
                    float4 svv = sn4[qv];
                    float ca[4] = {cv.x, cv.y, cv.z, cv.w};
                    float sa[4] = {svv.x, svv.y, svv.z, svv.w};
#pragma unroll
                    for (int e = 0; e < 4; ++e) {
                        float v0 = __uint_as_float(r[qv * 8 + e * 2]);
                        float v1 = __uint_as_float(r[qv * 8 + e * 2 + 1]);
                        float o0 = (v0 * ca[e] - v1 * sa[e]) * scale;
                        float o1 = (v0 * sa[e] + v1 * ca[e]) * scale;
                        int j = qv * 4 + e;
                        hh[j] = bpack(o0, o1);
                        __nv_bfloat162 hv = *(__nv_bfloat162*)&hh[j];
                        ll[j] = bpack(o0 - __bfloat162float(hv.x),
                                      o1 - __bfloat162float(hv.y));
                    }
                }
                uint4* dh = (uint4*)&Ch[(long)row * N + colbase];
                uint4* dl = (uint4*)&Cl[(long)row * N + colbase];
#pragma unroll
                for (int qv = 0; qv < 4; ++qv) {
                    dh[qv] = make_uint4(hh[qv * 4], hh[qv * 4 + 1],
                                        hh[qv * 4 + 2], hh[qv * 4 + 3]);
                    dl[qv] = make_uint4(ll[qv * 4], ll[qv * 4 + 1],
                                        ll[qv * 4 + 2], ll[qv * 4 + 3]);
                }
            } else {
                float* dst = &Cf[(long)row * N + colbase];
#pragma unroll
                for (int q = 0; q < 8; ++q) {
                    *(float4*)(dst + q * 4) = make_float4(
                        __uint_as_float(r[q * 4 + 0]), __uint_as_float(r[q * 4 + 1]),
                        __uint_as_float(r[q * 4 + 2]), __uint_as_float(r[q * 4 + 3]));
                }
            }
        }
    }
    __syncthreads();
    if (wid == 0) TCGEN05_DEALLOC(tmem, 256);

#else
    const int wm = (wid >> 1) * 32;
    const int wn = (wid & 1) * 128;

    float acc[2][16][4];
#pragma unroll
    for (int i = 0; i < 2; ++i)
#pragma unroll
        for (int j = 0; j < 16; ++j)
#pragma unroll
            for (int q = 0; q < 4; ++q) acc[i][j][q] = 0.0f;

    for (int t = 0; t < nst; ++t) {
        gt_stage(Ah, Al, Bh, Bl, t0, m0, n0, K, t * 64, tid);
        asm volatile("cp.async.wait_group 0;");
        __syncthreads();

#pragma unroll
        for (int kb = 0; kb < 4; ++kb) {
            uint32_t ah[2][4], al[2][4];
#pragma unroll
            for (int mf = 0; mf < 2; ++mf) {
                int arow = wm + mf * 16 + (lane & 15);
                int col8 = kb * 2 + (lane >> 4);
                uint32_t off = arow * 128 + ((col8 ^ (arow & 7)) << 4);
                ldsm4(ah[mf][0], ah[mf][1], ah[mf][2], ah[mf][3], t0 + off);
                ldsm4(al[mf][0], al[mf][1], al[mf][2], al[mf][3],
                      t0 + GT_ST_A + off);
            }
#pragma unroll
            for (int np = 0; np < 8; ++np) {
                int brow = wn + np * 16 + (lane & 7) + ((lane >> 4) << 3);
                int col8 = kb * 2 + ((lane >> 3) & 1);
                uint32_t off = brow * 128 + ((col8 ^ (brow & 7)) << 4);
                uint32_t bh[4], bl[4];
                ldsm4(bh[0], bh[1], bh[2], bh[3], t0 + 2 * GT_ST_A + off);
                ldsm4(bl[0], bl[1], bl[2], bl[3],
                      t0 + 2 * GT_ST_A + GT_ST_B + off);
#pragma unroll
                for (int hf = 0; hf < 2; ++hf) {
                    int nf = np * 2 + hf;
#pragma unroll
                    for (int mf = 0; mf < 2; ++mf) {
                        mma16816(acc[mf][nf], ah[mf], bh[hf * 2], bh[hf * 2 + 1]);
                        mma16816(acc[mf][nf], ah[mf], bl[hf * 2], bl[hf * 2 + 1]);
                        mma16816(acc[mf][nf], al[mf], bh[hf * 2], bh[hf * 2 + 1]);
                    }
                }
            }
        }
        __syncthreads();
    }

#pragma unroll
    for (int mf = 0; mf < 2; ++mf) {
        int row = m0 + wm + mf * 16 + (lane >> 2);
#pragma unroll
        for (int nf = 0; nf < 16; ++nf) {
            int col = n0 + wn + nf * 8 + (lane & 3) * 2;
            if (dosplit) {
                rope_pair_store(acc[mf][nf][0], acc[mf][nf][1],
                                row, col, N, scale, cs, sn, Ch, Cl);
                rope_pair_store(acc[mf][nf][2], acc[mf][nf][3],
                                row + 8, col, N, scale, cs, sn, Ch, Cl);
            } else {
                *(float2*)&Cf[(long)row * N + col] =
                    make_float2(acc[mf][nf][0], acc[mf][nf][1]);
                *(float2*)&Cf[(long)(row + 8) * N + col] =
                    make_float2(acc[mf][nf][2], acc[mf][nf][3]);
            }
        }
    }
#endif
}

// ---------------------------------------------------------------------------
// tcgen05 flash attention (causal, GQA 4:1) — R10-proven structure.
// TMEM: S [0,64) | Ph [64,96) | Pl [96,128) | PV [128,256).
// ---------------------------------------------------------------------------
#define ATC_STAGE 65536
#define ATC_CTRL  (3 * 65536)
#define ATC_SMEM  (1024 + ATC_CTRL + 64 + 3072)
#define ATT_TS (64 * PADK)
#define ATT_SMEM_FB (8 * ATT_TS * 2)

__device__ __forceinline__ void atc_stage(
    const __nv_bfloat16* Kh, const __nv_bfloat16* Kl,
    const __nv_bfloat16* Vth, const __nv_bfloat16* Vtl,
    uint32_t sbase, int j0, int kvh, int tid) {
#pragma unroll
    for (int i = 0; i < 4; ++i) {
        int c = tid + 256 * i;
        int kr = c >> 4, kc = c & 15;
        int ch = kc >> 3, col = kc & 7;
        uint32_t so = sbase + ch * 8192 + kr * 128 + ((col ^ (kr & 7)) << 4);
        long g = (long)(j0 + kr) * KV_DIM + kvh * HD + kc * 8;
        cp16(so,          Kh + g);
        cp16(so + 16384,  Kl + g);
    }
#pragma unroll
    for (int i = 0; i < 4; ++i) {
        int c = tid + 256 * i;
        int vr = c >> 3, col = c & 7;
        uint32_t so = sbase + 32768 + vr * 128 + ((col ^ (vr & 7)) << 4);
        long g = (long)(kvh * HD + vr) * SEQ + j0 + col * 8;
        cp16(so,          Vth + g);
        cp16(so + 16384,  Vtl + g);
    }
    cp_commit();
}

__device__ __forceinline__ void attn_issue_fb(
    const __nv_bfloat16* Kh_, const __nv_bfloat16* Kl_,
    const __nv_bfloat16* Vh_, const __nv_bfloat16* Vl_,
    __nv_bfloat16* sKh, __nv_bfloat16* sKl,
    __nv_bfloat16* sVh, __nv_bfloat16* sVl,
    int j0, int kvh, int tid) {
#pragma unroll
    for (int i = 0; i < 4; ++i) {
        int c = tid + 256 * i;
        int row = c >> 4, c16 = c & 15;
        long g = (long)(j0 + row) * KV_DIM + kvh * HD + c16 * 8;
        int so = row * PADK + c16 * 8;
        cp16(smaddr(sKh + so), Kh_ + g);
        cp16(smaddr(sKl + so), Kl_ + g);
        cp16(smaddr(sVh + so), Vh_ + g);
        cp16(smaddr(sVl + so), Vl_ + g);
    }
    cp_commit();
}

__global__ __launch_bounds__(256, 1)
void attn_tc(const __nv_bfloat16* __restrict__ Qh,
             const __nv_bfloat16* __restrict__ Ql,
             const __nv_bfloat16* __restrict__ Kh,
             const __nv_bfloat16* __restrict__ Kl,
             const __nv_bfloat16* __restrict__ Vh,
             const __nv_bfloat16* __restrict__ Vl,
             const __nv_bfloat16* __restrict__ Vth,
             const __nv_bfloat16* __restrict__ Vtl,
             __nv_bfloat16* __restrict__ Oh,
             __nv_bfloat16* __restrict__ Ol) {
    extern __shared__ char smg_raw[];
    const int tid = threadIdx.x;
    const int lane = tid & 31;
    const int w = tid >> 5;
    const int h = blockIdx.y;
    const int kvh = h >> 2;
    const int qt = gridDim.x - 1 - blockIdx.x;
    const int q0 = qt * BQT;
    const int nt = 2 * qt + 2;

#if HAS_TCGEN05
    uint32_t u = smaddr(smg_raw);
    uint32_t t0 = (u + 1023u) & ~1023u;
    char* gb = smg_raw + (t0 - u);
    const int half = w >> 2;
    const int sp = w & 3;
    const int row = sp * 32 + lane;
    const int qrow = q0 + row;

    uint32_t ctrl = t0 + ATC_CTRL;
    uint32_t mbs = ctrl + 8, mbpv = ctrl + 16;
    float* red0 = (float*)(gb + ATC_CTRL + 64);
    float* red1 = red0 + 256;
    float* smm  = red1 + 256;
    float* sml  = smm + 128;

    if (w == 0) {
        TCGEN05_ALLOC(ctrl, 256);
        TCGEN05_RELINQ();
    }
    if (tid == 0) {
        MBARRIER_INIT(mbs, 1);
        MBARRIER_INIT(mbpv, 1);
    }
    if (tid < 128) { smm[tid] = -1e30f; sml[tid] = 0.0f; }
    __syncthreads();
    uint32_t tmem;
    asm volatile("ld.shared.b32 %0, [%1];" : "=r"(tmem) : "r"(ctrl));

#pragma unroll
    for (int i = 0; i < 8; ++i) {
        int c = tid + 256 * i;
        int r = c >> 4, kc = c & 15;
        int ch = kc >> 3, col = kc & 7;
        uint32_t so = t0 + ch * 16384 + r * 128 + ((col ^ (r & 7)) << 4);
        long g = (long)(q0 + r) * DIM + h * HD + kc * 8;
        cp16(so,          Qh + g);
        cp16(so + 32768,  Ql + g);
    }
    atc_stage(Kh, Kl, Vth, Vtl, t0 + ATC_STAGE,     0,  kvh, tid);
    atc_stage(Kh, Kl, Vth, Vtl, t0 + 2 * ATC_STAGE, 64, kvh, tid);

    float of[64];
#pragma unroll
    for (int j = 0; j < 64; ++j) of[j] = 0.0f;

    for (int t = 0; t < nt; ++t) {
        const int j0 = t * BKT;
        if (t >= 1 && t + 1 < nt)
            atc_stage(Kh, Kl, Vth, Vtl, t0 + ATC_STAGE * (1 + ((t + 1) & 1)),
                      (t + 1) * BKT, kvh, tid);
        if (t + 1 < nt) asm volatile("cp.async.wait_group 1;");
        else            asm volatile("cp.async.wait_group 0;");
        FENCE_ASYNC();
        __syncthreads();

        const uint32_t sbase = t0 + ATC_STAGE * (1 + (t & 1));

        if (tid == 0) {
            TCGEN05_FENCE_AFTER();
#pragma unroll
            for (int c = 0; c < 2; ++c) {
                uint64_t dQh = MAKE_SMEM_DESC(t0 + c * 16384);
                uint64_t dQl = MAKE_SMEM_DESC(t0 + 32768 + c * 16384);
                uint64_t dKh = MAKE_SMEM_DESC(sbase + c * 8192);
                uint64_t dKl = MAKE_SMEM_DESC(sbase + 16384 + c * 8192);
#pragma unroll
                for (int s = 0; s < 4; ++s) {
                    umma_f16_ss(tmem, dQh + 2 * s, dKh + 2 * s, IDESC_S,
                                (c == 0 && s == 0) ? 0u : 1u);
                    umma_f16_ss(tmem, dQh + 2 * s, dKl + 2 * s, IDESC_S, 1u);
                    umma_f16_ss(tmem, dQl + 2 * s, dKh + 2 * s, IDESC_S, 1u);
                }
            }
            TCGEN05_COMMIT(mbs);
        }
        MBARRIER_WAIT_PARITY(mbs, t & 1);
        TCGEN05_FENCE_AFTER();

        uint32_t sr[32];
        TCGEN05_LD_X32(sr, tmem + half * 32);
        TCGEN05_WAIT_LD();
        float sv[32];
#pragma unroll
        for (int j = 0; j < 32; ++j) sv[j] = __uint_as_float(sr[j]);
        if (t >= nt - 2) {
#pragma unroll
            for (int j = 0; j < 32; ++j)
                if (j0 + half * 32 + j > qrow) sv[j] = -1e30f;
        }
        float mymax = -1e30f;
#pragma unroll
        for (int j = 0; j < 32; ++j) mymax = fmaxf(mymax, sv[j]);
        red0[half * 128 + row] = mymax;
        __syncthreads();
        float mt = fmaxf(red0[row], red0[128 + row]);
        float mold = smm[row];
        float mn = fmaxf(mold, mt);
        float alpha = __expf(mold - mn);
        float mysum = 0.0f;
#pragma unroll
        for (int j = 0; j < 32; ++j) {
            sv[j] = __expf(sv[j] - mn);
            mysum += sv[j];
        }
        red1[half * 128 + row] = mysum;
        __syncthreads();
        if (half == 0) {
            sml[row] = sml[row] * alpha + red1[row] + red1[128 + row];
            smm[row] = mn;
        }

        uint32_t ph[16], pl[16];
#pragma unroll
        for (int j = 0; j < 16; ++j) {
            float a = sv[2 * j], b = sv[2 * j + 1];
            ph[j] = bpack(a, b);
            __nv_bfloat162 hv = *(__nv_bfloat162*)&ph[j];
            pl[j] = bpack(a - __bfloat162float(hv.x), b - __bfloat162float(hv.y));
        }
        uint32_t lo_off = (uint32_t)sp << 21;
        TCGEN05_ST_X16(tmem + 64 + half * 16 + lo_off, ph);
        TCGEN05_ST_X16(tmem + 96 + half * 16 + lo_off, pl);
        TCGEN05_WAIT_ST();
        TCGEN05_FENCE_BEFORE();
        __syncthreads();

        if (tid == 0) {
            TCGEN05_FENCE_AFTER();
            uint64_t dVh = MAKE_SMEM_DESC(sbase + 32768);
            uint64_t dVl = MAKE_SMEM_DESC(sbase + 49152);
#pragma unroll
            for (int ks = 0; ks < 4; ++ks) {
                umma_f16_ts(tmem + 128, tmem + 64 + ks * 8, dVh + 2 * ks,
                            IDESC_PV, ks == 0 ? 0u : 1u);
                umma_f16_ts(tmem + 128, tmem + 64 + ks * 8, dVl + 2 * ks,
                            IDESC_PV, 1u);
                umma_f16_ts(tmem + 128, tmem + 96 + ks * 8, dVh + 2 * ks,
                            IDESC_PV, 1u);
            }
            TCGEN05_COMMIT(mbpv);
        }
        MBARRIER_WAIT_PARITY(mbpv, t & 1);
        TCGEN05_FENCE_AFTER();

        uint32_t pv[32];
        TCGEN05_LD_X32(pv, tmem + 128 + half * 64);
        TCGEN05_WAIT_LD();
#pragma unroll
        for (int j = 0; j < 32; ++j)
            of[j] = of[j] * alpha + __uint_as_float(pv[j]);
        TCGEN05_LD_X32(pv, tmem + 128 + half * 64 + 32);
        TCGEN05_WAIT_LD();
#pragma unroll
        for (int j = 0; j < 32; ++j)
            of[32 + j] = of[32 + j] * alpha + __uint_as_float(pv[j]);
    }

    float inv = 1.0f / sml[row];
#pragma unroll
    for (int j = 0; j < 32; ++j) {
        float a = of[2 * j] * inv, b = of[2 * j + 1] * inv;
        uint32_t hh = bpack(a, b);
        __nv_bfloat162 hv = *(__nv_bfloat162*)&hh;
        uint32_t ll = bpack(a - __bfloat162float(hv.x),
                            b - __bfloat162float(hv.y));
        long o = (long)qrow * DIM + h * HD + half * 64 + 2 * j;
        *(uint32_t*)&Oh[o] = hh;
        *(uint32_t*)&Ol[o] = ll;
    }
    __syncthreads();
    if (w == 0) TCGEN05_DEALLOC(tmem, 256);

#else
    // ======================= mma.sync fallback ===============================
    __nv_bfloat16* sma = (__nv_bfloat16*)smg_raw;
    __nv_bfloat16* sKh[2] = {sma + 0 * ATT_TS, sma + 1 * ATT_TS};
    __nv_bfloat16* sKl[2] = {sma + 2 * ATT_TS, sma + 3 * ATT_TS};
    __nv_bfloat16* sVh[2] = {sma + 4 * ATT_TS, sma + 5 * ATT_TS};
    __nv_bfloat16* sVl[2] = {sma + 6 * ATT_TS, sma + 7 * ATT_TS};

    const int g = lane >> 2;
    const int qq = lane & 3;
    const int r0 = q0 + w * 16 + g;
    const int r1 = r0 + 8;
    uint32_t qfh[8][4], qfl[8][4];
#pragma unroll
    for (int k = 0; k < 8; ++k) {
        int c = h * HD + k * 16 + qq * 2;
        qfh[k][0] = *(const uint32_t*)&Qh[(long)r0 * DIM + c];
        qfh[k][1] = *(const uint32_t*)&Qh[(long)r1 * DIM + c];
        qfh[k][2] = *(const uint32_t*)&Qh[(long)r0 * DIM + c + 8];
        qfh[k][3] = *(const uint32_t*)&Qh[(long)r1 * DIM + c + 8];
        qfl[k][0] = *(const uint32_t*)&Ql[(long)r0 * DIM + c];
        qfl[k][1] = *(const uint32_t*)&Ql[(long)r1 * DIM + c];
        qfl[k][2] = *(const uint32_t*)&Ql[(long)r0 * DIM + c + 8];
        qfl[k][3] = *(const uint32_t*)&Ql[(long)r1 * DIM + c + 8];
    }

    float of[16][4];
#pragma unroll
    for (int i = 0; i < 16; ++i)
#pragma unroll
        for (int j = 0; j < 4; ++j) of[i][j] = 0.0f;
    float m0 = -1e30f, m1 = -1e30f, l0 = 0.0f, l1 = 0.0f;

    attn_issue_fb(Kh, Kl, Vh, Vl, sKh[0], sKl[0], sVh[0], sVl[0], 0, kvh, tid);

    for (int t = 0; t < nt; ++t) {
        if (t + 1 < nt) {
            int bb = (t + 1) & 1;
            attn_issue_fb(Kh, Kl, Vh, Vl, sKh[bb], sKl[bb], sVh[bb], sVl[bb],
                          (t + 1) * BKT, kvh, tid);
            asm volatile("cp.async.wait_group 1;");
        } else {
            asm volatile("cp.async.wait_group 0;");
        }
        __syncthreads();
        const int buf = t & 1;
        const int j0 = t * BKT;

        float sc[8][4];
#pragma unroll
        for (int i = 0; i < 8; ++i)
#pragma unroll
            for (int j = 0; j < 4; ++j) sc[i][j] = 0.0f;

#pragma unroll
        for (int k = 0; k < 8; ++k) {
#pragma unroll
            for (int np = 0; np < 4; ++np) {
                int brow = np * 16 + (lane & 7) + ((lane >> 4) << 3);
                int bcol = k * 16 + (((lane >> 3) & 1) << 3);
                uint32_t bh[4], bl[4];
                ldsm4(bh[0], bh[1], bh[2], bh[3],
                      smaddr(sKh[buf] + brow * PADK + bcol));
                ldsm4(bl[0], bl[1], bl[2], bl[3],
                      smaddr(sKl[buf] + brow * PADK + bcol));
#pragma unroll
                for (int hf = 0; hf < 2; ++hf) {
                    int nf = np * 2 + hf;
                    mma16816(sc[nf], qfh[k], bh[hf * 2], bh[hf * 2 + 1]);
                    mma16816(sc[nf], qfh[k], bl[hf * 2], bl[hf * 2 + 1]);
                    mma16816(sc[nf], qfl[k], bh[hf * 2], bh[hf * 2 + 1]);
                }
            }
        }

        if (t >= nt - 2) {
#pragma unroll
            for (int nf = 0; nf < 8; ++nf) {
                int cb = j0 + nf * 8 + qq * 2;
                if (cb > r0)     sc[nf][0] = -1e30f;
                if (cb + 1 > r0) sc[nf][1] = -1e30f;
                if (cb > r1)     sc[nf][2] = -1e30f;
                if (cb + 1 > r1) sc[nf][3] = -1e30f;
            }
        }

        float mt0 = -1e30f, mt1 = -1e30f;
#pragma unroll
        for (int nf = 0; nf < 8; ++nf) {
            mt0 = fmaxf(mt0, fmaxf(sc[nf][0], sc[nf][1]));
            mt1 = fmaxf(mt1, fmaxf(sc[nf][2], sc[nf][3]));
        }
        mt0 = fmaxf(mt0, __shfl_xor_sync(0xffffffff, mt0, 1));
        mt0 = fmaxf(mt0, __shfl_xor_sync(0xffffffff, mt0, 2));
        mt1 = fmaxf(mt1, __shfl_xor_sync(0xffffffff, mt1, 1));
        mt1 = fmaxf(mt1, __shfl_xor_sync(0xffffffff, mt1, 2));
        float mn0 = fmaxf(m0, mt0), mn1 = fmaxf(m1, mt1);
        float a0 = __expf(m0 - mn0), a1 = __expf(m1 - mn1);
        m0 = mn0; m1 = mn1;

        float rs0 = 0.0f, rs1 = 0.0f;
#pragma unroll
        for (int nf = 0; nf < 8; ++nf) {
            sc[nf][0] = __expf(sc[nf][0] - mn0); rs0 += sc[nf][0];
            sc[nf][1] = __expf(sc[nf][1] - mn0); rs0 += sc[nf][1];
            sc[nf][2] = __expf(sc[nf][2] - mn1); rs1 += sc[nf][2];
            sc[nf][3] = __expf(sc[nf][3] - mn1); rs1 += sc[nf][3];
        }
        rs0 += __shfl_xor_sync(0xffffffff, rs0, 1);
        rs0 += __shfl_xor_sync(0xffffffff, rs0, 2);
        rs1 += __shfl_xor_sync(0xffffffff, rs1, 1);
        rs1 += __shfl_xor_sync(0xffffffff, rs1, 2);
        l0 = l0 * a0 + rs0;
        l1 = l1 * a1 + rs1;

#pragma unroll
        for (int nf = 0; nf < 16; ++nf) {
            of[nf][0] *= a0; of[nf][1] *= a0;
            of[nf][2] *= a1; of[nf][3] *= a1;
        }

#pragma unroll
        for (int ks = 0; ks < 4; ++ks) {
            uint32_t ph[4], pl[4];
            {
                float s00 = sc[2 * ks][0],     s01 = sc[2 * ks][1];
                float s02 = sc[2 * ks][2],     s03 = sc[2 * ks][3];
                float s10 = sc[2 * ks + 1][0], s11 = sc[2 * ks + 1][1];
                float s12 = sc[2 * ks + 1][2], s13 = sc[2 * ks + 1][3];
                ph[0] = bpack(s00, s01); ph[1] = bpack(s02, s03);
                ph[2] = bpack(s10, s11); ph[3] = bpack(s12, s13);
                __nv_bfloat162* hp;
                hp = (__nv_bfloat162*)&ph[0];
                pl[0] = bpack(s00 - __bfloat162float(hp->x), s01 - __bfloat162float(hp->y));
                hp = (__nv_bfloat162*)&ph[1];
                pl[1] = bpack(s02 - __bfloat162float(hp->x), s03 - __bfloat162float(hp->y));
                hp = (__nv_bfloat162*)&ph[2];
                pl[2] = bpack(s10 - __bfloat162float(hp->x), s11 - __bfloat162float(hp->y));
                hp = (__nv_bfloat162*)&ph[3];
                pl[3] = bpack(s12 - __bfloat162float(hp->x), s13 - __bfloat162float(hp->y));
            }
            int vrow = ks * 16 + (lane & 7) + (((lane >> 3) & 1) << 3);
#pragma unroll
            for (int nn = 0; nn < 8; ++nn) {
                int vcol = nn * 16 + ((lane >> 4) << 3);
                uint32_t vh[4], vl[4];
                ldsm4t(vh[0], vh[1], vh[2], vh[3],
                       smaddr(sVh[buf] + vrow * PADK + vcol));
                ldsm4t(vl[0], vl[1], vl[2], vl[3],
                       smaddr(sVl[buf] + vrow * PADK + vcol));
                mma16816(of[nn * 2], ph, vh[0], vh[1]);
                mma16816(of[nn * 2], ph, vl[0], vl[1]);
                mma16816(of[nn * 2], pl, vh[0], vh[1]);
                mma16816(of[nn * 2 + 1], ph, vh[2], vh[3]);
                mma16816(of[nn * 2 + 1], ph, vl[2], vl[3]);
                mma16816(of[nn * 2 + 1], pl, vh[2], vh[3]);
            }
        }
        __syncthreads();
    }

    float inv0 = 1.0f / l0, inv1 = 1.0f / l1;
#pragma unroll
    for (int nf = 0; nf < 16; ++nf) {
        int col = h * HD + nf * 8 + qq * 2;
        {
            float a = of[nf][0] * inv0, b = of[nf][1] * inv0;
            uint32_t hh = bpack(a, b);
            __nv_bfloat162 hv = *(__nv_bfloat162*)&hh;
            uint32_t ll = bpack(a - __bfloat162float(hv.x),
                                b - __bfloat162float(hv.y));
            *(uint32_t*)&Oh[(long)r0 * DIM + col] = hh;
            *(uint32_t*)&Ol[(long)r0 * DIM + col] = ll;
        }
        {
            float a = of[nf][2] * inv1, b = of[nf][3] * inv1;
            uint32_t hh = bpack(a, b);
            __nv_bfloat162 hv = *(__nv_bfloat162*)&hh;
            uint32_t ll = bpack(a - __bfloat162float(hv.x),
                                b - __bfloat162float(hv.y));
            *(uint32_t*)&Oh[(long)r1 * DIM + col] = hh;
            *(uint32_t*)&Ol[(long)r1 * DIM + col] = ll;
        }
    }
#endif
}

// ---------------------------------------------------------------------------
// Launcher
// ---------------------------------------------------------------------------
extern "C" void kernel_launch(void* const* d_in, const int* in_sizes, int n_in,
                              void* d_out, int out_size) {
    const float* x  = (const float*)d_in[0];
    const float* wq = (const float*)d_in[1];
    const float* wk = (const float*)d_in[2];
    const float* wv = (const float*)d_in[3];
    const float* wo = (const float*)d_in[4];
    const float* fc = (const float*)d_in[5];
    const float* fs = (const float*)d_in[6];
    float* out = (float*)d_out;

    float* Vp;
    cudaGetSymbolAddress((void**)&Vp, g_V);

    __nv_bfloat16 *xh, *xl, *wqh, *wql, *wkh, *wkl, *wvh, *wvl, *woh, *wol, *oh, *ol;
    __nv_bfloat16 *qh, *ql, *kh, *kl, *vh, *vl, *vth, *vtl;
    cudaGetSymbolAddress((void**)&xh,  g_xh);  cudaGetSymbolAddress((void**)&xl,  g_xl);
    cudaGetSymbolAddress((void**)&wqh, g_wqh); cudaGetSymbolAddress((void**)&wql, g_wql);
    cudaGetSymbolAddress((void**)&wkh, g_wkh); cudaGetSymbolAddress((void**)&wkl, g_wkl);
    cudaGetSymbolAddress((void**)&wvh, g_wvh); cudaGetSymbolAddress((void**)&wvl, g_wvl);
    cudaGetSymbolAddress((void**)&woh, g_woh); cudaGetSymbolAddress((void**)&wol, g_wol);
    cudaGetSymbolAddress((void**)&oh,  g_oh);  cudaGetSymbolAddress((void**)&ol,  g_ol);
    cudaGetSymbolAddress((void**)&qh,  g_Qh);  cudaGetSymbolAddress((void**)&ql,  g_Ql);
    cudaGetSymbolAddress((void**)&kh,  g_Kh);  cudaGetSymbolAddress((void**)&kl,  g_Kl);
    cudaGetSymbolAddress((void**)&vh,  g_Vh);  cudaGetSymbolAddress((void**)&vl,  g_Vl);
    cudaGetSymbolAddress((void**)&vth, g_Vth); cudaGetSymbolAddress((void**)&vtl, g_Vtl);

    cudaFuncSetAttribute(gemm_tc,
                         cudaFuncAttributeMaxDynamicSharedMemorySize, GT_SMEM);
    int att_smem = ATC_SMEM > ATT_SMEM_FB ? ATC_SMEM : ATT_SMEM_FB;
    cudaFuncSetAttribute(attn_tc,
                         cudaFuncAttributeMaxDynamicSharedMemorySize, att_smem);

    // Fused splits of x + all four weights (one launch, 6144 blocks)
    split_all<<<6144, 256>>>(x, xh, xl, wq, wqh, wql, wk, wkh, wkl,
                             wv, wvh, wvl, wo, woh, wol);

    const float qscale = 0.08838834764831845f;

    // Fused Q + K + V projections: one launch, 3 segments (16 + 4 + 4 tiles)
    gemm_tc<<<dim3(24, SEQ / 128), 256, GT_SMEM>>>(
        xh, xl,
        wqh, wql, nullptr, qh, ql, qscale,
        wkh, wkl, kh, kl,
        wvh, wvl, Vp,
        16, 4, fc, fs, DIM, KV_DIM, DIM);

    // V splits (row-major + transposed) in one fused kernel, V read once
    v_split_all<<<dim3(SEQ / 32, KV_DIM / 32), dim3(32, 8)>>>(Vp, vh, vl, vth, vtl);

    // Flash attention (tcgen05, R10 structure) -> bf16 hi/lo output
    attn_tc<<<dim3(SEQ / BQT, NH), 256, att_smem>>>(
        qh, ql, kh, kl, vh, vl, vth, vtl, oh, ol);

    // Output projection (fp32 out) — segments 2,3 empty
    gemm_tc<<<dim3(16, SEQ / 128), 256, GT_SMEM>>>(
        oh, ol,
        woh, wol, out, nullptr, nullptr, 0.0f,
        nullptr, nullptr, nullptr, nullptr,
        nullptr, nullptr, nullptr,
        16, 0, fc, fs, DIM, KV_DIM, DIM);
}